// round 1
// baseline (speedup 1.0000x reference)
#include <cuda_runtime.h>
#include <math.h>

#define B_   32
#define S_   512
#define IN_  64
#define D_   512
#define H_   8
#define L_   4
#define FF_  2048
#define TOK_ (B_ * S_)   // 16384

// ---------------- scratch (device globals; no allocation allowed) ----------------
__device__ __align__(16) float g_x[TOK_ * D_];          // 32 MB  activation stream
__device__ __align__(16) float g_qkv[TOK_ * 3 * D_];    // 100 MB
__device__ __align__(16) float g_ctx[TOK_ * D_];        // 32 MB
__device__ __align__(16) float g_tmp[TOK_ * D_];        // 32 MB
__device__ __align__(16) float g_ff[TOK_ * FF_];        // 128 MB
__device__ __align__(16) float g_pool[B_ * 2 * D_];
__device__ __align__(16) float g_head[B_ * D_];

__device__ __forceinline__ float gelu_exact(float v) {
    return 0.5f * v * (1.0f + erff(v * 0.7071067811865475f));
}

// ---------------- generic GEMM: C[M,N] = act(A[M,K] * W[N,K]^T + bias) ----------------
// ACT: 0 = none, 1 = exact GELU, 2 = add positional encoding (input projection)
// 128x128 tile, BK=8, 256 threads, 8x8 per thread (2x2 quadrants of 4x4, float4 smem reads)
template <int ACT>
__global__ __launch_bounds__(256)
void gemm_kernel(const float* __restrict__ A, const float* __restrict__ W,
                 const float* __restrict__ bias, float* __restrict__ C,
                 int M, int N, int K)
{
    __shared__ __align__(16) float As[8][128];
    __shared__ __align__(16) float Ws[8][128];

    const int tid = threadIdx.x;
    const int tx = tid & 15;        // 0..15
    const int ty = tid >> 4;        // 0..15
    const int m0 = blockIdx.y * 128;
    const int n0 = blockIdx.x * 128;

    float acc[2][2][4][4];
#pragma unroll
    for (int p = 0; p < 2; p++)
#pragma unroll
        for (int q = 0; q < 2; q++)
#pragma unroll
            for (int i = 0; i < 4; i++)
#pragma unroll
                for (int j = 0; j < 4; j++) acc[p][q][i][j] = 0.f;

    const int lr = tid >> 1;          // 0..127 (row within tile)
    const int lk = (tid & 1) * 4;     // 0 or 4 (k offset)
    const float* Ag = A + (size_t)(m0 + lr) * K + lk;
    const float* Wg = W + (size_t)(n0 + lr) * K + lk;
    const bool aval = (m0 + lr) < M;

    for (int k0 = 0; k0 < K; k0 += 8) {
        float4 av = make_float4(0.f, 0.f, 0.f, 0.f);
        if (aval) av = *(const float4*)(Ag + k0);
        const float4 wv = *(const float4*)(Wg + k0);
        __syncthreads();
        As[lk + 0][lr] = av.x; As[lk + 1][lr] = av.y;
        As[lk + 2][lr] = av.z; As[lk + 3][lr] = av.w;
        Ws[lk + 0][lr] = wv.x; Ws[lk + 1][lr] = wv.y;
        Ws[lk + 2][lr] = wv.z; Ws[lk + 3][lr] = wv.w;
        __syncthreads();
#pragma unroll
        for (int kk = 0; kk < 8; kk++) {
            const float4 a0 = *(const float4*)&As[kk][ty * 4];
            const float4 a1 = *(const float4*)&As[kk][64 + ty * 4];
            const float4 b0 = *(const float4*)&Ws[kk][tx * 4];
            const float4 b1 = *(const float4*)&Ws[kk][64 + tx * 4];
            const float ar[2][4] = {{a0.x, a0.y, a0.z, a0.w}, {a1.x, a1.y, a1.z, a1.w}};
            const float br[2][4] = {{b0.x, b0.y, b0.z, b0.w}, {b1.x, b1.y, b1.z, b1.w}};
#pragma unroll
            for (int p = 0; p < 2; p++)
#pragma unroll
                for (int q = 0; q < 2; q++)
#pragma unroll
                    for (int i = 0; i < 4; i++)
#pragma unroll
                        for (int j = 0; j < 4; j++)
                            acc[p][q][i][j] += ar[p][i] * br[q][j];
        }
    }

#pragma unroll
    for (int p = 0; p < 2; p++) {
#pragma unroll
        for (int i = 0; i < 4; i++) {
            const int m = m0 + p * 64 + ty * 4 + i;
            if (m >= M) continue;
#pragma unroll
            for (int q = 0; q < 2; q++) {
                const int c = n0 + q * 64 + tx * 4;
                float4 o;
                float* po = &o.x;
#pragma unroll
                for (int j = 0; j < 4; j++) {
                    float v = acc[p][q][i][j] + bias[c + j];
                    if (ACT == 1) {
                        v = gelu_exact(v);
                    } else if (ACT == 2) {
                        const int d = c + j;
                        const int s = m & (S_ - 1);
                        // pe: even d -> sin(pos*exp(-d*ln(1e4)/D)), odd -> cos with d-1
                        const float freq = expf(-9.210340371976184f * (float)(d & ~1) / (float)D_);
                        const float ang = (float)s * freq;
                        v += (d & 1) ? cosf(ang) : sinf(ang);
                    }
                    po[j] = v;
                }
                *(float4*)&C[(size_t)m * N + c] = o;
            }
        }
    }
}

// ---------------- attention scores + softmax -> write probs to d_out ----------------
// block: (q-tile of 16 rows) x (b*H+h). 256 threads. dynamic smem.
#define SC_SMEM_FLOATS (16 * 65 + 128 * 65 + 16 * 512)
__global__ __launch_bounds__(256)
void attn_kernel(const float* __restrict__ qkv, float* __restrict__ attn)
{
    extern __shared__ float sm[];
    float* qs = sm;                        // [16][65]
    float* ks = sm + 16 * 65;              // [128][65]
    float* sc = sm + 16 * 65 + 128 * 65;   // [16][512]

    const int tid = threadIdx.x;
    const int q0 = blockIdx.x * 16;
    const int bh = blockIdx.y;
    const int b = bh >> 3, h = bh & 7;

    // load q tile (pre-scaled by 1/sqrt(64))
    {
        const int r = tid >> 4;
        const int d0 = (tid & 15) * 4;
        const float4 v = *(const float4*)&qkv[(size_t)(b * S_ + q0 + r) * (3 * D_) + h * 64 + d0];
        qs[r * 65 + d0 + 0] = v.x * 0.125f;
        qs[r * 65 + d0 + 1] = v.y * 0.125f;
        qs[r * 65 + d0 + 2] = v.z * 0.125f;
        qs[r * 65 + d0 + 3] = v.w * 0.125f;
    }

    const int qi = tid >> 4;   // q row 0..15
    const int kl = tid & 15;   // base k lane (k = kl + j*16, conflict-free LDS)

    for (int kt = 0; kt < 4; kt++) {
        __syncthreads();
#pragma unroll
        for (int i = 0; i < 8; i++) {
            const int idx = tid + i * 256;
            const int r = idx >> 4;
            const int d0 = (idx & 15) * 4;
            const float4 v = *(const float4*)&qkv[(size_t)(b * S_ + kt * 128 + r) * (3 * D_) + D_ + h * 64 + d0];
            ks[r * 65 + d0 + 0] = v.x; ks[r * 65 + d0 + 1] = v.y;
            ks[r * 65 + d0 + 2] = v.z; ks[r * 65 + d0 + 3] = v.w;
        }
        __syncthreads();
        float acc[8] = {0.f, 0.f, 0.f, 0.f, 0.f, 0.f, 0.f, 0.f};
#pragma unroll
        for (int d = 0; d < 64; d++) {
            const float qv = qs[qi * 65 + d];
#pragma unroll
            for (int j = 0; j < 8; j++)
                acc[j] += qv * ks[(kl + j * 16) * 65 + d];
        }
#pragma unroll
        for (int j = 0; j < 8; j++)
            sc[qi * 512 + kt * 128 + kl + j * 16] = acc[j];
    }
    __syncthreads();

    // softmax: each warp handles 2 rows
    const int warp = tid >> 5, lane = tid & 31;
#pragma unroll
    for (int rr = 0; rr < 2; rr++) {
        const int row = warp * 2 + rr;
        float mx = -1e30f;
#pragma unroll
        for (int t = 0; t < 16; t++)
            mx = fmaxf(mx, sc[row * 512 + lane + t * 32]);
#pragma unroll
        for (int o = 16; o > 0; o >>= 1)
            mx = fmaxf(mx, __shfl_xor_sync(0xFFFFFFFFu, mx, o));
        float vals[16];
        float sum = 0.f;
#pragma unroll
        for (int t = 0; t < 16; t++) {
            const float v = expf(sc[row * 512 + lane + t * 32] - mx);
            vals[t] = v;
            sum += v;
        }
#pragma unroll
        for (int o = 16; o > 0; o >>= 1)
            sum += __shfl_xor_sync(0xFFFFFFFFu, sum, o);
        const float inv = 1.f / sum;
        float* dst = attn + ((size_t)bh * S_ + q0 + row) * S_;
#pragma unroll
        for (int t = 0; t < 16; t++)
            dst[lane + t * 32] = vals[t] * inv;
    }
}

// ---------------- ctx = attn @ V  (per (b,h): [512,512] x [512,64]) ----------------
__global__ __launch_bounds__(256)
void ctx_kernel(const float* __restrict__ attn, const float* __restrict__ qkv,
                float* __restrict__ ctx)
{
    __shared__ __align__(16) float at[64][68];
    __shared__ __align__(16) float vt[64][68];

    const int tid = threadIdx.x;
    const int q0 = blockIdx.x * 64;
    const int bh = blockIdx.y;
    const int b = bh >> 3, h = bh & 7;
    const int tx = tid & 15, ty = tid >> 4;

    float acc[4][4];
#pragma unroll
    for (int i = 0; i < 4; i++)
#pragma unroll
        for (int j = 0; j < 4; j++) acc[i][j] = 0.f;

    for (int k0 = 0; k0 < S_; k0 += 64) {
        __syncthreads();
#pragma unroll
        for (int i = 0; i < 4; i++) {
            const int idx = tid + i * 256;
            const int r = idx >> 4;
            const int c4 = (idx & 15) * 4;
            const float4 a = *(const float4*)&attn[((size_t)bh * S_ + q0 + r) * S_ + k0 + c4];
            *(float4*)&at[r][c4] = a;
            const float4 v = *(const float4*)&qkv[(size_t)(b * S_ + k0 + r) * (3 * D_) + 2 * D_ + h * 64 + c4];
            *(float4*)&vt[r][c4] = v;
        }
        __syncthreads();
#pragma unroll 8
        for (int kk = 0; kk < 64; kk++) {
            const float a0 = at[ty * 4 + 0][kk];
            const float a1 = at[ty * 4 + 1][kk];
            const float a2 = at[ty * 4 + 2][kk];
            const float a3 = at[ty * 4 + 3][kk];
            const float4 bv = *(const float4*)&vt[kk][tx * 4];
            acc[0][0] += a0 * bv.x; acc[0][1] += a0 * bv.y; acc[0][2] += a0 * bv.z; acc[0][3] += a0 * bv.w;
            acc[1][0] += a1 * bv.x; acc[1][1] += a1 * bv.y; acc[1][2] += a1 * bv.z; acc[1][3] += a1 * bv.w;
            acc[2][0] += a2 * bv.x; acc[2][1] += a2 * bv.y; acc[2][2] += a2 * bv.z; acc[2][3] += a2 * bv.w;
            acc[3][0] += a3 * bv.x; acc[3][1] += a3 * bv.y; acc[3][2] += a3 * bv.z; acc[3][3] += a3 * bv.w;
        }
    }
#pragma unroll
    for (int i = 0; i < 4; i++) {
        const float4 o = make_float4(acc[i][0], acc[i][1], acc[i][2], acc[i][3]);
        *(float4*)&ctx[(size_t)(b * S_ + q0 + ty * 4 + i) * D_ + h * 64 + tx * 4] = o;
    }
}

// ---------------- fused residual-add + LayerNorm (row-wise) ----------------
__global__ __launch_bounds__(128)
void ln_kernel(const float* __restrict__ x, const float* __restrict__ add,
               const float* __restrict__ w, const float* __restrict__ bvec,
               float* __restrict__ out)
{
    const int row = blockIdx.x;
    const int tid = threadIdx.x;
    const float* xr = x + (size_t)row * D_;
    const float* ar = add + (size_t)row * D_;
    float v[4];
    float s = 0.f;
#pragma unroll
    for (int i = 0; i < 4; i++) {
        const int c = tid + i * 128;
        v[i] = xr[c] + ar[c];
        s += v[i];
    }
    __shared__ float red[4];
#pragma unroll
    for (int o = 16; o > 0; o >>= 1) s += __shfl_xor_sync(0xFFFFFFFFu, s, o);
    if ((tid & 31) == 0) red[tid >> 5] = s;
    __syncthreads();
    const float mean = (red[0] + red[1] + red[2] + red[3]) * (1.f / 512.f);
    float vs = 0.f;
#pragma unroll
    for (int i = 0; i < 4; i++) {
        const float d = v[i] - mean;
        vs += d * d;
    }
    __syncthreads();
#pragma unroll
    for (int o = 16; o > 0; o >>= 1) vs += __shfl_xor_sync(0xFFFFFFFFu, vs, o);
    if ((tid & 31) == 0) red[tid >> 5] = vs;
    __syncthreads();
    const float rstd = rsqrtf((red[0] + red[1] + red[2] + red[3]) * (1.f / 512.f) + 1e-5f);
    float* orow = out + (size_t)row * D_;
#pragma unroll
    for (int i = 0; i < 4; i++) {
        const int c = tid + i * 128;
        orow[c] = (v[i] - mean) * rstd * w[c] + bvec[c];
    }
}

// ---------------- mean+max pooling over sequence ----------------
__global__ __launch_bounds__(512)
void pool_kernel(const float* __restrict__ x, float* __restrict__ pool)
{
    const int b = blockIdx.x, d = threadIdx.x;
    float s = 0.f, m = -1e30f;
    for (int t = 0; t < S_; t++) {
        const float v = x[(size_t)(b * S_ + t) * D_ + d];
        s += v;
        m = fmaxf(m, v);
    }
    pool[b * (2 * D_) + d] = s * (1.f / 512.f);
    pool[b * (2 * D_) + D_ + d] = m;
}

// ---------------- final head: out[b] = dot(h[b,:], w2) + b2 ----------------
__global__ __launch_bounds__(128)
void head2_kernel(const float* __restrict__ h, const float* __restrict__ w,
                  const float* __restrict__ bb, float* __restrict__ out)
{
    const int b = blockIdx.x, tid = threadIdx.x;
    float s = 0.f;
    for (int c = tid; c < D_; c += 128) s += h[(size_t)b * D_ + c] * w[c];
    __shared__ float red[4];
#pragma unroll
    for (int o = 16; o > 0; o >>= 1) s += __shfl_xor_sync(0xFFFFFFFFu, s, o);
    if ((tid & 31) == 0) red[tid >> 5] = s;
    __syncthreads();
    if (tid == 0) out[b] = red[0] + red[1] + red[2] + red[3] + bb[0];
}

// ---------------- launch ----------------
extern "C" void kernel_launch(void* const* d_in, const int* in_sizes, int n_in,
                              void* d_out, int out_size)
{
    const float* x_in = (const float*)d_in[0];
    const float* w_in = (const float*)d_in[1];
    const float* b_in = (const float*)d_in[2];
    const float* inpw = (const float*)d_in[3];
    const float* inpb = (const float*)d_in[4];
    const float* outw = (const float*)d_in[5];
    const float* outb = (const float*)d_in[6];
    const float* ln1w = (const float*)d_in[7];
    const float* ln1b = (const float*)d_in[8];
    const float* ln2w = (const float*)d_in[9];
    const float* ln2b = (const float*)d_in[10];
    const float* ff1w = (const float*)d_in[11];
    const float* ff1b = (const float*)d_in[12];
    const float* ff2w = (const float*)d_in[13];
    const float* ff2b = (const float*)d_in[14];
    const float* h1w  = (const float*)d_in[15];
    const float* h1b  = (const float*)d_in[16];
    const float* h2w  = (const float*)d_in[17];
    const float* h2b  = (const float*)d_in[18];

    float* out  = (float*)d_out;
    float* attn = out + 32;   // [L, B, H, S, S] follows the [B,1] output

    float *px, *pqkv, *pctx, *ptmp, *pff, *ppool, *phead;
    cudaGetSymbolAddress((void**)&px,    g_x);
    cudaGetSymbolAddress((void**)&pqkv,  g_qkv);
    cudaGetSymbolAddress((void**)&pctx,  g_ctx);
    cudaGetSymbolAddress((void**)&ptmp,  g_tmp);
    cudaGetSymbolAddress((void**)&pff,   g_ff);
    cudaGetSymbolAddress((void**)&ppool, g_pool);
    cudaGetSymbolAddress((void**)&phead, g_head);

    const int sc_smem = SC_SMEM_FLOATS * (int)sizeof(float);  // 70208 B
    cudaFuncSetAttribute(attn_kernel, cudaFuncAttributeMaxDynamicSharedMemorySize, sc_smem);

    const dim3 blk(256);

    // input projection + positional encoding (fused)
    gemm_kernel<2><<<dim3(D_ / 128, TOK_ / 128), blk>>>(x_in, w_in, b_in, px, TOK_, D_, IN_);

    for (int l = 0; l < L_; l++) {
        // QKV projection
        gemm_kernel<0><<<dim3((3 * D_) / 128, TOK_ / 128), blk>>>(
            px, inpw + (size_t)l * 3 * D_ * D_, inpb + l * 3 * D_, pqkv, TOK_, 3 * D_, D_);

        float* attn_l = attn + (size_t)l * B_ * H_ * S_ * S_;

        // scores + softmax -> attention probs (written straight to output)
        attn_kernel<<<dim3(S_ / 16, B_ * H_), blk, sc_smem>>>(pqkv, attn_l);

        // ctx = attn @ V
        ctx_kernel<<<dim3(S_ / 64, B_ * H_), blk>>>(attn_l, pqkv, pctx);

        // output projection
        gemm_kernel<0><<<dim3(D_ / 128, TOK_ / 128), blk>>>(
            pctx, outw + (size_t)l * D_ * D_, outb + l * D_, ptmp, TOK_, D_, D_);

        // x = LN(x + attn_out)
        ln_kernel<<<TOK_, 128>>>(px, ptmp, ln1w + l * D_, ln1b + l * D_, px);

        // ff1 + GELU
        gemm_kernel<1><<<dim3(FF_ / 128, TOK_ / 128), blk>>>(
            px, ff1w + (size_t)l * FF_ * D_, ff1b + l * FF_, pff, TOK_, FF_, D_);

        // ff2
        gemm_kernel<0><<<dim3(D_ / 128, TOK_ / 128), blk>>>(
            pff, ff2w + (size_t)l * D_ * FF_, ff2b + l * D_, ptmp, TOK_, D_, FF_);

        // x = LN(x + ff)
        ln_kernel<<<TOK_, 128>>>(px, ptmp, ln2w + l * D_, ln2b + l * D_, px);
    }

    // pooled = [mean(x,s), max(x,s)]  -> [32, 1024]
    pool_kernel<<<B_, 512>>>(px, ppool);

    // head1 + GELU: [32,1024] x [512,1024]^T
    gemm_kernel<1><<<dim3(D_ / 128, 1), blk>>>(ppool, h1w, h1b, phead, B_, D_, 2 * D_);

    // head2: [32,512] . [512] -> out[32]
    head2_kernel<<<B_, 128>>>(phead, h2w, h2b, out);
}

// round 3
// speedup vs baseline: 1.2161x; 1.2161x over previous
#include <cuda_runtime.h>
#include <cstdint>
#include <math.h>

#define B_   32
#define S_   512
#define IN_  64
#define D_   512
#define H_   8
#define L_   4
#define FF_  2048
#define TOK_ (B_ * S_)   // 16384

// ---------------- scratch (device globals; no allocation allowed) ----------------
__device__ __align__(16) float g_x[TOK_ * D_];
__device__ __align__(16) float g_qkv[TOK_ * 3 * D_];
__device__ __align__(16) float g_ctx[TOK_ * D_];
__device__ __align__(16) float g_tmp[TOK_ * D_];
__device__ __align__(16) float g_ff[TOK_ * FF_];
__device__ __align__(16) float g_pool[B_ * 2 * D_];
__device__ __align__(16) float g_head[B_ * D_];

__device__ __forceinline__ float gelu_exact(float v) {
    return 0.5f * v * (1.0f + erff(v * 0.7071067811865475f));
}

__device__ __forceinline__ uint32_t smem_u32(const void* p) {
    uint32_t a;
    asm("{ .reg .u64 t; cvta.to.shared.u64 t, %1; cvt.u32.u64 %0, t; }" : "=r"(a) : "l"(p));
    return a;
}
__device__ __forceinline__ uint32_t f2tf32(float f) {
    uint32_t u;
    asm("cvt.rna.tf32.f32 %0, %1;" : "=r"(u) : "f"(f));
    return u;
}
__device__ __forceinline__ void mma_tf32(float* c, const uint32_t* a, const uint32_t* b) {
    asm volatile(
        "mma.sync.aligned.m16n8k8.row.col.f32.tf32.tf32.f32 "
        "{%0,%1,%2,%3}, {%4,%5,%6,%7}, {%8,%9}, {%0,%1,%2,%3};"
        : "+f"(c[0]), "+f"(c[1]), "+f"(c[2]), "+f"(c[3])
        : "r"(a[0]), "r"(a[1]), "r"(a[2]), "r"(a[3]), "r"(b[0]), "r"(b[1]));
}

// ======================= mma.sync tf32 GEMM =======================
// C[M,N] = act(A[M,K] * W[N,K]^T + bias).  Requires M%128==0, N%128==0, K%32==0, K>=64.
// 128x128x32 tile, 256 threads, warps 4(M)x2(N), each warp 32x64.
// Smem per stage: A[128][36] floats + B[128][36] floats (pad 4 -> conflict-free frags).
#define MM_RS     36                       // row stride in floats
#define MM_TILEB  (128 * MM_RS * 4)        // 18432 B per operand
#define MM_STAGE  (2 * MM_TILEB)           // 36864 B per stage
#define MM_SMEM   (2 * MM_STAGE)           // 73728 B total

__device__ __forceinline__ void mm_cp_issue(
    const float* __restrict__ A, const float* __restrict__ W,
    uint32_t sbase, int stage, int m0, int n0, int K, int k0, int tid)
{
    const uint32_t as = sbase + stage * MM_STAGE;
    const uint32_t bs = as + MM_TILEB;
#pragma unroll
    for (int i = 0; i < 4; i++) {
        const int idx = i * 256 + tid;
        const int row = idx >> 3;
        const int q = idx & 7;
        const uint32_t so = (uint32_t)(row * (MM_RS * 4) + q * 16);
        const float* ga = A + (size_t)(m0 + row) * K + k0 + q * 4;
        const float* gw = W + (size_t)(n0 + row) * K + k0 + q * 4;
        asm volatile("cp.async.cg.shared.global [%0], [%1], 16;" :: "r"(as + so), "l"(ga));
        asm volatile("cp.async.cg.shared.global [%0], [%1], 16;" :: "r"(bs + so), "l"(gw));
    }
    asm volatile("cp.async.commit_group;" ::: "memory");
}

template <int ACT>   // 0=none, 1=exact GELU
__global__ __launch_bounds__(256)
void gemm_mma(const float* __restrict__ A, const float* __restrict__ W,
              const float* __restrict__ bias, float* __restrict__ C,
              int M, int N, int K)
{
    extern __shared__ char smem[];
    const uint32_t sbase = smem_u32(smem);
    const int tid = threadIdx.x;
    const int lane = tid & 31, wid = tid >> 5;
    const int g = lane >> 2, t4 = lane & 3;
    const int wm = wid & 3;          // M-warp: 32 rows each
    const int wn = wid >> 2;         // N-warp: 64 cols each
    const int m0 = blockIdx.y * 128, n0 = blockIdx.x * 128;

    float acc[2][8][4];
#pragma unroll
    for (int mt = 0; mt < 2; mt++)
#pragma unroll
        for (int nt = 0; nt < 8; nt++)
#pragma unroll
            for (int j = 0; j < 4; j++) acc[mt][nt][j] = 0.f;

    const int nch = K >> 5;          // chunks of BK=32 (assume nch >= 2)
    mm_cp_issue(A, W, sbase, 0, m0, n0, K, 0, tid);
    mm_cp_issue(A, W, sbase, 1, m0, n0, K, 32, tid);

    for (int c = 0; c < nch; c++) {
        if (c + 1 < nch)
            asm volatile("cp.async.wait_group 1;" ::: "memory");
        else
            asm volatile("cp.async.wait_group 0;" ::: "memory");
        __syncthreads();

        const int s = c & 1;
        const float* as = (const float*)(smem + s * MM_STAGE);
        const float* bs = as + 128 * MM_RS;

#pragma unroll
        for (int ks = 0; ks < 4; ks++) {
            uint32_t afr[2][4];
#pragma unroll
            for (int mt = 0; mt < 2; mt++) {
                const float* ap = as + (wm * 32 + mt * 16 + g) * MM_RS + ks * 8 + t4;
                afr[mt][0] = f2tf32(ap[0]);
                afr[mt][1] = f2tf32(ap[8 * MM_RS]);
                afr[mt][2] = f2tf32(ap[4]);
                afr[mt][3] = f2tf32(ap[8 * MM_RS + 4]);
            }
            uint32_t bfr[8][2];
#pragma unroll
            for (int nt = 0; nt < 8; nt++) {
                const float* bp = bs + (wn * 64 + nt * 8 + g) * MM_RS + ks * 8 + t4;
                bfr[nt][0] = f2tf32(bp[0]);
                bfr[nt][1] = f2tf32(bp[4]);
            }
#pragma unroll
            for (int mt = 0; mt < 2; mt++)
#pragma unroll
                for (int nt = 0; nt < 8; nt++)
                    mma_tf32(acc[mt][nt], afr[mt], bfr[nt]);
        }
        __syncthreads();
        if (c + 2 < nch)
            mm_cp_issue(A, W, sbase, s, m0, n0, K, (c + 2) * 32, tid);
    }

    // epilogue: c0,c1 at (row g, cols 2*t4,2*t4+1); c2,c3 at row g+8
#pragma unroll
    for (int mt = 0; mt < 2; mt++) {
        const int r0 = m0 + wm * 32 + mt * 16 + g;
#pragma unroll
        for (int nt = 0; nt < 8; nt++) {
            const int cb = n0 + wn * 64 + nt * 8 + 2 * t4;
            const float b0 = bias[cb], b1 = bias[cb + 1];
            float v0 = acc[mt][nt][0] + b0;
            float v1 = acc[mt][nt][1] + b1;
            float v2 = acc[mt][nt][2] + b0;
            float v3 = acc[mt][nt][3] + b1;
            if (ACT == 1) {
                v0 = gelu_exact(v0); v1 = gelu_exact(v1);
                v2 = gelu_exact(v2); v3 = gelu_exact(v3);
            }
            *(float2*)&C[(size_t)r0 * N + cb]       = make_float2(v0, v1);
            *(float2*)&C[(size_t)(r0 + 8) * N + cb] = make_float2(v2, v3);
        }
    }
}

// ---------------- SIMT GEMM (input proj / head1) ----------------
template <int ACT>
__global__ __launch_bounds__(256)
void gemm_kernel(const float* __restrict__ A, const float* __restrict__ W,
                 const float* __restrict__ bias, float* __restrict__ C,
                 int M, int N, int K)
{
    __shared__ __align__(16) float As[8][128];
    __shared__ __align__(16) float Ws[8][128];

    const int tid = threadIdx.x;
    const int tx = tid & 15;
    const int ty = tid >> 4;
    const int m0 = blockIdx.y * 128;
    const int n0 = blockIdx.x * 128;

    float acc[2][2][4][4];
#pragma unroll
    for (int p = 0; p < 2; p++)
#pragma unroll
        for (int q = 0; q < 2; q++)
#pragma unroll
            for (int i = 0; i < 4; i++)
#pragma unroll
                for (int j = 0; j < 4; j++) acc[p][q][i][j] = 0.f;

    const int lr = tid >> 1;
    const int lk = (tid & 1) * 4;
    const float* Ag = A + (size_t)(m0 + lr) * K + lk;
    const float* Wg = W + (size_t)(n0 + lr) * K + lk;
    const bool aval = (m0 + lr) < M;

    for (int k0 = 0; k0 < K; k0 += 8) {
        float4 av = make_float4(0.f, 0.f, 0.f, 0.f);
        if (aval) av = *(const float4*)(Ag + k0);
        const float4 wv = *(const float4*)(Wg + k0);
        __syncthreads();
        As[lk + 0][lr] = av.x; As[lk + 1][lr] = av.y;
        As[lk + 2][lr] = av.z; As[lk + 3][lr] = av.w;
        Ws[lk + 0][lr] = wv.x; Ws[lk + 1][lr] = wv.y;
        Ws[lk + 2][lr] = wv.z; Ws[lk + 3][lr] = wv.w;
        __syncthreads();
#pragma unroll
        for (int kk = 0; kk < 8; kk++) {
            const float4 a0 = *(const float4*)&As[kk][ty * 4];
            const float4 a1 = *(const float4*)&As[kk][64 + ty * 4];
            const float4 b0 = *(const float4*)&Ws[kk][tx * 4];
            const float4 b1 = *(const float4*)&Ws[kk][64 + tx * 4];
            const float ar[2][4] = {{a0.x, a0.y, a0.z, a0.w}, {a1.x, a1.y, a1.z, a1.w}};
            const float br[2][4] = {{b0.x, b0.y, b0.z, b0.w}, {b1.x, b1.y, b1.z, b1.w}};
#pragma unroll
            for (int p = 0; p < 2; p++)
#pragma unroll
                for (int q = 0; q < 2; q++)
#pragma unroll
                    for (int i = 0; i < 4; i++)
#pragma unroll
                        for (int j = 0; j < 4; j++)
                            acc[p][q][i][j] += ar[p][i] * br[q][j];
        }
    }

#pragma unroll
    for (int p = 0; p < 2; p++) {
#pragma unroll
        for (int i = 0; i < 4; i++) {
            const int m = m0 + p * 64 + ty * 4 + i;
            if (m >= M) continue;
#pragma unroll
            for (int q = 0; q < 2; q++) {
                const int c = n0 + q * 64 + tx * 4;
                float4 o;
                float* po = &o.x;
#pragma unroll
                for (int j = 0; j < 4; j++) {
                    float v = acc[p][q][i][j] + bias[c + j];
                    if (ACT == 1) {
                        v = gelu_exact(v);
                    } else if (ACT == 2) {
                        const int d = c + j;
                        const int s = m & (S_ - 1);
                        const float freq = expf(-9.210340371976184f * (float)(d & ~1) / (float)D_);
                        const float ang = (float)s * freq;
                        v += (d & 1) ? cosf(ang) : sinf(ang);
                    }
                    po[j] = v;
                }
                *(float4*)&C[(size_t)m * N + c] = o;
            }
        }
    }
}

// ---------------- attention scores + softmax -> write probs to d_out ----------------
#define SC_SMEM_FLOATS (16 * 65 + 128 * 65 + 16 * 512)
__global__ __launch_bounds__(256)
void attn_kernel(const float* __restrict__ qkv, float* __restrict__ attn)
{
    extern __shared__ float sm[];
    float* qs = sm;
    float* ks = sm + 16 * 65;
    float* sc = sm + 16 * 65 + 128 * 65;

    const int tid = threadIdx.x;
    const int q0 = blockIdx.x * 16;
    const int bh = blockIdx.y;
    const int b = bh >> 3, h = bh & 7;

    {
        const int r = tid >> 4;
        const int d0 = (tid & 15) * 4;
        const float4 v = *(const float4*)&qkv[(size_t)(b * S_ + q0 + r) * (3 * D_) + h * 64 + d0];
        qs[r * 65 + d0 + 0] = v.x * 0.125f;
        qs[r * 65 + d0 + 1] = v.y * 0.125f;
        qs[r * 65 + d0 + 2] = v.z * 0.125f;
        qs[r * 65 + d0 + 3] = v.w * 0.125f;
    }

    const int qi = tid >> 4;
    const int kl = tid & 15;

    for (int kt = 0; kt < 4; kt++) {
        __syncthreads();
#pragma unroll
        for (int i = 0; i < 8; i++) {
            const int idx = tid + i * 256;
            const int r = idx >> 4;
            const int d0 = (idx & 15) * 4;
            const float4 v = *(const float4*)&qkv[(size_t)(b * S_ + kt * 128 + r) * (3 * D_) + D_ + h * 64 + d0];
            ks[r * 65 + d0 + 0] = v.x; ks[r * 65 + d0 + 1] = v.y;
            ks[r * 65 + d0 + 2] = v.z; ks[r * 65 + d0 + 3] = v.w;
        }
        __syncthreads();
        float acc[8] = {0.f, 0.f, 0.f, 0.f, 0.f, 0.f, 0.f, 0.f};
#pragma unroll
        for (int d = 0; d < 64; d++) {
            const float qv = qs[qi * 65 + d];
#pragma unroll
            for (int j = 0; j < 8; j++)
                acc[j] += qv * ks[(kl + j * 16) * 65 + d];
        }
#pragma unroll
        for (int j = 0; j < 8; j++)
            sc[qi * 512 + kt * 128 + kl + j * 16] = acc[j];
    }
    __syncthreads();

    const int warp = tid >> 5, lane = tid & 31;
#pragma unroll
    for (int rr = 0; rr < 2; rr++) {
        const int row = warp * 2 + rr;
        float mx = -1e30f;
#pragma unroll
        for (int t = 0; t < 16; t++)
            mx = fmaxf(mx, sc[row * 512 + lane + t * 32]);
#pragma unroll
        for (int o = 16; o > 0; o >>= 1)
            mx = fmaxf(mx, __shfl_xor_sync(0xFFFFFFFFu, mx, o));
        float vals[16];
        float sum = 0.f;
#pragma unroll
        for (int t = 0; t < 16; t++) {
            const float v = expf(sc[row * 512 + lane + t * 32] - mx);
            vals[t] = v;
            sum += v;
        }
#pragma unroll
        for (int o = 16; o > 0; o >>= 1)
            sum += __shfl_xor_sync(0xFFFFFFFFu, sum, o);
        const float inv = 1.f / sum;
        float* dst = attn + ((size_t)bh * S_ + q0 + row) * S_;
#pragma unroll
        for (int t = 0; t < 16; t++)
            dst[lane + t * 32] = vals[t] * inv;
    }
}

// ---------------- ctx = attn @ V ----------------
__global__ __launch_bounds__(256)
void ctx_kernel(const float* __restrict__ attn, const float* __restrict__ qkv,
                float* __restrict__ ctx)
{
    __shared__ __align__(16) float at[64][68];
    __shared__ __align__(16) float vt[64][68];

    const int tid = threadIdx.x;
    const int q0 = blockIdx.x * 64;
    const int bh = blockIdx.y;
    const int b = bh >> 3, h = bh & 7;
    const int tx = tid & 15, ty = tid >> 4;

    float acc[4][4];
#pragma unroll
    for (int i = 0; i < 4; i++)
#pragma unroll
        for (int j = 0; j < 4; j++) acc[i][j] = 0.f;

    for (int k0 = 0; k0 < S_; k0 += 64) {
        __syncthreads();
#pragma unroll
        for (int i = 0; i < 4; i++) {
            const int idx = tid + i * 256;
            const int r = idx >> 4;
            const int c4 = (idx & 15) * 4;
            const float4 a = *(const float4*)&attn[((size_t)bh * S_ + q0 + r) * S_ + k0 + c4];
            *(float4*)&at[r][c4] = a;
            const float4 v = *(const float4*)&qkv[(size_t)(b * S_ + k0 + r) * (3 * D_) + 2 * D_ + h * 64 + c4];
            *(float4*)&vt[r][c4] = v;
        }
        __syncthreads();
#pragma unroll 8
        for (int kk = 0; kk < 64; kk++) {
            const float a0 = at[ty * 4 + 0][kk];
            const float a1 = at[ty * 4 + 1][kk];
            const float a2 = at[ty * 4 + 2][kk];
            const float a3 = at[ty * 4 + 3][kk];
            const float4 bv = *(const float4*)&vt[kk][tx * 4];
            acc[0][0] += a0 * bv.x; acc[0][1] += a0 * bv.y; acc[0][2] += a0 * bv.z; acc[0][3] += a0 * bv.w;
            acc[1][0] += a1 * bv.x; acc[1][1] += a1 * bv.y; acc[1][2] += a1 * bv.z; acc[1][3] += a1 * bv.w;
            acc[2][0] += a2 * bv.x; acc[2][1] += a2 * bv.y; acc[2][2] += a2 * bv.z; acc[2][3] += a2 * bv.w;
            acc[3][0] += a3 * bv.x; acc[3][1] += a3 * bv.y; acc[3][2] += a3 * bv.z; acc[3][3] += a3 * bv.w;
        }
    }
#pragma unroll
    for (int i = 0; i < 4; i++) {
        const float4 o = make_float4(acc[i][0], acc[i][1], acc[i][2], acc[i][3]);
        *(float4*)&ctx[(size_t)(b * S_ + q0 + ty * 4 + i) * D_ + h * 64 + tx * 4] = o;
    }
}

// ---------------- fused residual-add + LayerNorm ----------------
__global__ __launch_bounds__(128)
void ln_kernel(const float* __restrict__ x, const float* __restrict__ add,
               const float* __restrict__ w, const float* __restrict__ bvec,
               float* __restrict__ out)
{
    const int row = blockIdx.x;
    const int tid = threadIdx.x;
    const float* xr = x + (size_t)row * D_;
    const float* ar = add + (size_t)row * D_;
    float v[4];
    float s = 0.f;
#pragma unroll
    for (int i = 0; i < 4; i++) {
        const int c = tid + i * 128;
        v[i] = xr[c] + ar[c];
        s += v[i];
    }
    __shared__ float red[4];
#pragma unroll
    for (int o = 16; o > 0; o >>= 1) s += __shfl_xor_sync(0xFFFFFFFFu, s, o);
    if ((tid & 31) == 0) red[tid >> 5] = s;
    __syncthreads();
    const float mean = (red[0] + red[1] + red[2] + red[3]) * (1.f / 512.f);
    float vs = 0.f;
#pragma unroll
    for (int i = 0; i < 4; i++) {
        const float d = v[i] - mean;
        vs += d * d;
    }
    __syncthreads();
#pragma unroll
    for (int o = 16; o > 0; o >>= 1) vs += __shfl_xor_sync(0xFFFFFFFFu, vs, o);
    if ((tid & 31) == 0) red[tid >> 5] = vs;
    __syncthreads();
    const float rstd = rsqrtf((red[0] + red[1] + red[2] + red[3]) * (1.f / 512.f) + 1e-5f);
    float* orow = out + (size_t)row * D_;
#pragma unroll
    for (int i = 0; i < 4; i++) {
        const int c = tid + i * 128;
        orow[c] = (v[i] - mean) * rstd * w[c] + bvec[c];
    }
}

// ---------------- mean+max pooling over sequence ----------------
__global__ __launch_bounds__(512)
void pool_kernel(const float* __restrict__ x, float* __restrict__ pool)
{
    const int b = blockIdx.x, d = threadIdx.x;
    float s = 0.f, m = -1e30f;
    for (int t = 0; t < S_; t++) {
        const float v = x[(size_t)(b * S_ + t) * D_ + d];
        s += v;
        m = fmaxf(m, v);
    }
    pool[b * (2 * D_) + d] = s * (1.f / 512.f);
    pool[b * (2 * D_) + D_ + d] = m;
}

// ---------------- final head ----------------
__global__ __launch_bounds__(128)
void head2_kernel(const float* __restrict__ h, const float* __restrict__ w,
                  const float* __restrict__ bb, float* __restrict__ out)
{
    const int b = blockIdx.x, tid = threadIdx.x;
    float s = 0.f;
    for (int c = tid; c < D_; c += 128) s += h[(size_t)b * D_ + c] * w[c];
    __shared__ float red[4];
#pragma unroll
    for (int o = 16; o > 0; o >>= 1) s += __shfl_xor_sync(0xFFFFFFFFu, s, o);
    if ((tid & 31) == 0) red[tid >> 5] = s;
    __syncthreads();
    if (tid == 0) out[b] = red[0] + red[1] + red[2] + red[3] + bb[0];
}

// ---------------- launch ----------------
extern "C" void kernel_launch(void* const* d_in, const int* in_sizes, int n_in,
                              void* d_out, int out_size)
{
    const float* x_in = (const float*)d_in[0];
    const float* w_in = (const float*)d_in[1];
    const float* b_in = (const float*)d_in[2];
    const float* inpw = (const float*)d_in[3];
    const float* inpb = (const float*)d_in[4];
    const float* outw = (const float*)d_in[5];
    const float* outb = (const float*)d_in[6];
    const float* ln1w = (const float*)d_in[7];
    const float* ln1b = (const float*)d_in[8];
    const float* ln2w = (const float*)d_in[9];
    const float* ln2b = (const float*)d_in[10];
    const float* ff1w = (const float*)d_in[11];
    const float* ff1b = (const float*)d_in[12];
    const float* ff2w = (const float*)d_in[13];
    const float* ff2b = (const float*)d_in[14];
    const float* h1w  = (const float*)d_in[15];
    const float* h1b  = (const float*)d_in[16];
    const float* h2w  = (const float*)d_in[17];
    const float* h2b  = (const float*)d_in[18];

    float* out  = (float*)d_out;
    float* attn = out + 32;   // [L,B,H,S,S] follows the [B,1] output

    float *px, *pqkv, *pctx, *ptmp, *pff, *ppool, *phead;
    cudaGetSymbolAddress((void**)&px,    g_x);
    cudaGetSymbolAddress((void**)&pqkv,  g_qkv);
    cudaGetSymbolAddress((void**)&pctx,  g_ctx);
    cudaGetSymbolAddress((void**)&ptmp,  g_tmp);
    cudaGetSymbolAddress((void**)&pff,   g_ff);
    cudaGetSymbolAddress((void**)&ppool, g_pool);
    cudaGetSymbolAddress((void**)&phead, g_head);

    const int sc_smem = SC_SMEM_FLOATS * (int)sizeof(float);
    cudaFuncSetAttribute(attn_kernel, cudaFuncAttributeMaxDynamicSharedMemorySize, sc_smem);
    cudaFuncSetAttribute(gemm_mma<0>, cudaFuncAttributeMaxDynamicSharedMemorySize, MM_SMEM);
    cudaFuncSetAttribute(gemm_mma<1>, cudaFuncAttributeMaxDynamicSharedMemorySize, MM_SMEM);

    const dim3 blk(256);

    // input projection + positional encoding (fused, SIMT — K=64 is small)
    gemm_kernel<2><<<dim3(D_ / 128, TOK_ / 128), blk>>>(x_in, w_in, b_in, px, TOK_, D_, IN_);

    for (int l = 0; l < L_; l++) {
        // QKV projection (tensor core tf32)
        gemm_mma<0><<<dim3((3 * D_) / 128, TOK_ / 128), blk, MM_SMEM>>>(
            px, inpw + (size_t)l * 3 * D_ * D_, inpb + l * 3 * D_, pqkv, TOK_, 3 * D_, D_);

        float* attn_l = attn + (size_t)l * B_ * H_ * S_ * S_;

        attn_kernel<<<dim3(S_ / 16, B_ * H_), blk, sc_smem>>>(pqkv, attn_l);
        ctx_kernel<<<dim3(S_ / 64, B_ * H_), blk>>>(attn_l, pqkv, pctx);

        // output projection (tensor core)
        gemm_mma<0><<<dim3(D_ / 128, TOK_ / 128), blk, MM_SMEM>>>(
            pctx, outw + (size_t)l * D_ * D_, outb + l * D_, ptmp, TOK_, D_, D_);

        ln_kernel<<<TOK_, 128>>>(px, ptmp, ln1w + l * D_, ln1b + l * D_, px);

        // ff1 + GELU (tensor core)
        gemm_mma<1><<<dim3(FF_ / 128, TOK_ / 128), blk, MM_SMEM>>>(
            px, ff1w + (size_t)l * FF_ * D_, ff1b + l * FF_, pff, TOK_, FF_, D_);

        // ff2 (tensor core)
        gemm_mma<0><<<dim3(D_ / 128, TOK_ / 128), blk, MM_SMEM>>>(
            pff, ff2w + (size_t)l * D_ * FF_, ff2b + l * D_, ptmp, TOK_, D_, FF_);

        ln_kernel<<<TOK_, 128>>>(px, ptmp, ln2w + l * D_, ln2b + l * D_, px);
    }

    pool_kernel<<<B_, 512>>>(px, ppool);
    gemm_kernel<1><<<dim3(D_ / 128, 1), blk>>>(ppool, h1w, h1b, phead, B_, D_, 2 * D_);
    head2_kernel<<<B_, 128>>>(phead, h2w, h2b, out);
}

// round 4
// speedup vs baseline: 2.5173x; 2.0700x over previous
#include <cuda_runtime.h>
#include <cstdint>
#include <math.h>

#define B_   32
#define S_   512
#define IN_  64
#define D_   512
#define H_   8
#define L_   4
#define FF_  2048
#define TOK_ (B_ * S_)   // 16384

// ---------------- scratch (device globals; no allocation allowed) ----------------
__device__ __align__(16) float g_x[TOK_ * D_];
__device__ __align__(16) float g_qkv[TOK_ * 3 * D_];
__device__ __align__(16) float g_ctx[TOK_ * D_];
__device__ __align__(16) float g_tmp[TOK_ * D_];
__device__ __align__(16) float g_ff[TOK_ * FF_];
__device__ __align__(16) float g_pool[B_ * 2 * D_];
__device__ __align__(16) float g_head[B_ * D_];
// tf32-rounded weights: [in_proj | out_proj | ff1 | ff2]
#define WB_IN  0
#define WB_OUT (WB_IN  + L_ * 3 * D_ * D_)
#define WB_FF1 (WB_OUT + L_ * D_ * D_)
#define WB_FF2 (WB_FF1 + L_ * FF_ * D_)
#define WB_TOT (WB_FF2 + L_ * D_ * FF_)
__device__ __align__(16) float g_wbuf[WB_TOT];

__device__ __forceinline__ float gelu_exact(float v) {
    return 0.5f * v * (1.0f + erff(v * 0.7071067811865475f));
}
__device__ __forceinline__ float tf32r(float f) {
    uint32_t u;
    asm("cvt.rna.tf32.f32 %0, %1;" : "=r"(u) : "f"(f));
    return __uint_as_float(u);
}
// fast exp: poly 2^f, all fma/alu pipe (no MUFU, no libm). valid |x| < ~80.
__device__ __forceinline__ float fast_exp(float x) {
    float y = x * 1.442695041f;
    float z = y + 12582912.f;              // round-to-int magic (|y| < 2^22)
    float k = z - 12582912.f;
    float f = y - k;
    float p = 1.3333558e-3f;
    p = fmaf(p, f, 9.6181291e-3f);
    p = fmaf(p, f, 5.5504109e-2f);
    p = fmaf(p, f, 2.4022651e-1f);
    p = fmaf(p, f, 6.9314718e-1f);
    p = fmaf(p, f, 1.0f);
    int ki = (__float_as_int(z) - 0x4B400000) << 23;
    return __int_as_float(__float_as_int(p) + ki);
}
__device__ __forceinline__ uint32_t smem_u32(const void* p) {
    uint32_t a;
    asm("{ .reg .u64 t; cvta.to.shared.u64 t, %1; cvt.u32.u64 %0, t; }" : "=r"(a) : "l"(p));
    return a;
}
__device__ __forceinline__ void mma_tf32(float* c, const uint32_t* a, const uint32_t* b) {
    asm volatile(
        "mma.sync.aligned.m16n8k8.row.col.f32.tf32.tf32.f32 "
        "{%0,%1,%2,%3}, {%4,%5,%6,%7}, {%8,%9}, {%0,%1,%2,%3};"
        : "+f"(c[0]), "+f"(c[1]), "+f"(c[2]), "+f"(c[3])
        : "r"(a[0]), "r"(a[1]), "r"(a[2]), "r"(a[3]), "r"(b[0]), "r"(b[1]));
}
#define FBITS(x) __float_as_uint(x)

// ---------------- tf32 rounding copy (weights, once per replay) ----------------
__global__ __launch_bounds__(256)
void round_copy(const float* __restrict__ src, float* __restrict__ dst, int n)
{
    const int i = (blockIdx.x * 256 + threadIdx.x) * 4;
    if (i < n) {
        float4 v = *(const float4*)(src + i);
        v.x = tf32r(v.x); v.y = tf32r(v.y); v.z = tf32r(v.z); v.w = tf32r(v.w);
        *(float4*)(dst + i) = v;
    }
}

// ======================= mma.sync tf32 GEMM =======================
// C[M,N] = act(A[M,K] * W[N,K]^T + bias). M%128==0, N%128==0, K%32==0, K>=64.
// All operands must already be tf32-rounded (raw bits fed to HMMA).
#define MM_RS     36
#define MM_TILEB  (128 * MM_RS * 4)
#define MM_STAGE  (2 * MM_TILEB)
#define MM_SMEM   (2 * MM_STAGE)        // 73728 B

__device__ __forceinline__ void mm_cp_issue(
    const float* __restrict__ A, const float* __restrict__ W,
    uint32_t sbase, int stage, int m0, int n0, int K, int k0, int tid)
{
    const uint32_t as = sbase + stage * MM_STAGE;
    const uint32_t bs = as + MM_TILEB;
#pragma unroll
    for (int i = 0; i < 4; i++) {
        const int idx = i * 256 + tid;
        const int row = idx >> 3;
        const int q = idx & 7;
        const uint32_t so = (uint32_t)(row * (MM_RS * 4) + q * 16);
        const float* ga = A + (size_t)(m0 + row) * K + k0 + q * 4;
        const float* gw = W + (size_t)(n0 + row) * K + k0 + q * 4;
        asm volatile("cp.async.cg.shared.global [%0], [%1], 16;" :: "r"(as + so), "l"(ga));
        asm volatile("cp.async.cg.shared.global [%0], [%1], 16;" :: "r"(bs + so), "l"(gw));
    }
    asm volatile("cp.async.commit_group;" ::: "memory");
}

template <int ACT, int RND>   // ACT: 0=none,1=GELU ; RND: round output to tf32
__global__ __launch_bounds__(256)
void gemm_mma(const float* __restrict__ A, const float* __restrict__ W,
              const float* __restrict__ bias, float* __restrict__ C,
              int M, int N, int K)
{
    extern __shared__ char smem[];
    const uint32_t sbase = smem_u32(smem);
    const int tid = threadIdx.x;
    const int lane = tid & 31, wid = tid >> 5;
    const int g = lane >> 2, t4 = lane & 3;
    const int wm = wid & 3;
    const int wn = wid >> 2;
    const int m0 = blockIdx.y * 128, n0 = blockIdx.x * 128;

    float acc[2][8][4];
#pragma unroll
    for (int mt = 0; mt < 2; mt++)
#pragma unroll
        for (int nt = 0; nt < 8; nt++)
#pragma unroll
            for (int j = 0; j < 4; j++) acc[mt][nt][j] = 0.f;

    const int nch = K >> 5;
    mm_cp_issue(A, W, sbase, 0, m0, n0, K, 0, tid);
    mm_cp_issue(A, W, sbase, 1, m0, n0, K, 32, tid);

    for (int c = 0; c < nch; c++) {
        if (c + 1 < nch)
            asm volatile("cp.async.wait_group 1;" ::: "memory");
        else
            asm volatile("cp.async.wait_group 0;" ::: "memory");
        __syncthreads();

        const int s = c & 1;
        const float* as = (const float*)(smem + s * MM_STAGE);
        const float* bs = as + 128 * MM_RS;

#pragma unroll
        for (int ks = 0; ks < 4; ks++) {
            uint32_t afr[2][4];
#pragma unroll
            for (int mt = 0; mt < 2; mt++) {
                const float* ap = as + (wm * 32 + mt * 16 + g) * MM_RS + ks * 8 + t4;
                afr[mt][0] = FBITS(ap[0]);
                afr[mt][1] = FBITS(ap[8 * MM_RS]);
                afr[mt][2] = FBITS(ap[4]);
                afr[mt][3] = FBITS(ap[8 * MM_RS + 4]);
            }
            uint32_t bfr[8][2];
#pragma unroll
            for (int nt = 0; nt < 8; nt++) {
                const float* bp = bs + (wn * 64 + nt * 8 + g) * MM_RS + ks * 8 + t4;
                bfr[nt][0] = FBITS(bp[0]);
                bfr[nt][1] = FBITS(bp[4]);
            }
#pragma unroll
            for (int mt = 0; mt < 2; mt++)
#pragma unroll
                for (int nt = 0; nt < 8; nt++)
                    mma_tf32(acc[mt][nt], afr[mt], bfr[nt]);
        }
        __syncthreads();
        if (c + 2 < nch)
            mm_cp_issue(A, W, sbase, s, m0, n0, K, (c + 2) * 32, tid);
    }

#pragma unroll
    for (int mt = 0; mt < 2; mt++) {
        const int r0 = m0 + wm * 32 + mt * 16 + g;
#pragma unroll
        for (int nt = 0; nt < 8; nt++) {
            const int cb = n0 + wn * 64 + nt * 8 + 2 * t4;
            const float b0 = bias[cb], b1 = bias[cb + 1];
            float v0 = acc[mt][nt][0] + b0;
            float v1 = acc[mt][nt][1] + b1;
            float v2 = acc[mt][nt][2] + b0;
            float v3 = acc[mt][nt][3] + b1;
            if (ACT == 1) {
                v0 = gelu_exact(v0); v1 = gelu_exact(v1);
                v2 = gelu_exact(v2); v3 = gelu_exact(v3);
            }
            if (RND) {
                v0 = tf32r(v0); v1 = tf32r(v1); v2 = tf32r(v2); v3 = tf32r(v3);
            }
            *(float2*)&C[(size_t)r0 * N + cb]       = make_float2(v0, v1);
            *(float2*)&C[(size_t)(r0 + 8) * N + cb] = make_float2(v2, v3);
        }
    }
}

// ======================= fused attention =======================
// block = (q-tile of 32 rows) x (b*H + h). 256 threads (8 warps).
// scores (tf32 mma) -> softmax (fast_exp) -> probs to d_out (tf32-rounded) -> P@V (tf32 mma) -> ctx.
#define FA_QS 68       // Q tile stride (floats)
#define FA_SS 516      // scores stride
#define FA_KS 68       // K tile stride
#define FA_VS 65       // V tile stride (k-major frag reads conflict-free)
#define FA_SMEM_FLOATS (32 * FA_QS + 32 * FA_SS + 128 * FA_KS)
#define FA_SMEM_BYTES  (FA_SMEM_FLOATS * 4)     // 109568

__global__ __launch_bounds__(256)
void fused_attn(const float* __restrict__ qkv, float* __restrict__ probs,
                float* __restrict__ ctx)
{
    extern __shared__ float sm[];
    float* qs = sm;                       // [32][68]
    float* sc = sm + 32 * FA_QS;          // [32][516]
    float* kv = sc + 32 * FA_SS;          // [128][68] (K) / [128][65] (V)

    const int tid = threadIdx.x;
    const int lane = tid & 31, wid = tid >> 5;
    const int g = lane >> 2, t4 = lane & 3;
    const int q0 = blockIdx.x * 32;
    const int bh = blockIdx.y;
    const int b = bh >> 3, h = bh & 7;
    const int wm = wid & 1;      // 2 m-tiles of 16
    const int wn = wid >> 1;     // 4 n-groups

    // ---- load Q tile (scaled by 1/8), 32x64 ----
    {
        const int r = tid >> 3;
        const int d0 = (tid & 7) * 8;
        const float* src = qkv + (size_t)(b * S_ + q0 + r) * 1536 + h * 64 + d0;
        const float4 v0 = *(const float4*)src;
        const float4 v1 = *(const float4*)(src + 4);
        float* dst = qs + r * FA_QS + d0;
        dst[0] = v0.x * 0.125f; dst[1] = v0.y * 0.125f;
        dst[2] = v0.z * 0.125f; dst[3] = v0.w * 0.125f;
        dst[4] = v1.x * 0.125f; dst[5] = v1.y * 0.125f;
        dst[6] = v1.z * 0.125f; dst[7] = v1.w * 0.125f;
    }
    // NOTE: Q scaled by 0.125 then fed to mma: 0.125 is a power of 2, so scaled
    // values remain exactly tf32 (qkv was emitted tf32-rounded).

    // ---- scores: 4 K-tiles of 128 ----
    for (int kt = 0; kt < 4; kt++) {
        __syncthreads();
#pragma unroll
        for (int i = 0; i < 4; i++) {
            const int idx = i * 256 + tid;
            const int r = idx >> 3;
            const int d0 = (idx & 7) * 8;
            const float* src = qkv + (size_t)(b * S_ + kt * 128 + r) * 1536 + D_ + h * 64 + d0;
            const float4 v0 = *(const float4*)src;
            const float4 v1 = *(const float4*)(src + 4);
            float* dst = kv + r * FA_KS + d0;
            dst[0] = v0.x; dst[1] = v0.y; dst[2] = v0.z; dst[3] = v0.w;
            dst[4] = v1.x; dst[5] = v1.y; dst[6] = v1.z; dst[7] = v1.w;
        }
        __syncthreads();

        float acc[4][4];
#pragma unroll
        for (int nt = 0; nt < 4; nt++)
#pragma unroll
            for (int j = 0; j < 4; j++) acc[nt][j] = 0.f;

#pragma unroll
        for (int ks = 0; ks < 8; ks++) {
            uint32_t afr[4];
            const float* ap = qs + (wm * 16 + g) * FA_QS + ks * 8 + t4;
            afr[0] = FBITS(ap[0]);
            afr[1] = FBITS(ap[8 * FA_QS]);
            afr[2] = FBITS(ap[4]);
            afr[3] = FBITS(ap[8 * FA_QS + 4]);
#pragma unroll
            for (int nt = 0; nt < 4; nt++) {
                const float* bp = kv + (wn * 32 + nt * 8 + g) * FA_KS + ks * 8 + t4;
                uint32_t bfr[2] = {FBITS(bp[0]), FBITS(bp[4])};
                mma_tf32(acc[nt], afr, bfr);
            }
        }
#pragma unroll
        for (int nt = 0; nt < 4; nt++) {
            const int col = kt * 128 + wn * 32 + nt * 8 + 2 * t4;
            const int row = wm * 16 + g;
            *(float2*)&sc[row * FA_SS + col]       = make_float2(acc[nt][0], acc[nt][1]);
            *(float2*)&sc[(row + 8) * FA_SS + col] = make_float2(acc[nt][2], acc[nt][3]);
        }
    }
    __syncthreads();

    // ---- softmax (no max-subtract: scores are O(1) by construction) ----
    // each warp: 4 rows. exp via fma-pipe poly; write normalized tf32-rounded
    // probs back to smem (for PV) and to gmem (output).
#pragma unroll
    for (int rr = 0; rr < 4; rr++) {
        const int row = wid * 4 + rr;
        float vals[16];
        float sum = 0.f;
#pragma unroll
        for (int t = 0; t < 4; t++) {
            const float4 v = *(const float4*)&sc[row * FA_SS + lane * 4 + t * 128];
            vals[t * 4 + 0] = fast_exp(v.x);
            vals[t * 4 + 1] = fast_exp(v.y);
            vals[t * 4 + 2] = fast_exp(v.z);
            vals[t * 4 + 3] = fast_exp(v.w);
            sum += vals[t * 4 + 0] + vals[t * 4 + 1] + vals[t * 4 + 2] + vals[t * 4 + 3];
        }
#pragma unroll
        for (int o = 16; o > 0; o >>= 1)
            sum += __shfl_xor_sync(0xFFFFFFFFu, sum, o);
        const float inv = 1.f / sum;
        float* prow = probs + ((size_t)bh * S_ + q0 + row) * S_;
#pragma unroll
        for (int t = 0; t < 4; t++) {
            float4 o;
            o.x = tf32r(vals[t * 4 + 0] * inv);
            o.y = tf32r(vals[t * 4 + 1] * inv);
            o.z = tf32r(vals[t * 4 + 2] * inv);
            o.w = tf32r(vals[t * 4 + 3] * inv);
            *(float4*)&sc[row * FA_SS + lane * 4 + t * 128] = o;
            *(float4*)&prow[lane * 4 + t * 128] = o;
        }
    }

    // ---- ctx = P @ V : 4 V-tiles of 128 ----
    float pacc[2][4];
#pragma unroll
    for (int nt = 0; nt < 2; nt++)
#pragma unroll
        for (int j = 0; j < 4; j++) pacc[nt][j] = 0.f;

    for (int vt = 0; vt < 4; vt++) {
        __syncthreads();
#pragma unroll
        for (int i = 0; i < 8; i++) {
            const int idx = i * 256 + tid;
            const int r = idx >> 4;              // 0..127
            const int d0 = (idx & 15) * 4;       // 0..60
            const float4 v = *(const float4*)&qkv[(size_t)(b * S_ + vt * 128 + r) * 1536 + 2 * D_ + h * 64 + d0];
            float* dst = kv + r * FA_VS + d0;
            dst[0] = v.x; dst[1] = v.y; dst[2] = v.z; dst[3] = v.w;
        }
        __syncthreads();

#pragma unroll
        for (int ks = 0; ks < 16; ks++) {
            uint32_t afr[4];
            const float* ap = sc + (wm * 16 + g) * FA_SS + vt * 128 + ks * 8 + t4;
            afr[0] = FBITS(ap[0]);
            afr[1] = FBITS(ap[8 * FA_SS]);
            afr[2] = FBITS(ap[4]);
            afr[3] = FBITS(ap[8 * FA_SS + 4]);
#pragma unroll
            for (int nt = 0; nt < 2; nt++) {
                // B[n=d][k=s] read from V natural layout [s][d], stride 65
                const float* bp = kv + (ks * 8 + t4) * FA_VS + wn * 16 + nt * 8 + g;
                uint32_t bfr[2] = {FBITS(bp[0]), FBITS(bp[4 * FA_VS])};
                mma_tf32(pacc[nt], afr, bfr);
            }
        }
    }

    // write ctx (tf32-rounded: feeds out_proj mma)
#pragma unroll
    for (int nt = 0; nt < 2; nt++) {
        const int row = b * S_ + q0 + wm * 16 + g;
        const int col = h * 64 + wn * 16 + nt * 8 + 2 * t4;
        *(float2*)&ctx[(size_t)row * D_ + col] =
            make_float2(tf32r(pacc[nt][0]), tf32r(pacc[nt][1]));
        *(float2*)&ctx[(size_t)(row + 8) * D_ + col] =
            make_float2(tf32r(pacc[nt][2]), tf32r(pacc[nt][3]));
    }
}

// ---------------- SIMT GEMM (input proj / head1) ----------------
template <int ACT>   // 0=none, 1=GELU, 2=add PE + tf32 round
__global__ __launch_bounds__(256)
void gemm_kernel(const float* __restrict__ A, const float* __restrict__ W,
                 const float* __restrict__ bias, float* __restrict__ C,
                 int M, int N, int K)
{
    __shared__ __align__(16) float As[8][128];
    __shared__ __align__(16) float Ws[8][128];

    const int tid = threadIdx.x;
    const int tx = tid & 15;
    const int ty = tid >> 4;
    const int m0 = blockIdx.y * 128;
    const int n0 = blockIdx.x * 128;

    float acc[2][2][4][4];
#pragma unroll
    for (int p = 0; p < 2; p++)
#pragma unroll
        for (int q = 0; q < 2; q++)
#pragma unroll
            for (int i = 0; i < 4; i++)
#pragma unroll
                for (int j = 0; j < 4; j++) acc[p][q][i][j] = 0.f;

    const int lr = tid >> 1;
    const int lk = (tid & 1) * 4;
    const float* Ag = A + (size_t)(m0 + lr) * K + lk;
    const float* Wg = W + (size_t)(n0 + lr) * K + lk;
    const bool aval = (m0 + lr) < M;

    for (int k0 = 0; k0 < K; k0 += 8) {
        float4 av = make_float4(0.f, 0.f, 0.f, 0.f);
        if (aval) av = *(const float4*)(Ag + k0);
        const float4 wv = *(const float4*)(Wg + k0);
        __syncthreads();
        As[lk + 0][lr] = av.x; As[lk + 1][lr] = av.y;
        As[lk + 2][lr] = av.z; As[lk + 3][lr] = av.w;
        Ws[lk + 0][lr] = wv.x; Ws[lk + 1][lr] = wv.y;
        Ws[lk + 2][lr] = wv.z; Ws[lk + 3][lr] = wv.w;
        __syncthreads();
#pragma unroll
        for (int kk = 0; kk < 8; kk++) {
            const float4 a0 = *(const float4*)&As[kk][ty * 4];
            const float4 a1 = *(const float4*)&As[kk][64 + ty * 4];
            const float4 b0 = *(const float4*)&Ws[kk][tx * 4];
            const float4 b1 = *(const float4*)&Ws[kk][64 + tx * 4];
            const float ar[2][4] = {{a0.x, a0.y, a0.z, a0.w}, {a1.x, a1.y, a1.z, a1.w}};
            const float br[2][4] = {{b0.x, b0.y, b0.z, b0.w}, {b1.x, b1.y, b1.z, b1.w}};
#pragma unroll
            for (int p = 0; p < 2; p++)
#pragma unroll
                for (int q = 0; q < 2; q++)
#pragma unroll
                    for (int i = 0; i < 4; i++)
#pragma unroll
                        for (int j = 0; j < 4; j++)
                            acc[p][q][i][j] += ar[p][i] * br[q][j];
        }
    }

#pragma unroll
    for (int p = 0; p < 2; p++) {
#pragma unroll
        for (int i = 0; i < 4; i++) {
            const int m = m0 + p * 64 + ty * 4 + i;
            if (m >= M) continue;
#pragma unroll
            for (int q = 0; q < 2; q++) {
                const int c = n0 + q * 64 + tx * 4;
                float4 o;
                float* po = &o.x;
#pragma unroll
                for (int j = 0; j < 4; j++) {
                    float v = acc[p][q][i][j] + bias[c + j];
                    if (ACT == 1) {
                        v = gelu_exact(v);
                    } else if (ACT == 2) {
                        const int d = c + j;
                        const int s = m & (S_ - 1);
                        const float freq = expf(-9.210340371976184f * (float)(d & ~1) / (float)D_);
                        const float ang = (float)s * freq;
                        v += (d & 1) ? cosf(ang) : sinf(ang);
                        v = tf32r(v);
                    }
                    po[j] = v;
                }
                *(float4*)&C[(size_t)m * N + c] = o;
            }
        }
    }
}

// ---------------- fused residual-add + LayerNorm (tf32-rounded output) ----------------
__global__ __launch_bounds__(128)
void ln_kernel(const float* __restrict__ x, const float* __restrict__ add,
               const float* __restrict__ w, const float* __restrict__ bvec,
               float* __restrict__ out)
{
    const int row = blockIdx.x;
    const int tid = threadIdx.x;
    const float* xr = x + (size_t)row * D_;
    const float* ar = add + (size_t)row * D_;
    float v[4];
    float s = 0.f;
#pragma unroll
    for (int i = 0; i < 4; i++) {
        const int c = tid + i * 128;
        v[i] = xr[c] + ar[c];
        s += v[i];
    }
    __shared__ float red[4];
#pragma unroll
    for (int o = 16; o > 0; o >>= 1) s += __shfl_xor_sync(0xFFFFFFFFu, s, o);
    if ((tid & 31) == 0) red[tid >> 5] = s;
    __syncthreads();
    const float mean = (red[0] + red[1] + red[2] + red[3]) * (1.f / 512.f);
    float vs = 0.f;
#pragma unroll
    for (int i = 0; i < 4; i++) {
        const float d = v[i] - mean;
        vs += d * d;
    }
    __syncthreads();
#pragma unroll
    for (int o = 16; o > 0; o >>= 1) vs += __shfl_xor_sync(0xFFFFFFFFu, vs, o);
    if ((tid & 31) == 0) red[tid >> 5] = vs;
    __syncthreads();
    const float rstd = rsqrtf((red[0] + red[1] + red[2] + red[3]) * (1.f / 512.f) + 1e-5f);
    float* orow = out + (size_t)row * D_;
#pragma unroll
    for (int i = 0; i < 4; i++) {
        const int c = tid + i * 128;
        orow[c] = tf32r((v[i] - mean) * rstd * w[c] + bvec[c]);
    }
}

// ---------------- mean+max pooling over sequence ----------------
__global__ __launch_bounds__(512)
void pool_kernel(const float* __restrict__ x, float* __restrict__ pool)
{
    const int b = blockIdx.x, d = threadIdx.x;
    float s = 0.f, m = -1e30f;
    for (int t = 0; t < S_; t++) {
        const float v = x[(size_t)(b * S_ + t) * D_ + d];
        s += v;
        m = fmaxf(m, v);
    }
    pool[b * (2 * D_) + d] = s * (1.f / 512.f);
    pool[b * (2 * D_) + D_ + d] = m;
}

// ---------------- final head ----------------
__global__ __launch_bounds__(128)
void head2_kernel(const float* __restrict__ h, const float* __restrict__ w,
                  const float* __restrict__ bb, float* __restrict__ out)
{
    const int b = blockIdx.x, tid = threadIdx.x;
    float s = 0.f;
    for (int c = tid; c < D_; c += 128) s += h[(size_t)b * D_ + c] * w[c];
    __shared__ float red[4];
#pragma unroll
    for (int o = 16; o > 0; o >>= 1) s += __shfl_xor_sync(0xFFFFFFFFu, s, o);
    if ((tid & 31) == 0) red[tid >> 5] = s;
    __syncthreads();
    if (tid == 0) out[b] = red[0] + red[1] + red[2] + red[3] + bb[0];
}

// ---------------- launch ----------------
extern "C" void kernel_launch(void* const* d_in, const int* in_sizes, int n_in,
                              void* d_out, int out_size)
{
    const float* x_in = (const float*)d_in[0];
    const float* w_in = (const float*)d_in[1];
    const float* b_in = (const float*)d_in[2];
    const float* inpw = (const float*)d_in[3];
    const float* inpb = (const float*)d_in[4];
    const float* outw = (const float*)d_in[5];
    const float* outb = (const float*)d_in[6];
    const float* ln1w = (const float*)d_in[7];
    const float* ln1b = (const float*)d_in[8];
    const float* ln2w = (const float*)d_in[9];
    const float* ln2b = (const float*)d_in[10];
    const float* ff1w = (const float*)d_in[11];
    const float* ff1b = (const float*)d_in[12];
    const float* ff2w = (const float*)d_in[13];
    const float* ff2b = (const float*)d_in[14];
    const float* h1w  = (const float*)d_in[15];
    const float* h1b  = (const float*)d_in[16];
    const float* h2w  = (const float*)d_in[17];
    const float* h2b  = (const float*)d_in[18];

    float* out  = (float*)d_out;
    float* attn = out + 32;   // [L,B,H,S,S] follows the [B,1] output

    float *px, *pqkv, *pctx, *ptmp, *pff, *ppool, *phead, *pwb;
    cudaGetSymbolAddress((void**)&px,    g_x);
    cudaGetSymbolAddress((void**)&pqkv,  g_qkv);
    cudaGetSymbolAddress((void**)&pctx,  g_ctx);
    cudaGetSymbolAddress((void**)&ptmp,  g_tmp);
    cudaGetSymbolAddress((void**)&pff,   g_ff);
    cudaGetSymbolAddress((void**)&ppool, g_pool);
    cudaGetSymbolAddress((void**)&phead, g_head);
    cudaGetSymbolAddress((void**)&pwb,   g_wbuf);

    cudaFuncSetAttribute(gemm_mma<0,1>, cudaFuncAttributeMaxDynamicSharedMemorySize, MM_SMEM);
    cudaFuncSetAttribute(gemm_mma<0,0>, cudaFuncAttributeMaxDynamicSharedMemorySize, MM_SMEM);
    cudaFuncSetAttribute(gemm_mma<1,1>, cudaFuncAttributeMaxDynamicSharedMemorySize, MM_SMEM);
    cudaFuncSetAttribute(fused_attn, cudaFuncAttributeMaxDynamicSharedMemorySize, FA_SMEM_BYTES);

    const dim3 blk(256);

    // tf32-round all weights once (graph replays include this; ~25us)
    {
        const int n_in_w  = L_ * 3 * D_ * D_;
        const int n_out_w = L_ * D_ * D_;
        const int n_ff1_w = L_ * FF_ * D_;
        const int n_ff2_w = L_ * D_ * FF_;
        round_copy<<<(n_in_w  + 1023) / 1024, 256>>>(inpw, pwb + WB_IN,  n_in_w);
        round_copy<<<(n_out_w + 1023) / 1024, 256>>>(outw, pwb + WB_OUT, n_out_w);
        round_copy<<<(n_ff1_w + 1023) / 1024, 256>>>(ff1w, pwb + WB_FF1, n_ff1_w);
        round_copy<<<(n_ff2_w + 1023) / 1024, 256>>>(ff2w, pwb + WB_FF2, n_ff2_w);
    }

    // input projection + PE (SIMT, output tf32-rounded)
    gemm_kernel<2><<<dim3(D_ / 128, TOK_ / 128), blk>>>(x_in, w_in, b_in, px, TOK_, D_, IN_);

    for (int l = 0; l < L_; l++) {
        // QKV projection (output rounded: feeds attention mma)
        gemm_mma<0,1><<<dim3((3 * D_) / 128, TOK_ / 128), blk, MM_SMEM>>>(
            px, pwb + WB_IN + (size_t)l * 3 * D_ * D_, inpb + l * 3 * D_, pqkv, TOK_, 3 * D_, D_);

        float* attn_l = attn + (size_t)l * B_ * H_ * S_ * S_;

        // fused scores + softmax + probs-out + P@V
        fused_attn<<<dim3(S_ / 32, B_ * H_), blk, FA_SMEM_BYTES>>>(pqkv, attn_l, pctx);

        // output projection (feeds LN: no rounding)
        gemm_mma<0,0><<<dim3(D_ / 128, TOK_ / 128), blk, MM_SMEM>>>(
            pctx, pwb + WB_OUT + (size_t)l * D_ * D_, outb + l * D_, ptmp, TOK_, D_, D_);

        ln_kernel<<<TOK_, 128>>>(px, ptmp, ln1w + l * D_, ln1b + l * D_, px);

        // ff1 + GELU (output rounded: feeds ff2 mma)
        gemm_mma<1,1><<<dim3(FF_ / 128, TOK_ / 128), blk, MM_SMEM>>>(
            px, pwb + WB_FF1 + (size_t)l * FF_ * D_, ff1b + l * FF_, pff, TOK_, FF_, D_);

        // ff2 (feeds LN: no rounding)
        gemm_mma<0,0><<<dim3(D_ / 128, TOK_ / 128), blk, MM_SMEM>>>(
            pff, pwb + WB_FF2 + (size_t)l * D_ * FF_, ff2b + l * D_, ptmp, TOK_, D_, FF_);

        ln_kernel<<<TOK_, 128>>>(px, ptmp, ln2w + l * D_, ln2b + l * D_, px);
    }

    pool_kernel<<<B_, 512>>>(px, ppool);
    gemm_kernel<1><<<dim3(D_ / 128, 1), blk>>>(ppool, h1w, h1b, phead, B_, D_, 2 * D_);
    head2_kernel<<<B_, 128>>>(phead, h2w, h2b, out);
}

// round 5
// speedup vs baseline: 2.7867x; 1.1070x over previous
#include <cuda_runtime.h>
#include <cstdint>
#include <math.h>

#define B_   32
#define S_   512
#define IN_  64
#define D_   512
#define H_   8
#define L_   4
#define FF_  2048
#define TOK_ (B_ * S_)   // 16384

// ---------------- scratch (device globals; no allocation allowed) ----------------
__device__ __align__(16) float g_x[TOK_ * D_];
__device__ __align__(16) float g_qkv[TOK_ * 3 * D_];
__device__ __align__(16) float g_ctx[TOK_ * D_];
__device__ __align__(16) float g_tmp[TOK_ * D_];
__device__ __align__(16) float g_ff[TOK_ * FF_];
__device__ __align__(16) float g_pool[B_ * 2 * D_];
__device__ __align__(16) float g_head[B_ * D_];
// tf32-rounded weights: [in_proj | out_proj | ff1 | ff2]
#define WB_IN  0
#define WB_OUT (WB_IN  + L_ * 3 * D_ * D_)
#define WB_FF1 (WB_OUT + L_ * D_ * D_)
#define WB_FF2 (WB_FF1 + L_ * FF_ * D_)
#define WB_TOT (WB_FF2 + L_ * D_ * FF_)
__device__ __align__(16) float g_wbuf[WB_TOT];

__device__ __forceinline__ float gelu_exact(float v) {
    return 0.5f * v * (1.0f + erff(v * 0.7071067811865475f));
}
__device__ __forceinline__ float tf32r(float f) {
    uint32_t u;
    asm("cvt.rna.tf32.f32 %0, %1;" : "=r"(u) : "f"(f));
    return __uint_as_float(u);
}
// fast exp: poly 2^f, all fma/alu pipe (no MUFU, no libm). valid |x| < ~80.
__device__ __forceinline__ float fast_exp(float x) {
    float y = x * 1.442695041f;
    float z = y + 12582912.f;
    float k = z - 12582912.f;
    float f = y - k;
    float p = 1.3333558e-3f;
    p = fmaf(p, f, 9.6181291e-3f);
    p = fmaf(p, f, 5.5504109e-2f);
    p = fmaf(p, f, 2.4022651e-1f);
    p = fmaf(p, f, 6.9314718e-1f);
    p = fmaf(p, f, 1.0f);
    int ki = (__float_as_int(z) - 0x4B400000) << 23;
    return __int_as_float(__float_as_int(p) + ki);
}
__device__ __forceinline__ uint32_t smem_u32(const void* p) {
    uint32_t a;
    asm("{ .reg .u64 t; cvta.to.shared.u64 t, %1; cvt.u32.u64 %0, t; }" : "=r"(a) : "l"(p));
    return a;
}
__device__ __forceinline__ void mma_tf32(float* c, const uint32_t* a, const uint32_t* b) {
    asm volatile(
        "mma.sync.aligned.m16n8k8.row.col.f32.tf32.tf32.f32 "
        "{%0,%1,%2,%3}, {%4,%5,%6,%7}, {%8,%9}, {%0,%1,%2,%3};"
        : "+f"(c[0]), "+f"(c[1]), "+f"(c[2]), "+f"(c[3])
        : "r"(a[0]), "r"(a[1]), "r"(a[2]), "r"(a[3]), "r"(b[0]), "r"(b[1]));
}
#define FBITS(x) __float_as_uint(x)

// ---------------- tf32 rounding copy (weights, once per replay) ----------------
__global__ __launch_bounds__(256)
void round_copy(const float* __restrict__ src, float* __restrict__ dst, int n)
{
    const int i = (blockIdx.x * 256 + threadIdx.x) * 4;
    if (i < n) {
        float4 v = *(const float4*)(src + i);
        v.x = tf32r(v.x); v.y = tf32r(v.y); v.z = tf32r(v.z); v.w = tf32r(v.w);
        *(float4*)(dst + i) = v;
    }
}

// ======================= mma.sync tf32 GEMM =======================
// C[M,N] = act(A[M,K] * W[N,K]^T + bias). M%128==0, N%128==0, K%32==0, K>=96.
// 128x128x32 CTA tile, 128 threads = 4 warps in 2x2, each warp 64x64.
// 3-stage cp.async pipeline. All operands pre-rounded to tf32 (raw bits fed to HMMA).
#define MM_RS     36
#define MM_TILEB  (128 * MM_RS * 4)      // 18432 B per operand
#define MM_STAGE  (2 * MM_TILEB)         // 36864 B per stage
#define MM_NST    3
#define MM_SMEM   (MM_NST * MM_STAGE)    // 110592 B

__device__ __forceinline__ void mm_cp_issue(
    const float* __restrict__ A, const float* __restrict__ W,
    uint32_t sbase, int stage, int m0, int n0, int K, int k0, int tid)
{
    const uint32_t as = sbase + stage * MM_STAGE;
    const uint32_t bs = as + MM_TILEB;
#pragma unroll
    for (int i = 0; i < 8; i++) {
        const int idx = i * 128 + tid;
        const int row = idx >> 3;
        const int q = idx & 7;
        const uint32_t so = (uint32_t)(row * (MM_RS * 4) + q * 16);
        const float* ga = A + (size_t)(m0 + row) * K + k0 + q * 4;
        const float* gw = W + (size_t)(n0 + row) * K + k0 + q * 4;
        asm volatile("cp.async.cg.shared.global [%0], [%1], 16;" :: "r"(as + so), "l"(ga));
        asm volatile("cp.async.cg.shared.global [%0], [%1], 16;" :: "r"(bs + so), "l"(gw));
    }
    asm volatile("cp.async.commit_group;" ::: "memory");
}

template <int ACT, int RND>   // ACT: 0=none,1=GELU ; RND: round output to tf32
__global__ __launch_bounds__(128, 2)
void gemm_mma(const float* __restrict__ A, const float* __restrict__ W,
              const float* __restrict__ bias, float* __restrict__ C,
              int M, int N, int K)
{
    extern __shared__ char smem[];
    const uint32_t sbase = smem_u32(smem);
    const int tid = threadIdx.x;
    const int lane = tid & 31, wid = tid >> 5;
    const int g = lane >> 2, t4 = lane & 3;
    const int wm = wid & 1;          // M half (64 rows)
    const int wn = wid >> 1;         // N half (64 cols)
    const int m0 = blockIdx.y * 128, n0 = blockIdx.x * 128;

    float acc[4][8][4];
#pragma unroll
    for (int mt = 0; mt < 4; mt++)
#pragma unroll
        for (int nt = 0; nt < 8; nt++)
#pragma unroll
            for (int j = 0; j < 4; j++) acc[mt][nt][j] = 0.f;

    const int nch = K >> 5;          // assume nch >= 3
    mm_cp_issue(A, W, sbase, 0, m0, n0, K, 0, tid);
    mm_cp_issue(A, W, sbase, 1, m0, n0, K, 32, tid);
    mm_cp_issue(A, W, sbase, 2, m0, n0, K, 64, tid);

    int stage = 0;
    for (int c = 0; c < nch; c++) {
        const int rem = nch - 1 - c;
        if (rem >= 2)
            asm volatile("cp.async.wait_group 2;" ::: "memory");
        else if (rem == 1)
            asm volatile("cp.async.wait_group 1;" ::: "memory");
        else
            asm volatile("cp.async.wait_group 0;" ::: "memory");
        __syncthreads();

        const float* as = (const float*)(smem + stage * MM_STAGE);
        const float* bs = as + 128 * MM_RS;

#pragma unroll
        for (int ks = 0; ks < 4; ks++) {
            uint32_t afr[4][4];
#pragma unroll
            for (int mt = 0; mt < 4; mt++) {
                const float* ap = as + (wm * 64 + mt * 16 + g) * MM_RS + ks * 8 + t4;
                afr[mt][0] = FBITS(ap[0]);
                afr[mt][1] = FBITS(ap[8 * MM_RS]);
                afr[mt][2] = FBITS(ap[4]);
                afr[mt][3] = FBITS(ap[8 * MM_RS + 4]);
            }
            uint32_t bfr[8][2];
#pragma unroll
            for (int nt = 0; nt < 8; nt++) {
                const float* bp = bs + (wn * 64 + nt * 8 + g) * MM_RS + ks * 8 + t4;
                bfr[nt][0] = FBITS(bp[0]);
                bfr[nt][1] = FBITS(bp[4]);
            }
#pragma unroll
            for (int mt = 0; mt < 4; mt++)
#pragma unroll
                for (int nt = 0; nt < 8; nt++)
                    mma_tf32(acc[mt][nt], afr[mt], bfr[nt]);
        }
        __syncthreads();
        if (c + 3 < nch)
            mm_cp_issue(A, W, sbase, stage, m0, n0, K, (c + 3) * 32, tid);
        stage = (stage == MM_NST - 1) ? 0 : stage + 1;
    }

#pragma unroll
    for (int mt = 0; mt < 4; mt++) {
        const int r0 = m0 + wm * 64 + mt * 16 + g;
#pragma unroll
        for (int nt = 0; nt < 8; nt++) {
            const int cb = n0 + wn * 64 + nt * 8 + 2 * t4;
            const float b0 = bias[cb], b1 = bias[cb + 1];
            float v0 = acc[mt][nt][0] + b0;
            float v1 = acc[mt][nt][1] + b1;
            float v2 = acc[mt][nt][2] + b0;
            float v3 = acc[mt][nt][3] + b1;
            if (ACT == 1) {
                v0 = gelu_exact(v0); v1 = gelu_exact(v1);
                v2 = gelu_exact(v2); v3 = gelu_exact(v3);
            }
            if (RND) {
                v0 = tf32r(v0); v1 = tf32r(v1); v2 = tf32r(v2); v3 = tf32r(v3);
            }
            *(float2*)&C[(size_t)r0 * N + cb]       = make_float2(v0, v1);
            *(float2*)&C[(size_t)(r0 + 8) * N + cb] = make_float2(v2, v3);
        }
    }
}

// ======================= fused attention =======================
// block = (q-tile of 32 rows) x (b*H + h). 256 threads (8 warps).
#define FA_QS 68
#define FA_SS 516
#define FA_KS 68
#define FA_VS 65
#define FA_SMEM_FLOATS (32 * FA_QS + 32 * FA_SS + 128 * FA_KS)
#define FA_SMEM_BYTES  (FA_SMEM_FLOATS * 4)     // 109568

__global__ __launch_bounds__(256)
void fused_attn(const float* __restrict__ qkv, float* __restrict__ probs,
                float* __restrict__ ctx)
{
    extern __shared__ float sm[];
    float* qs = sm;                       // [32][68]
    float* sc = sm + 32 * FA_QS;          // [32][516]
    float* kv = sc + 32 * FA_SS;          // [128][68] (K) / [128][65] (V)

    const int tid = threadIdx.x;
    const int lane = tid & 31, wid = tid >> 5;
    const int g = lane >> 2, t4 = lane & 3;
    const int q0 = blockIdx.x * 32;
    const int bh = blockIdx.y;
    const int b = bh >> 3, h = bh & 7;
    const int wm = wid & 1;
    const int wn = wid >> 1;

    {
        const int r = tid >> 3;
        const int d0 = (tid & 7) * 8;
        const float* src = qkv + (size_t)(b * S_ + q0 + r) * 1536 + h * 64 + d0;
        const float4 v0 = *(const float4*)src;
        const float4 v1 = *(const float4*)(src + 4);
        float* dst = qs + r * FA_QS + d0;
        dst[0] = v0.x * 0.125f; dst[1] = v0.y * 0.125f;
        dst[2] = v0.z * 0.125f; dst[3] = v0.w * 0.125f;
        dst[4] = v1.x * 0.125f; dst[5] = v1.y * 0.125f;
        dst[6] = v1.z * 0.125f; dst[7] = v1.w * 0.125f;
    }

    for (int kt = 0; kt < 4; kt++) {
        __syncthreads();
#pragma unroll
        for (int i = 0; i < 4; i++) {
            const int idx = i * 256 + tid;
            const int r = idx >> 3;
            const int d0 = (idx & 7) * 8;
            const float* src = qkv + (size_t)(b * S_ + kt * 128 + r) * 1536 + D_ + h * 64 + d0;
            const float4 v0 = *(const float4*)src;
            const float4 v1 = *(const float4*)(src + 4);
            float* dst = kv + r * FA_KS + d0;
            dst[0] = v0.x; dst[1] = v0.y; dst[2] = v0.z; dst[3] = v0.w;
            dst[4] = v1.x; dst[5] = v1.y; dst[6] = v1.z; dst[7] = v1.w;
        }
        __syncthreads();

        float acc[4][4];
#pragma unroll
        for (int nt = 0; nt < 4; nt++)
#pragma unroll
            for (int j = 0; j < 4; j++) acc[nt][j] = 0.f;

#pragma unroll
        for (int ks = 0; ks < 8; ks++) {
            uint32_t afr[4];
            const float* ap = qs + (wm * 16 + g) * FA_QS + ks * 8 + t4;
            afr[0] = FBITS(ap[0]);
            afr[1] = FBITS(ap[8 * FA_QS]);
            afr[2] = FBITS(ap[4]);
            afr[3] = FBITS(ap[8 * FA_QS + 4]);
#pragma unroll
            for (int nt = 0; nt < 4; nt++) {
                const float* bp = kv + (wn * 32 + nt * 8 + g) * FA_KS + ks * 8 + t4;
                uint32_t bfr[2] = {FBITS(bp[0]), FBITS(bp[4])};
                mma_tf32(acc[nt], afr, bfr);
            }
        }
#pragma unroll
        for (int nt = 0; nt < 4; nt++) {
            const int col = kt * 128 + wn * 32 + nt * 8 + 2 * t4;
            const int row = wm * 16 + g;
            *(float2*)&sc[row * FA_SS + col]       = make_float2(acc[nt][0], acc[nt][1]);
            *(float2*)&sc[(row + 8) * FA_SS + col] = make_float2(acc[nt][2], acc[nt][3]);
        }
    }
    __syncthreads();

#pragma unroll
    for (int rr = 0; rr < 4; rr++) {
        const int row = wid * 4 + rr;
        float vals[16];
        float sum = 0.f;
#pragma unroll
        for (int t = 0; t < 4; t++) {
            const float4 v = *(const float4*)&sc[row * FA_SS + lane * 4 + t * 128];
            vals[t * 4 + 0] = fast_exp(v.x);
            vals[t * 4 + 1] = fast_exp(v.y);
            vals[t * 4 + 2] = fast_exp(v.z);
            vals[t * 4 + 3] = fast_exp(v.w);
            sum += vals[t * 4 + 0] + vals[t * 4 + 1] + vals[t * 4 + 2] + vals[t * 4 + 3];
        }
#pragma unroll
        for (int o = 16; o > 0; o >>= 1)
            sum += __shfl_xor_sync(0xFFFFFFFFu, sum, o);
        const float inv = 1.f / sum;
        float* prow = probs + ((size_t)bh * S_ + q0 + row) * S_;
#pragma unroll
        for (int t = 0; t < 4; t++) {
            float4 o;
            o.x = tf32r(vals[t * 4 + 0] * inv);
            o.y = tf32r(vals[t * 4 + 1] * inv);
            o.z = tf32r(vals[t * 4 + 2] * inv);
            o.w = tf32r(vals[t * 4 + 3] * inv);
            *(float4*)&sc[row * FA_SS + lane * 4 + t * 128] = o;
            *(float4*)&prow[lane * 4 + t * 128] = o;
        }
    }

    float pacc[2][4];
#pragma unroll
    for (int nt = 0; nt < 2; nt++)
#pragma unroll
        for (int j = 0; j < 4; j++) pacc[nt][j] = 0.f;

    for (int vt = 0; vt < 4; vt++) {
        __syncthreads();
#pragma unroll
        for (int i = 0; i < 8; i++) {
            const int idx = i * 256 + tid;
            const int r = idx >> 4;
            const int d0 = (idx & 15) * 4;
            const float4 v = *(const float4*)&qkv[(size_t)(b * S_ + vt * 128 + r) * 1536 + 2 * D_ + h * 64 + d0];
            float* dst = kv + r * FA_VS + d0;
            dst[0] = v.x; dst[1] = v.y; dst[2] = v.z; dst[3] = v.w;
        }
        __syncthreads();

#pragma unroll
        for (int ks = 0; ks < 16; ks++) {
            uint32_t afr[4];
            const float* ap = sc + (wm * 16 + g) * FA_SS + vt * 128 + ks * 8 + t4;
            afr[0] = FBITS(ap[0]);
            afr[1] = FBITS(ap[8 * FA_SS]);
            afr[2] = FBITS(ap[4]);
            afr[3] = FBITS(ap[8 * FA_SS + 4]);
#pragma unroll
            for (int nt = 0; nt < 2; nt++) {
                const float* bp = kv + (ks * 8 + t4) * FA_VS + wn * 16 + nt * 8 + g;
                uint32_t bfr[2] = {FBITS(bp[0]), FBITS(bp[4 * FA_VS])};
                mma_tf32(pacc[nt], afr, bfr);
            }
        }
    }

#pragma unroll
    for (int nt = 0; nt < 2; nt++) {
        const int row = b * S_ + q0 + wm * 16 + g;
        const int col = h * 64 + wn * 16 + nt * 8 + 2 * t4;
        *(float2*)&ctx[(size_t)row * D_ + col] =
            make_float2(tf32r(pacc[nt][0]), tf32r(pacc[nt][1]));
        *(float2*)&ctx[(size_t)(row + 8) * D_ + col] =
            make_float2(tf32r(pacc[nt][2]), tf32r(pacc[nt][3]));
    }
}

// ---------------- SIMT GEMM (input proj / head1) ----------------
template <int ACT>   // 0=none, 1=GELU, 2=add PE + tf32 round
__global__ __launch_bounds__(256)
void gemm_kernel(const float* __restrict__ A, const float* __restrict__ W,
                 const float* __restrict__ bias, float* __restrict__ C,
                 int M, int N, int K)
{
    __shared__ __align__(16) float As[8][128];
    __shared__ __align__(16) float Ws[8][128];

    const int tid = threadIdx.x;
    const int tx = tid & 15;
    const int ty = tid >> 4;
    const int m0 = blockIdx.y * 128;
    const int n0 = blockIdx.x * 128;

    float acc[2][2][4][4];
#pragma unroll
    for (int p = 0; p < 2; p++)
#pragma unroll
        for (int q = 0; q < 2; q++)
#pragma unroll
            for (int i = 0; i < 4; i++)
#pragma unroll
                for (int j = 0; j < 4; j++) acc[p][q][i][j] = 0.f;

    const int lr = tid >> 1;
    const int lk = (tid & 1) * 4;
    const float* Ag = A + (size_t)(m0 + lr) * K + lk;
    const float* Wg = W + (size_t)(n0 + lr) * K + lk;
    const bool aval = (m0 + lr) < M;

    for (int k0 = 0; k0 < K; k0 += 8) {
        float4 av = make_float4(0.f, 0.f, 0.f, 0.f);
        if (aval) av = *(const float4*)(Ag + k0);
        const float4 wv = *(const float4*)(Wg + k0);
        __syncthreads();
        As[lk + 0][lr] = av.x; As[lk + 1][lr] = av.y;
        As[lk + 2][lr] = av.z; As[lk + 3][lr] = av.w;
        Ws[lk + 0][lr] = wv.x; Ws[lk + 1][lr] = wv.y;
        Ws[lk + 2][lr] = wv.z; Ws[lk + 3][lr] = wv.w;
        __syncthreads();
#pragma unroll
        for (int kk = 0; kk < 8; kk++) {
            const float4 a0 = *(const float4*)&As[kk][ty * 4];
            const float4 a1 = *(const float4*)&As[kk][64 + ty * 4];
            const float4 b0 = *(const float4*)&Ws[kk][tx * 4];
            const float4 b1 = *(const float4*)&Ws[kk][64 + tx * 4];
            const float ar[2][4] = {{a0.x, a0.y, a0.z, a0.w}, {a1.x, a1.y, a1.z, a1.w}};
            const float br[2][4] = {{b0.x, b0.y, b0.z, b0.w}, {b1.x, b1.y, b1.z, b1.w}};
#pragma unroll
            for (int p = 0; p < 2; p++)
#pragma unroll
                for (int q = 0; q < 2; q++)
#pragma unroll
                    for (int i = 0; i < 4; i++)
#pragma unroll
                        for (int j = 0; j < 4; j++)
                            acc[p][q][i][j] += ar[p][i] * br[q][j];
        }
    }

#pragma unroll
    for (int p = 0; p < 2; p++) {
#pragma unroll
        for (int i = 0; i < 4; i++) {
            const int m = m0 + p * 64 + ty * 4 + i;
            if (m >= M) continue;
#pragma unroll
            for (int q = 0; q < 2; q++) {
                const int c = n0 + q * 64 + tx * 4;
                float4 o;
                float* po = &o.x;
#pragma unroll
                for (int j = 0; j < 4; j++) {
                    float v = acc[p][q][i][j] + bias[c + j];
                    if (ACT == 1) {
                        v = gelu_exact(v);
                    } else if (ACT == 2) {
                        const int d = c + j;
                        const int s = m & (S_ - 1);
                        const float freq = expf(-9.210340371976184f * (float)(d & ~1) / (float)D_);
                        const float ang = (float)s * freq;
                        v += (d & 1) ? cosf(ang) : sinf(ang);
                        v = tf32r(v);
                    }
                    po[j] = v;
                }
                *(float4*)&C[(size_t)m * N + c] = o;
            }
        }
    }
}

// ---------------- fused residual-add + LayerNorm (tf32-rounded output) ----------------
__global__ __launch_bounds__(128)
void ln_kernel(const float* __restrict__ x, const float* __restrict__ add,
               const float* __restrict__ w, const float* __restrict__ bvec,
               float* __restrict__ out)
{
    const int row = blockIdx.x;
    const int tid = threadIdx.x;
    const float* xr = x + (size_t)row * D_;
    const float* ar = add + (size_t)row * D_;
    float v[4];
    float s = 0.f;
#pragma unroll
    for (int i = 0; i < 4; i++) {
        const int c = tid + i * 128;
        v[i] = xr[c] + ar[c];
        s += v[i];
    }
    __shared__ float red[4];
#pragma unroll
    for (int o = 16; o > 0; o >>= 1) s += __shfl_xor_sync(0xFFFFFFFFu, s, o);
    if ((tid & 31) == 0) red[tid >> 5] = s;
    __syncthreads();
    const float mean = (red[0] + red[1] + red[2] + red[3]) * (1.f / 512.f);
    float vs = 0.f;
#pragma unroll
    for (int i = 0; i < 4; i++) {
        const float d = v[i] - mean;
        vs += d * d;
    }
    __syncthreads();
#pragma unroll
    for (int o = 16; o > 0; o >>= 1) vs += __shfl_xor_sync(0xFFFFFFFFu, vs, o);
    if ((tid & 31) == 0) red[tid >> 5] = vs;
    __syncthreads();
    const float rstd = rsqrtf((red[0] + red[1] + red[2] + red[3]) * (1.f / 512.f) + 1e-5f);
    float* orow = out + (size_t)row * D_;
#pragma unroll
    for (int i = 0; i < 4; i++) {
        const int c = tid + i * 128;
        orow[c] = tf32r((v[i] - mean) * rstd * w[c] + bvec[c]);
    }
}

// ---------------- mean+max pooling over sequence ----------------
__global__ __launch_bounds__(512)
void pool_kernel(const float* __restrict__ x, float* __restrict__ pool)
{
    const int b = blockIdx.x, d = threadIdx.x;
    float s = 0.f, m = -1e30f;
    for (int t = 0; t < S_; t++) {
        const float v = x[(size_t)(b * S_ + t) * D_ + d];
        s += v;
        m = fmaxf(m, v);
    }
    pool[b * (2 * D_) + d] = s * (1.f / 512.f);
    pool[b * (2 * D_) + D_ + d] = m;
}

// ---------------- final head ----------------
__global__ __launch_bounds__(128)
void head2_kernel(const float* __restrict__ h, const float* __restrict__ w,
                  const float* __restrict__ bb, float* __restrict__ out)
{
    const int b = blockIdx.x, tid = threadIdx.x;
    float s = 0.f;
    for (int c = tid; c < D_; c += 128) s += h[(size_t)b * D_ + c] * w[c];
    __shared__ float red[4];
#pragma unroll
    for (int o = 16; o > 0; o >>= 1) s += __shfl_xor_sync(0xFFFFFFFFu, s, o);
    if ((tid & 31) == 0) red[tid >> 5] = s;
    __syncthreads();
    if (tid == 0) out[b] = red[0] + red[1] + red[2] + red[3] + bb[0];
}

// ---------------- launch ----------------
extern "C" void kernel_launch(void* const* d_in, const int* in_sizes, int n_in,
                              void* d_out, int out_size)
{
    const float* x_in = (const float*)d_in[0];
    const float* w_in = (const float*)d_in[1];
    const float* b_in = (const float*)d_in[2];
    const float* inpw = (const float*)d_in[3];
    const float* inpb = (const float*)d_in[4];
    const float* outw = (const float*)d_in[5];
    const float* outb = (const float*)d_in[6];
    const float* ln1w = (const float*)d_in[7];
    const float* ln1b = (const float*)d_in[8];
    const float* ln2w = (const float*)d_in[9];
    const float* ln2b = (const float*)d_in[10];
    const float* ff1w = (const float*)d_in[11];
    const float* ff1b = (const float*)d_in[12];
    const float* ff2w = (const float*)d_in[13];
    const float* ff2b = (const float*)d_in[14];
    const float* h1w  = (const float*)d_in[15];
    const float* h1b  = (const float*)d_in[16];
    const float* h2w  = (const float*)d_in[17];
    const float* h2b  = (const float*)d_in[18];

    float* out  = (float*)d_out;
    float* attn = out + 32;   // [L,B,H,S,S] follows the [B,1] output

    float *px, *pqkv, *pctx, *ptmp, *pff, *ppool, *phead, *pwb;
    cudaGetSymbolAddress((void**)&px,    g_x);
    cudaGetSymbolAddress((void**)&pqkv,  g_qkv);
    cudaGetSymbolAddress((void**)&pctx,  g_ctx);
    cudaGetSymbolAddress((void**)&ptmp,  g_tmp);
    cudaGetSymbolAddress((void**)&pff,   g_ff);
    cudaGetSymbolAddress((void**)&ppool, g_pool);
    cudaGetSymbolAddress((void**)&phead, g_head);
    cudaGetSymbolAddress((void**)&pwb,   g_wbuf);

    cudaFuncSetAttribute(gemm_mma<0,1>, cudaFuncAttributeMaxDynamicSharedMemorySize, MM_SMEM);
    cudaFuncSetAttribute(gemm_mma<0,0>, cudaFuncAttributeMaxDynamicSharedMemorySize, MM_SMEM);
    cudaFuncSetAttribute(gemm_mma<1,1>, cudaFuncAttributeMaxDynamicSharedMemorySize, MM_SMEM);
    cudaFuncSetAttribute(fused_attn, cudaFuncAttributeMaxDynamicSharedMemorySize, FA_SMEM_BYTES);

    const dim3 blk(256);
    const dim3 mblk(128);

    // tf32-round all weights once per replay (~30us)
    {
        const int n_in_w  = L_ * 3 * D_ * D_;
        const int n_out_w = L_ * D_ * D_;
        const int n_ff1_w = L_ * FF_ * D_;
        const int n_ff2_w = L_ * D_ * FF_;
        round_copy<<<(n_in_w  + 1023) / 1024, 256>>>(inpw, pwb + WB_IN,  n_in_w);
        round_copy<<<(n_out_w + 1023) / 1024, 256>>>(outw, pwb + WB_OUT, n_out_w);
        round_copy<<<(n_ff1_w + 1023) / 1024, 256>>>(ff1w, pwb + WB_FF1, n_ff1_w);
        round_copy<<<(n_ff2_w + 1023) / 1024, 256>>>(ff2w, pwb + WB_FF2, n_ff2_w);
    }

    // input projection + PE (SIMT, output tf32-rounded)
    gemm_kernel<2><<<dim3(D_ / 128, TOK_ / 128), blk>>>(x_in, w_in, b_in, px, TOK_, D_, IN_);

    for (int l = 0; l < L_; l++) {
        // QKV projection (output rounded: feeds attention mma)
        gemm_mma<0,1><<<dim3((3 * D_) / 128, TOK_ / 128), mblk, MM_SMEM>>>(
            px, pwb + WB_IN + (size_t)l * 3 * D_ * D_, inpb + l * 3 * D_, pqkv, TOK_, 3 * D_, D_);

        float* attn_l = attn + (size_t)l * B_ * H_ * S_ * S_;

        // fused scores + softmax + probs-out + P@V
        fused_attn<<<dim3(S_ / 32, B_ * H_), blk, FA_SMEM_BYTES>>>(pqkv, attn_l, pctx);

        // output projection (feeds LN: no rounding)
        gemm_mma<0,0><<<dim3(D_ / 128, TOK_ / 128), mblk, MM_SMEM>>>(
            pctx, pwb + WB_OUT + (size_t)l * D_ * D_, outb + l * D_, ptmp, TOK_, D_, D_);

        ln_kernel<<<TOK_, 128>>>(px, ptmp, ln1w + l * D_, ln1b + l * D_, px);

        // ff1 + GELU (output rounded: feeds ff2 mma)
        gemm_mma<1,1><<<dim3(FF_ / 128, TOK_ / 128), mblk, MM_SMEM>>>(
            px, pwb + WB_FF1 + (size_t)l * FF_ * D_, ff1b + l * FF_, pff, TOK_, FF_, D_);

        // ff2 (feeds LN: no rounding)
        gemm_mma<0,0><<<dim3(D_ / 128, TOK_ / 128), mblk, MM_SMEM>>>(
            pff, pwb + WB_FF2 + (size_t)l * D_ * FF_, ff2b + l * D_, ptmp, TOK_, D_, FF_);

        ln_kernel<<<TOK_, 128>>>(px, ptmp, ln2w + l * D_, ln2b + l * D_, px);
    }

    pool_kernel<<<B_, 512>>>(px, ppool);
    gemm_kernel<1><<<dim3(D_ / 128, 1), blk>>>(ppool, h1w, h1b, phead, B_, D_, 2 * D_);
    head2_kernel<<<B_, 128>>>(phead, h2w, h2b, out);
}

// round 7
// speedup vs baseline: 3.0322x; 1.0881x over previous
#include <cuda_runtime.h>
#include <cstdint>
#include <math.h>

#define B_   32
#define S_   512
#define IN_  64
#define D_   512
#define H_   8
#define L_   4
#define FF_  2048
#define TOK_ (B_ * S_)   // 16384

// ---------------- scratch (device globals; no allocation allowed) ----------------
__device__ __align__(16) float g_x[TOK_ * D_];
__device__ __align__(16) float g_qkv[TOK_ * 3 * D_];
__device__ __align__(16) float g_ctx[TOK_ * D_];
__device__ __align__(16) float g_tmp[TOK_ * D_];
__device__ __align__(16) float g_ff[TOK_ * FF_];
__device__ __align__(16) float g_pool[B_ * 2 * D_];
__device__ __align__(16) float g_head[B_ * D_];
// tf32-rounded weights: [in_proj | out_proj | ff1 | ff2]
#define WB_IN  0
#define WB_OUT (WB_IN  + L_ * 3 * D_ * D_)
#define WB_FF1 (WB_OUT + L_ * D_ * D_)
#define WB_FF2 (WB_FF1 + L_ * FF_ * D_)
#define WB_TOT (WB_FF2 + L_ * D_ * FF_)
__device__ __align__(16) float g_wbuf[WB_TOT];

__device__ __forceinline__ float gelu_exact(float v) {
    return 0.5f * v * (1.0f + erff(v * 0.7071067811865475f));
}
__device__ __forceinline__ float tf32r(float f) {
    uint32_t u;
    asm("cvt.rna.tf32.f32 %0, %1;" : "=r"(u) : "f"(f));
    return __uint_as_float(u);
}
// fast exp: poly 2^f, all fma/alu pipe (no MUFU, no libm). valid |x| < ~80.
__device__ __forceinline__ float fast_exp(float x) {
    float y = x * 1.442695041f;
    float z = y + 12582912.f;
    float k = z - 12582912.f;
    float f = y - k;
    float p = 1.3333558e-3f;
    p = fmaf(p, f, 9.6181291e-3f);
    p = fmaf(p, f, 5.5504109e-2f);
    p = fmaf(p, f, 2.4022651e-1f);
    p = fmaf(p, f, 6.9314718e-1f);
    p = fmaf(p, f, 1.0f);
    int ki = (__float_as_int(z) - 0x4B400000) << 23;
    return __int_as_float(__float_as_int(p) + ki);
}
__device__ __forceinline__ uint32_t smem_u32(const void* p) {
    uint32_t a;
    asm("{ .reg .u64 t; cvta.to.shared.u64 t, %1; cvt.u32.u64 %0, t; }" : "=r"(a) : "l"(p));
    return a;
}
__device__ __forceinline__ void mma_tf32(float* c, const uint32_t* a, const uint32_t* b) {
    asm volatile(
        "mma.sync.aligned.m16n8k8.row.col.f32.tf32.tf32.f32 "
        "{%0,%1,%2,%3}, {%4,%5,%6,%7}, {%8,%9}, {%0,%1,%2,%3};"
        : "+f"(c[0]), "+f"(c[1]), "+f"(c[2]), "+f"(c[3])
        : "r"(a[0]), "r"(a[1]), "r"(a[2]), "r"(a[3]), "r"(b[0]), "r"(b[1]));
}
#define FBITS(x) __float_as_uint(x)
// ldmatrix x4 on 32-bit data viewed as b16 pairs (bit-exact move)
#define LDSM_X4(r0, r1, r2, r3, addr) \
    asm volatile("ldmatrix.sync.aligned.m8n8.x4.shared.b16 {%0,%1,%2,%3}, [%4];" \
        : "=r"(r0), "=r"(r1), "=r"(r2), "=r"(r3) : "r"(addr))

// ---------------- tf32 rounding copy (weights, once per replay) ----------------
__global__ __launch_bounds__(256)
void round_copy(const float* __restrict__ src, float* __restrict__ dst, int n)
{
    const int i = (blockIdx.x * 256 + threadIdx.x) * 4;
    if (i < n) {
        float4 v = *(const float4*)(src + i);
        v.x = tf32r(v.x); v.y = tf32r(v.y); v.z = tf32r(v.z); v.w = tf32r(v.w);
        *(float4*)(dst + i) = v;
    }
}

// ======================= mma.sync tf32 GEMM =======================
// C[M,N] = act(A[M,K] * W[N,K]^T + bias). M%128==0, N%128==0, K%32==0, K>=96.
// 128x128x32 CTA tile, 128 threads = 4 warps in 2x2, each warp 64x64.
// 3-stage cp.async pipeline; fragment loads via ldmatrix.x4.
#define MM_RS     36
#define MM_TILEB  (128 * MM_RS * 4)      // 18432 B per operand
#define MM_STAGE  (2 * MM_TILEB)         // 36864 B per stage
#define MM_NST    3
#define MM_SMEM   (MM_NST * MM_STAGE)    // 110592 B

__device__ __forceinline__ void mm_cp_issue(
    const float* __restrict__ A, const float* __restrict__ W,
    uint32_t sbase, int stage, int m0, int n0, int K, int k0, int tid)
{
    const uint32_t as = sbase + stage * MM_STAGE;
    const uint32_t bs = as + MM_TILEB;
#pragma unroll
    for (int i = 0; i < 8; i++) {
        const int idx = i * 128 + tid;
        const int row = idx >> 3;
        const int q = idx & 7;
        const uint32_t so = (uint32_t)(row * (MM_RS * 4) + q * 16);
        const float* ga = A + (size_t)(m0 + row) * K + k0 + q * 4;
        const float* gw = W + (size_t)(n0 + row) * K + k0 + q * 4;
        asm volatile("cp.async.cg.shared.global [%0], [%1], 16;" :: "r"(as + so), "l"(ga));
        asm volatile("cp.async.cg.shared.global [%0], [%1], 16;" :: "r"(bs + so), "l"(gw));
    }
    asm volatile("cp.async.commit_group;" ::: "memory");
}

template <int ACT, int RND>   // ACT: 0=none,1=GELU ; RND: round output to tf32
__global__ __launch_bounds__(128, 2)
void gemm_mma(const float* __restrict__ A, const float* __restrict__ W,
              const float* __restrict__ bias, float* __restrict__ C,
              int M, int N, int K)
{
    extern __shared__ char smem[];
    const uint32_t sbase = smem_u32(smem);
    const int tid = threadIdx.x;
    const int lane = tid & 31, wid = tid >> 5;
    const int g = lane >> 2, t4 = lane & 3;
    const int wm = wid & 1;          // M half (64 rows)
    const int wn = wid >> 1;         // N half (64 cols)
    const int m0 = blockIdx.y * 128, n0 = blockIdx.x * 128;

    // ldmatrix lane-address offsets (floats):
    // A x4 per mt: mats = (rows0-7,k0-3),(rows8-15,k0-3),(rows0-7,k4-7),(rows8-15,k4-7)
    const uint32_t a_lane = (uint32_t)((wm * 64 + (lane & 7) + (lane & 8)) * MM_RS
                                       + ((lane & 16) >> 2));
    // B x4 per nt-pair p: mats = (nt=2p rows,k0-3),(2p,k4-7),(2p+1,k0-3),(2p+1,k4-7)
    const uint32_t b_lane = (uint32_t)((wn * 64 + ((lane & 16) >> 1) + (lane & 7)) * MM_RS
                                       + ((lane & 8) >> 1));

    float acc[4][8][4];
#pragma unroll
    for (int mt = 0; mt < 4; mt++)
#pragma unroll
        for (int nt = 0; nt < 8; nt++)
#pragma unroll
            for (int j = 0; j < 4; j++) acc[mt][nt][j] = 0.f;

    const int nch = K >> 5;          // assume nch >= 3
    mm_cp_issue(A, W, sbase, 0, m0, n0, K, 0, tid);
    mm_cp_issue(A, W, sbase, 1, m0, n0, K, 32, tid);
    mm_cp_issue(A, W, sbase, 2, m0, n0, K, 64, tid);

    int stage = 0;
    for (int c = 0; c < nch; c++) {
        const int rem = nch - 1 - c;
        if (rem >= 2)
            asm volatile("cp.async.wait_group 2;" ::: "memory");
        else if (rem == 1)
            asm volatile("cp.async.wait_group 1;" ::: "memory");
        else
            asm volatile("cp.async.wait_group 0;" ::: "memory");
        __syncthreads();

        const uint32_t a_base = sbase + stage * MM_STAGE + a_lane * 4;
        const uint32_t b_base = sbase + stage * MM_STAGE + MM_TILEB + b_lane * 4;

#pragma unroll
        for (int ks = 0; ks < 4; ks++) {
            uint32_t afr[4][4];
#pragma unroll
            for (int mt = 0; mt < 4; mt++)
                LDSM_X4(afr[mt][0], afr[mt][1], afr[mt][2], afr[mt][3],
                        a_base + (uint32_t)(mt * 16 * MM_RS + ks * 8) * 4);
            uint32_t bfr[8][2];
#pragma unroll
            for (int p = 0; p < 4; p++)
                LDSM_X4(bfr[2 * p][0], bfr[2 * p][1], bfr[2 * p + 1][0], bfr[2 * p + 1][1],
                        b_base + (uint32_t)(p * 16 * MM_RS + ks * 8) * 4);
#pragma unroll
            for (int mt = 0; mt < 4; mt++)
#pragma unroll
                for (int nt = 0; nt < 8; nt++)
                    mma_tf32(acc[mt][nt], afr[mt], bfr[nt]);
        }
        __syncthreads();
        if (c + 3 < nch)
            mm_cp_issue(A, W, sbase, stage, m0, n0, K, (c + 3) * 32, tid);
        stage = (stage == MM_NST - 1) ? 0 : stage + 1;
    }

#pragma unroll
    for (int mt = 0; mt < 4; mt++) {
        const int r0 = m0 + wm * 64 + mt * 16 + g;
#pragma unroll
        for (int nt = 0; nt < 8; nt++) {
            const int cb = n0 + wn * 64 + nt * 8 + 2 * t4;
            const float b0 = bias[cb], b1 = bias[cb + 1];
            float v0 = acc[mt][nt][0] + b0;
            float v1 = acc[mt][nt][1] + b1;
            float v2 = acc[mt][nt][2] + b0;
            float v3 = acc[mt][nt][3] + b1;
            if (ACT == 1) {
                v0 = gelu_exact(v0); v1 = gelu_exact(v1);
                v2 = gelu_exact(v2); v3 = gelu_exact(v3);
            }
            if (RND) {
                v0 = tf32r(v0); v1 = tf32r(v1); v2 = tf32r(v2); v3 = tf32r(v3);
            }
            *(float2*)&C[(size_t)r0 * N + cb]       = make_float2(v0, v1);
            *(float2*)&C[(size_t)(r0 + 8) * N + cb] = make_float2(v2, v3);
        }
    }
}

// ======================= fused attention =======================
// block = (q-tile of 32 rows) x (b*H + h). 256 threads (8 warps), 2 CTAs/SM.
#define FA_QS 68
#define FA_SS 516
#define FA_KS 68
#define FA_VS 72       // 72 % 32 == 8 -> PV B-fragment loads conflict-free
#define FA_SMEM_FLOATS (32 * FA_QS + 32 * FA_SS + 128 * FA_VS)
#define FA_SMEM_BYTES  (FA_SMEM_FLOATS * 4)     // 111616

__global__ __launch_bounds__(256, 2)
void fused_attn(const float* __restrict__ qkv, float* __restrict__ probs,
                float* __restrict__ ctx)
{
    extern __shared__ float sm[];
    float* qs = sm;                       // [32][68]
    float* sc = sm + 32 * FA_QS;          // [32][516]
    float* kv = sc + 32 * FA_SS;          // [128][68] (K) / [128][72] (V)

    const int tid = threadIdx.x;
    const int lane = tid & 31, wid = tid >> 5;
    const int g = lane >> 2, t4 = lane & 3;
    const int q0 = blockIdx.x * 32;
    const int bh = blockIdx.y;
    const int b = bh >> 3, h = bh & 7;
    const int wm = wid & 1;
    const int wn = wid >> 1;

    {
        const int r = tid >> 3;
        const int d0 = (tid & 7) * 8;
        const float* src = qkv + (size_t)(b * S_ + q0 + r) * 1536 + h * 64 + d0;
        const float4 v0 = *(const float4*)src;
        const float4 v1 = *(const float4*)(src + 4);
        float* dst = qs + r * FA_QS + d0;
        dst[0] = v0.x * 0.125f; dst[1] = v0.y * 0.125f;
        dst[2] = v0.z * 0.125f; dst[3] = v0.w * 0.125f;
        dst[4] = v1.x * 0.125f; dst[5] = v1.y * 0.125f;
        dst[6] = v1.z * 0.125f; dst[7] = v1.w * 0.125f;
    }

    for (int kt = 0; kt < 4; kt++) {
        __syncthreads();
#pragma unroll
        for (int i = 0; i < 4; i++) {
            const int idx = i * 256 + tid;
            const int r = idx >> 3;
            const int d0 = (idx & 7) * 8;
            const float* src = qkv + (size_t)(b * S_ + kt * 128 + r) * 1536 + D_ + h * 64 + d0;
            const float4 v0 = *(const float4*)src;
            const float4 v1 = *(const float4*)(src + 4);
            float* dst = kv + r * FA_KS + d0;
            dst[0] = v0.x; dst[1] = v0.y; dst[2] = v0.z; dst[3] = v0.w;
            dst[4] = v1.x; dst[5] = v1.y; dst[6] = v1.z; dst[7] = v1.w;
        }
        __syncthreads();

        float acc[4][4];
#pragma unroll
        for (int nt = 0; nt < 4; nt++)
#pragma unroll
            for (int j = 0; j < 4; j++) acc[nt][j] = 0.f;

#pragma unroll
        for (int ks = 0; ks < 8; ks++) {
            uint32_t afr[4];
            const float* ap = qs + (wm * 16 + g) * FA_QS + ks * 8 + t4;
            afr[0] = FBITS(ap[0]);
            afr[1] = FBITS(ap[8 * FA_QS]);
            afr[2] = FBITS(ap[4]);
            afr[3] = FBITS(ap[8 * FA_QS + 4]);
#pragma unroll
            for (int nt = 0; nt < 4; nt++) {
                const float* bp = kv + (wn * 32 + nt * 8 + g) * FA_KS + ks * 8 + t4;
                uint32_t bfr[2] = {FBITS(bp[0]), FBITS(bp[4])};
                mma_tf32(acc[nt], afr, bfr);
            }
        }
#pragma unroll
        for (int nt = 0; nt < 4; nt++) {
            const int col = kt * 128 + wn * 32 + nt * 8 + 2 * t4;
            const int row = wm * 16 + g;
            *(float2*)&sc[row * FA_SS + col]       = make_float2(acc[nt][0], acc[nt][1]);
            *(float2*)&sc[(row + 8) * FA_SS + col] = make_float2(acc[nt][2], acc[nt][3]);
        }
    }
    __syncthreads();

#pragma unroll
    for (int rr = 0; rr < 4; rr++) {
        const int row = wid * 4 + rr;
        float vals[16];
        float sum = 0.f;
#pragma unroll
        for (int t = 0; t < 4; t++) {
            const float4 v = *(const float4*)&sc[row * FA_SS + lane * 4 + t * 128];
            vals[t * 4 + 0] = fast_exp(v.x);
            vals[t * 4 + 1] = fast_exp(v.y);
            vals[t * 4 + 2] = fast_exp(v.z);
            vals[t * 4 + 3] = fast_exp(v.w);
            sum += vals[t * 4 + 0] + vals[t * 4 + 1] + vals[t * 4 + 2] + vals[t * 4 + 3];
        }
#pragma unroll
        for (int o = 16; o > 0; o >>= 1)
            sum += __shfl_xor_sync(0xFFFFFFFFu, sum, o);
        const float inv = 1.f / sum;
        float* prow = probs + ((size_t)bh * S_ + q0 + row) * S_;
#pragma unroll
        for (int t = 0; t < 4; t++) {
            float4 o;
            o.x = tf32r(vals[t * 4 + 0] * inv);
            o.y = tf32r(vals[t * 4 + 1] * inv);
            o.z = tf32r(vals[t * 4 + 2] * inv);
            o.w = tf32r(vals[t * 4 + 3] * inv);
            *(float4*)&sc[row * FA_SS + lane * 4 + t * 128] = o;
            *(float4*)&prow[lane * 4 + t * 128] = o;
        }
    }

    float pacc[2][4];
#pragma unroll
    for (int nt = 0; nt < 2; nt++)
#pragma unroll
        for (int j = 0; j < 4; j++) pacc[nt][j] = 0.f;

    for (int vt = 0; vt < 4; vt++) {
        __syncthreads();
#pragma unroll
        for (int i = 0; i < 8; i++) {
            const int idx = i * 256 + tid;
            const int r = idx >> 4;
            const int d0 = (idx & 15) * 4;
            const float4 v = *(const float4*)&qkv[(size_t)(b * S_ + vt * 128 + r) * 1536 + 2 * D_ + h * 64 + d0];
            float* dst = kv + r * FA_VS + d0;
            dst[0] = v.x; dst[1] = v.y; dst[2] = v.z; dst[3] = v.w;
        }
        __syncthreads();

#pragma unroll
        for (int ks = 0; ks < 16; ks++) {
            uint32_t afr[4];
            const float* ap = sc + (wm * 16 + g) * FA_SS + vt * 128 + ks * 8 + t4;
            afr[0] = FBITS(ap[0]);
            afr[1] = FBITS(ap[8 * FA_SS]);
            afr[2] = FBITS(ap[4]);
            afr[3] = FBITS(ap[8 * FA_SS + 4]);
#pragma unroll
            for (int nt = 0; nt < 2; nt++) {
                const float* bp = kv + (ks * 8 + t4) * FA_VS + wn * 16 + nt * 8 + g;
                uint32_t bfr[2] = {FBITS(bp[0]), FBITS(bp[4 * FA_VS])};
                mma_tf32(pacc[nt], afr, bfr);
            }
        }
    }

#pragma unroll
    for (int nt = 0; nt < 2; nt++) {
        const int row = b * S_ + q0 + wm * 16 + g;
        const int col = h * 64 + wn * 16 + nt * 8 + 2 * t4;
        *(float2*)&ctx[(size_t)row * D_ + col] =
            make_float2(tf32r(pacc[nt][0]), tf32r(pacc[nt][1]));
        *(float2*)&ctx[(size_t)(row + 8) * D_ + col] =
            make_float2(tf32r(pacc[nt][2]), tf32r(pacc[nt][3]));
    }
}

// ---------------- SIMT GEMM (input proj / head1) ----------------
template <int ACT>   // 0=none, 1=GELU, 2=add PE + tf32 round
__global__ __launch_bounds__(256)
void gemm_kernel(const float* __restrict__ A, const float* __restrict__ W,
                 const float* __restrict__ bias, float* __restrict__ C,
                 int M, int N, int K)
{
    __shared__ __align__(16) float As[8][128];
    __shared__ __align__(16) float Ws[8][128];

    const int tid = threadIdx.x;
    const int tx = tid & 15;
    const int ty = tid >> 4;
    const int m0 = blockIdx.y * 128;
    const int n0 = blockIdx.x * 128;

    float acc[2][2][4][4];
#pragma unroll
    for (int p = 0; p < 2; p++)
#pragma unroll
        for (int q = 0; q < 2; q++)
#pragma unroll
            for (int i = 0; i < 4; i++)
#pragma unroll
                for (int j = 0; j < 4; j++) acc[p][q][i][j] = 0.f;

    const int lr = tid >> 1;
    const int lk = (tid & 1) * 4;
    const float* Ag = A + (size_t)(m0 + lr) * K + lk;
    const float* Wg = W + (size_t)(n0 + lr) * K + lk;
    const bool aval = (m0 + lr) < M;

    for (int k0 = 0; k0 < K; k0 += 8) {
        float4 av = make_float4(0.f, 0.f, 0.f, 0.f);
        if (aval) av = *(const float4*)(Ag + k0);
        const float4 wv = *(const float4*)(Wg + k0);
        __syncthreads();
        As[lk + 0][lr] = av.x; As[lk + 1][lr] = av.y;
        As[lk + 2][lr] = av.z; As[lk + 3][lr] = av.w;
        Ws[lk + 0][lr] = wv.x; Ws[lk + 1][lr] = wv.y;
        Ws[lk + 2][lr] = wv.z; Ws[lk + 3][lr] = wv.w;
        __syncthreads();
#pragma unroll
        for (int kk = 0; kk < 8; kk++) {
            const float4 a0 = *(const float4*)&As[kk][ty * 4];
            const float4 a1 = *(const float4*)&As[kk][64 + ty * 4];
            const float4 b0 = *(const float4*)&Ws[kk][tx * 4];
            const float4 b1 = *(const float4*)&Ws[kk][64 + tx * 4];
            const float ar[2][4] = {{a0.x, a0.y, a0.z, a0.w}, {a1.x, a1.y, a1.z, a1.w}};
            const float br[2][4] = {{b0.x, b0.y, b0.z, b0.w}, {b1.x, b1.y, b1.z, b1.w}};
#pragma unroll
            for (int p = 0; p < 2; p++)
#pragma unroll
                for (int q = 0; q < 2; q++)
#pragma unroll
                    for (int i = 0; i < 4; i++)
#pragma unroll
                        for (int j = 0; j < 4; j++)
                            acc[p][q][i][j] += ar[p][i] * br[q][j];
        }
    }

#pragma unroll
    for (int p = 0; p < 2; p++) {
#pragma unroll
        for (int i = 0; i < 4; i++) {
            const int m = m0 + p * 64 + ty * 4 + i;
            if (m >= M) continue;
#pragma unroll
            for (int q = 0; q < 2; q++) {
                const int c = n0 + q * 64 + tx * 4;
                float4 o;
                float* po = &o.x;
#pragma unroll
                for (int j = 0; j < 4; j++) {
                    float v = acc[p][q][i][j] + bias[c + j];
                    if (ACT == 1) {
                        v = gelu_exact(v);
                    } else if (ACT == 2) {
                        const int d = c + j;
                        const int s = m & (S_ - 1);
                        const float freq = expf(-9.210340371976184f * (float)(d & ~1) / (float)D_);
                        const float ang = (float)s * freq;
                        v += (d & 1) ? cosf(ang) : sinf(ang);
                        v = tf32r(v);
                    }
                    po[j] = v;
                }
                *(float4*)&C[(size_t)m * N + c] = o;
            }
        }
    }
}

// ---------------- fused residual-add + LayerNorm (tf32-rounded output) ----------------
__global__ __launch_bounds__(128)
void ln_kernel(const float* __restrict__ x, const float* __restrict__ add,
               const float* __restrict__ w, const float* __restrict__ bvec,
               float* __restrict__ out)
{
    const int row = blockIdx.x;
    const int tid = threadIdx.x;
    const float* xr = x + (size_t)row * D_;
    const float* ar = add + (size_t)row * D_;
    float v[4];
    float s = 0.f;
#pragma unroll
    for (int i = 0; i < 4; i++) {
        const int c = tid + i * 128;
        v[i] = xr[c] + ar[c];
        s += v[i];
    }
    __shared__ float red[4];
#pragma unroll
    for (int o = 16; o > 0; o >>= 1) s += __shfl_xor_sync(0xFFFFFFFFu, s, o);
    if ((tid & 31) == 0) red[tid >> 5] = s;
    __syncthreads();
    const float mean = (red[0] + red[1] + red[2] + red[3]) * (1.f / 512.f);
    float vs = 0.f;
#pragma unroll
    for (int i = 0; i < 4; i++) {
        const float d = v[i] - mean;
        vs += d * d;
    }
    __syncthreads();
#pragma unroll
    for (int o = 16; o > 0; o >>= 1) vs += __shfl_xor_sync(0xFFFFFFFFu, vs, o);
    if ((tid & 31) == 0) red[tid >> 5] = vs;
    __syncthreads();
    const float rstd = rsqrtf((red[0] + red[1] + red[2] + red[3]) * (1.f / 512.f) + 1e-5f);
    float* orow = out + (size_t)row * D_;
#pragma unroll
    for (int i = 0; i < 4; i++) {
        const int c = tid + i * 128;
        orow[c] = tf32r((v[i] - mean) * rstd * w[c] + bvec[c]);
    }
}

// ---------------- mean+max pooling over sequence ----------------
__global__ __launch_bounds__(512)
void pool_kernel(const float* __restrict__ x, float* __restrict__ pool)
{
    const int b = blockIdx.x, d = threadIdx.x;
    float s = 0.f, m = -1e30f;
    for (int t = 0; t < S_; t++) {
        const float v = x[(size_t)(b * S_ + t) * D_ + d];
        s += v;
        m = fmaxf(m, v);
    }
    pool[b * (2 * D_) + d] = s * (1.f / 512.f);
    pool[b * (2 * D_) + D_ + d] = m;
}

// ---------------- final head ----------------
__global__ __launch_bounds__(128)
void head2_kernel(const float* __restrict__ h, const float* __restrict__ w,
                  const float* __restrict__ bb, float* __restrict__ out)
{
    const int b = blockIdx.x, tid = threadIdx.x;
    float s = 0.f;
    for (int c = tid; c < D_; c += 128) s += h[(size_t)b * D_ + c] * w[c];
    __shared__ float red[4];
#pragma unroll
    for (int o = 16; o > 0; o >>= 1) s += __shfl_xor_sync(0xFFFFFFFFu, s, o);
    if ((tid & 31) == 0) red[tid >> 5] = s;
    __syncthreads();
    if (tid == 0) out[b] = red[0] + red[1] + red[2] + red[3] + bb[0];
}

// ---------------- launch ----------------
extern "C" void kernel_launch(void* const* d_in, const int* in_sizes, int n_in,
                              void* d_out, int out_size)
{
    const float* x_in = (const float*)d_in[0];
    const float* w_in = (const float*)d_in[1];
    const float* b_in = (const float*)d_in[2];
    const float* inpw = (const float*)d_in[3];
    const float* inpb = (const float*)d_in[4];
    const float* outw = (const float*)d_in[5];
    const float* outb = (const float*)d_in[6];
    const float* ln1w = (const float*)d_in[7];
    const float* ln1b = (const float*)d_in[8];
    const float* ln2w = (const float*)d_in[9];
    const float* ln2b = (const float*)d_in[10];
    const float* ff1w = (const float*)d_in[11];
    const float* ff1b = (const float*)d_in[12];
    const float* ff2w = (const float*)d_in[13];
    const float* ff2b = (const float*)d_in[14];
    const float* h1w  = (const float*)d_in[15];
    const float* h1b  = (const float*)d_in[16];
    const float* h2w  = (const float*)d_in[17];
    const float* h2b  = (const float*)d_in[18];

    float* out  = (float*)d_out;
    float* attn = out + 32;   // [L,B,H,S,S] follows the [B,1] output

    float *px, *pqkv, *pctx, *ptmp, *pff, *ppool, *phead, *pwb;
    cudaGetSymbolAddress((void**)&px,    g_x);
    cudaGetSymbolAddress((void**)&pqkv,  g_qkv);
    cudaGetSymbolAddress((void**)&pctx,  g_ctx);
    cudaGetSymbolAddress((void**)&ptmp,  g_tmp);
    cudaGetSymbolAddress((void**)&pff,   g_ff);
    cudaGetSymbolAddress((void**)&ppool, g_pool);
    cudaGetSymbolAddress((void**)&phead, g_head);
    cudaGetSymbolAddress((void**)&pwb,   g_wbuf);

    cudaFuncSetAttribute(gemm_mma<0,1>, cudaFuncAttributeMaxDynamicSharedMemorySize, MM_SMEM);
    cudaFuncSetAttribute(gemm_mma<0,0>, cudaFuncAttributeMaxDynamicSharedMemorySize, MM_SMEM);
    cudaFuncSetAttribute(gemm_mma<1,1>, cudaFuncAttributeMaxDynamicSharedMemorySize, MM_SMEM);
    cudaFuncSetAttribute(fused_attn, cudaFuncAttributeMaxDynamicSharedMemorySize, FA_SMEM_BYTES);

    const dim3 blk(256);
    const dim3 mblk(128);

    // tf32-round all weights once per replay (~30us)
    {
        const int n_in_w  = L_ * 3 * D_ * D_;
        const int n_out_w = L_ * D_ * D_;
        const int n_ff1_w = L_ * FF_ * D_;
        const int n_ff2_w = L_ * D_ * FF_;
        round_copy<<<(n_in_w  + 1023) / 1024, 256>>>(inpw, pwb + WB_IN,  n_in_w);
        round_copy<<<(n_out_w + 1023) / 1024, 256>>>(outw, pwb + WB_OUT, n_out_w);
        round_copy<<<(n_ff1_w + 1023) / 1024, 256>>>(ff1w, pwb + WB_FF1, n_ff1_w);
        round_copy<<<(n_ff2_w + 1023) / 1024, 256>>>(ff2w, pwb + WB_FF2, n_ff2_w);
    }

    // input projection + PE (SIMT, output tf32-rounded)
    gemm_kernel<2><<<dim3(D_ / 128, TOK_ / 128), blk>>>(x_in, w_in, b_in, px, TOK_, D_, IN_);

    for (int l = 0; l < L_; l++) {
        // QKV projection (output rounded: feeds attention mma)
        gemm_mma<0,1><<<dim3((3 * D_) / 128, TOK_ / 128), mblk, MM_SMEM>>>(
            px, pwb + WB_IN + (size_t)l * 3 * D_ * D_, inpb + l * 3 * D_, pqkv, TOK_, 3 * D_, D_);

        float* attn_l = attn + (size_t)l * B_ * H_ * S_ * S_;

        // fused scores + softmax + probs-out + P@V
        fused_attn<<<dim3(S_ / 32, B_ * H_), blk, FA_SMEM_BYTES>>>(pqkv, attn_l, pctx);

        // output projection (feeds LN: no rounding)
        gemm_mma<0,0><<<dim3(D_ / 128, TOK_ / 128), mblk, MM_SMEM>>>(
            pctx, pwb + WB_OUT + (size_t)l * D_ * D_, outb + l * D_, ptmp, TOK_, D_, D_);

        ln_kernel<<<TOK_, 128>>>(px, ptmp, ln1w + l * D_, ln1b + l * D_, px);

        // ff1 + GELU (output rounded: feeds ff2 mma)
        gemm_mma<1,1><<<dim3(FF_ / 128, TOK_ / 128), mblk, MM_SMEM>>>(
            px, pwb + WB_FF1 + (size_t)l * FF_ * D_, ff1b + l * FF_, pff, TOK_, FF_, D_);

        // ff2 (feeds LN: no rounding)
        gemm_mma<0,0><<<dim3(D_ / 128, TOK_ / 128), mblk, MM_SMEM>>>(
            pff, pwb + WB_FF2 + (size_t)l * D_ * FF_, ff2b + l * D_, ptmp, TOK_, D_, FF_);

        ln_kernel<<<TOK_, 128>>>(px, ptmp, ln2w + l * D_, ln2b + l * D_, px);
    }

    pool_kernel<<<B_, 512>>>(px, ppool);
    gemm_kernel<1><<<dim3(D_ / 128, 1), blk>>>(ppool, h1w, h1b, phead, B_, D_, 2 * D_);
    head2_kernel<<<B_, 128>>>(phead, h2w, h2b, out);
}

// round 9
// speedup vs baseline: 3.0844x; 1.0172x over previous
#include <cuda_runtime.h>
#include <cstdint>
#include <math.h>

#define B_   32
#define S_   512
#define IN_  64
#define D_   512
#define H_   8
#define L_   4
#define FF_  2048
#define TOK_ (B_ * S_)   // 16384

// ---------------- scratch (device globals; no allocation allowed) ----------------
__device__ __align__(16) float g_x[TOK_ * D_];
__device__ __align__(16) float g_qkv[TOK_ * 3 * D_];
__device__ __align__(16) float g_ctx[TOK_ * D_];
__device__ __align__(16) float g_tmp[TOK_ * D_];
__device__ __align__(16) float g_ff[TOK_ * FF_];
__device__ __align__(16) float g_pool[B_ * 2 * D_];
__device__ __align__(16) float g_head[B_ * D_];
__device__ __align__(16) float g_pe[S_ * D_];     // positional encoding table
// tf32-rounded weights: [in_proj | out_proj | ff1 | ff2]
#define WB_IN  0
#define WB_OUT (WB_IN  + L_ * 3 * D_ * D_)
#define WB_FF1 (WB_OUT + L_ * D_ * D_)
#define WB_FF2 (WB_FF1 + L_ * FF_ * D_)
#define WB_TOT (WB_FF2 + L_ * D_ * FF_)
__device__ __align__(16) float g_wbuf[WB_TOT];

__device__ __forceinline__ float gelu_exact(float v) {
    return 0.5f * v * (1.0f + erff(v * 0.7071067811865475f));
}
__device__ __forceinline__ float tf32r(float f) {
    uint32_t u;
    asm("cvt.rna.tf32.f32 %0, %1;" : "=r"(u) : "f"(f));
    return __uint_as_float(u);
}
// fast exp: poly 2^f, all fma/alu pipe (no MUFU, no libm). valid |x| < ~80.
__device__ __forceinline__ float fast_exp(float x) {
    float y = x * 1.442695041f;
    float z = y + 12582912.f;
    float k = z - 12582912.f;
    float f = y - k;
    float p = 1.3333558e-3f;
    p = fmaf(p, f, 9.6181291e-3f);
    p = fmaf(p, f, 5.5504109e-2f);
    p = fmaf(p, f, 2.4022651e-1f);
    p = fmaf(p, f, 6.9314718e-1f);
    p = fmaf(p, f, 1.0f);
    int ki = (__float_as_int(z) - 0x4B400000) << 23;
    return __int_as_float(__float_as_int(p) + ki);
}
__device__ __forceinline__ uint32_t smem_u32(const void* p) {
    uint32_t a;
    asm("{ .reg .u64 t; cvta.to.shared.u64 t, %1; cvt.u32.u64 %0, t; }" : "=r"(a) : "l"(p));
    return a;
}
__device__ __forceinline__ void mma_tf32(float* c, const uint32_t* a, const uint32_t* b) {
    asm volatile(
        "mma.sync.aligned.m16n8k8.row.col.f32.tf32.tf32.f32 "
        "{%0,%1,%2,%3}, {%4,%5,%6,%7}, {%8,%9}, {%0,%1,%2,%3};"
        : "+f"(c[0]), "+f"(c[1]), "+f"(c[2]), "+f"(c[3])
        : "r"(a[0]), "r"(a[1]), "r"(a[2]), "r"(a[3]), "r"(b[0]), "r"(b[1]));
}
#define FBITS(x) __float_as_uint(x)
// ldmatrix x4 on 32-bit data viewed as b16 pairs (bit-exact move)
#define LDSM_X4(r0, r1, r2, r3, addr) \
    asm volatile("ldmatrix.sync.aligned.m8n8.x4.shared.b16 {%0,%1,%2,%3}, [%4];" \
        : "=r"(r0), "=r"(r1), "=r"(r2), "=r"(r3) : "r"(addr))

// ---------------- tf32 rounding copy (weights, once per replay) ----------------
__global__ __launch_bounds__(256)
void round_copy(const float* __restrict__ src, float* __restrict__ dst, int n)
{
    const int i = (blockIdx.x * 256 + threadIdx.x) * 4;
    if (i < n) {
        float4 v = *(const float4*)(src + i);
        v.x = tf32r(v.x); v.y = tf32r(v.y); v.z = tf32r(v.z); v.w = tf32r(v.w);
        *(float4*)(dst + i) = v;
    }
}

// ---------------- positional encoding table (once per replay) ----------------
__global__ __launch_bounds__(256)
void pe_init(float* __restrict__ pe)
{
    const int i = blockIdx.x * 256 + threadIdx.x;   // grid covers S_*D_
    const int s = i >> 9;            // / D_
    const int d = i & (D_ - 1);
    const float freq = expf(-9.210340371976184f * (float)(d & ~1) / (float)D_);
    const float ang = (float)s * freq;
    pe[i] = (d & 1) ? cosf(ang) : sinf(ang);
}

// ======================= mma.sync tf32 GEMM =======================
// C[M,N] = act(A[M,K] * W[N,K]^T + bias). M%128==0, N%128==0, K%32==0, K>=96.
// 128x128x32 CTA tile, 128 threads = 4 warps in 2x2, each warp 64x64.
// 3-stage cp.async pipeline; fragment loads via ldmatrix.x4.
#define MM_RS     36
#define MM_TILEB  (128 * MM_RS * 4)      // 18432 B per operand
#define MM_STAGE  (2 * MM_TILEB)         // 36864 B per stage
#define MM_NST    3
#define MM_SMEM   (MM_NST * MM_STAGE)    // 110592 B

__device__ __forceinline__ void mm_cp_issue(
    const float* __restrict__ A, const float* __restrict__ W,
    uint32_t sbase, int stage, int m0, int n0, int K, int k0, int tid)
{
    const uint32_t as = sbase + stage * MM_STAGE;
    const uint32_t bs = as + MM_TILEB;
#pragma unroll
    for (int i = 0; i < 8; i++) {
        const int idx = i * 128 + tid;
        const int row = idx >> 3;
        const int q = idx & 7;
        const uint32_t so = (uint32_t)(row * (MM_RS * 4) + q * 16);
        const float* ga = A + (size_t)(m0 + row) * K + k0 + q * 4;
        const float* gw = W + (size_t)(n0 + row) * K + k0 + q * 4;
        asm volatile("cp.async.cg.shared.global [%0], [%1], 16;" :: "r"(as + so), "l"(ga));
        asm volatile("cp.async.cg.shared.global [%0], [%1], 16;" :: "r"(bs + so), "l"(gw));
    }
    asm volatile("cp.async.commit_group;" ::: "memory");
}

template <int ACT, int RND>   // ACT: 0=none,1=GELU ; RND: round output to tf32
__global__ __launch_bounds__(128, 2)
void gemm_mma(const float* __restrict__ A, const float* __restrict__ W,
              const float* __restrict__ bias, float* __restrict__ C,
              int M, int N, int K)
{
    extern __shared__ char smem[];
    const uint32_t sbase = smem_u32(smem);
    const int tid = threadIdx.x;
    const int lane = tid & 31, wid = tid >> 5;
    const int g = lane >> 2, t4 = lane & 3;
    const int wm = wid & 1;          // M half (64 rows)
    const int wn = wid >> 1;         // N half (64 cols)
    const int m0 = blockIdx.y * 128, n0 = blockIdx.x * 128;

    const uint32_t a_lane = (uint32_t)((wm * 64 + (lane & 7) + (lane & 8)) * MM_RS
                                       + ((lane & 16) >> 2));
    const uint32_t b_lane = (uint32_t)((wn * 64 + ((lane & 16) >> 1) + (lane & 7)) * MM_RS
                                       + ((lane & 8) >> 1));

    float acc[4][8][4];
#pragma unroll
    for (int mt = 0; mt < 4; mt++)
#pragma unroll
        for (int nt = 0; nt < 8; nt++)
#pragma unroll
            for (int j = 0; j < 4; j++) acc[mt][nt][j] = 0.f;

    const int nch = K >> 5;          // assume nch >= 3
    mm_cp_issue(A, W, sbase, 0, m0, n0, K, 0, tid);
    mm_cp_issue(A, W, sbase, 1, m0, n0, K, 32, tid);
    mm_cp_issue(A, W, sbase, 2, m0, n0, K, 64, tid);

    int stage = 0;
    for (int c = 0; c < nch; c++) {
        const int rem = nch - 1 - c;
        if (rem >= 2)
            asm volatile("cp.async.wait_group 2;" ::: "memory");
        else if (rem == 1)
            asm volatile("cp.async.wait_group 1;" ::: "memory");
        else
            asm volatile("cp.async.wait_group 0;" ::: "memory");
        __syncthreads();

        const uint32_t a_base = sbase + stage * MM_STAGE + a_lane * 4;
        const uint32_t b_base = sbase + stage * MM_STAGE + MM_TILEB + b_lane * 4;

#pragma unroll
        for (int ks = 0; ks < 4; ks++) {
            uint32_t afr[4][4];
#pragma unroll
            for (int mt = 0; mt < 4; mt++)
                LDSM_X4(afr[mt][0], afr[mt][1], afr[mt][2], afr[mt][3],
                        a_base + (uint32_t)(mt * 16 * MM_RS + ks * 8) * 4);
            uint32_t bfr[8][2];
#pragma unroll
            for (int p = 0; p < 4; p++)
                LDSM_X4(bfr[2 * p][0], bfr[2 * p][1], bfr[2 * p + 1][0], bfr[2 * p + 1][1],
                        b_base + (uint32_t)(p * 16 * MM_RS + ks * 8) * 4);
#pragma unroll
            for (int mt = 0; mt < 4; mt++)
#pragma unroll
                for (int nt = 0; nt < 8; nt++)
                    mma_tf32(acc[mt][nt], afr[mt], bfr[nt]);
        }
        __syncthreads();
        if (c + 3 < nch)
            mm_cp_issue(A, W, sbase, stage, m0, n0, K, (c + 3) * 32, tid);
        stage = (stage == MM_NST - 1) ? 0 : stage + 1;
    }

#pragma unroll
    for (int mt = 0; mt < 4; mt++) {
        const int r0 = m0 + wm * 64 + mt * 16 + g;
#pragma unroll
        for (int nt = 0; nt < 8; nt++) {
            const int cb = n0 + wn * 64 + nt * 8 + 2 * t4;
            const float b0 = bias[cb], b1 = bias[cb + 1];
            float v0 = acc[mt][nt][0] + b0;
            float v1 = acc[mt][nt][1] + b1;
            float v2 = acc[mt][nt][2] + b0;
            float v3 = acc[mt][nt][3] + b1;
            if (ACT == 1) {
                v0 = gelu_exact(v0); v1 = gelu_exact(v1);
                v2 = gelu_exact(v2); v3 = gelu_exact(v3);
            }
            if (RND) {
                v0 = tf32r(v0); v1 = tf32r(v1); v2 = tf32r(v2); v3 = tf32r(v3);
            }
            *(float2*)&C[(size_t)r0 * N + cb]       = make_float2(v0, v1);
            *(float2*)&C[(size_t)(r0 + 8) * N + cb] = make_float2(v2, v3);
        }
    }
}

// ======================= fused attention =======================
// block = (q-tile of 32 rows) x (b*H + h). 256 threads (8 warps), 2 CTAs/SM.
#define FA_QS 68
#define FA_SS 516
#define FA_KS 68
#define FA_VS 72       // 72 % 32 == 8 -> PV B-fragment loads conflict-free
#define FA_SMEM_FLOATS (32 * FA_QS + 32 * FA_SS + 128 * FA_VS)
#define FA_SMEM_BYTES  (FA_SMEM_FLOATS * 4)     // 111616

__global__ __launch_bounds__(256, 2)
void fused_attn(const float* __restrict__ qkv, float* __restrict__ probs,
                float* __restrict__ ctx)
{
    extern __shared__ float sm[];
    float* qs = sm;                       // [32][68]
    float* sc = sm + 32 * FA_QS;          // [32][516]
    float* kv = sc + 32 * FA_SS;          // [128][68] (K) / [128][72] (V)
    const uint32_t sbase = smem_u32(sm);

    const int tid = threadIdx.x;
    const int lane = tid & 31, wid = tid >> 5;
    const int g = lane >> 2, t4 = lane & 3;
    const int q0 = blockIdx.x * 32;
    const int bh = blockIdx.y;
    const int b = bh >> 3, h = bh & 7;
    const int wm = wid & 1;
    const int wn = wid >> 1;

    // ldmatrix lane addresses (element offsets; stride ≡ 16B mod 128B -> conflict-free)
    const uint32_t qa_addr = sbase +
        (uint32_t)((wm * 16 + (lane & 7) + (lane & 8)) * FA_QS + ((lane & 16) >> 2)) * 4;
    const uint32_t kb_addr = sbase + (uint32_t)(32 * FA_QS + 32 * FA_SS) * 4 +
        (uint32_t)((wn * 32 + ((lane & 16) >> 1) + (lane & 7)) * FA_KS + ((lane & 8) >> 1)) * 4;
    const uint32_t pa_addr = sbase + (uint32_t)(32 * FA_QS) * 4 +
        (uint32_t)((wm * 16 + (lane & 7) + (lane & 8)) * FA_SS + ((lane & 16) >> 2)) * 4;

    {
        const int r = tid >> 3;
        const int d0 = (tid & 7) * 8;
        const float* src = qkv + (size_t)(b * S_ + q0 + r) * 1536 + h * 64 + d0;
        const float4 v0 = *(const float4*)src;
        const float4 v1 = *(const float4*)(src + 4);
        float* dst = qs + r * FA_QS + d0;
        dst[0] = v0.x * 0.125f; dst[1] = v0.y * 0.125f;
        dst[2] = v0.z * 0.125f; dst[3] = v0.w * 0.125f;
        dst[4] = v1.x * 0.125f; dst[5] = v1.y * 0.125f;
        dst[6] = v1.z * 0.125f; dst[7] = v1.w * 0.125f;
    }

    for (int kt = 0; kt < 4; kt++) {
        __syncthreads();
#pragma unroll
        for (int i = 0; i < 4; i++) {
            const int idx = i * 256 + tid;
            const int r = idx >> 3;
            const int d0 = (idx & 7) * 8;
            const float* src = qkv + (size_t)(b * S_ + kt * 128 + r) * 1536 + D_ + h * 64 + d0;
            const float4 v0 = *(const float4*)src;
            const float4 v1 = *(const float4*)(src + 4);
            float* dst = kv + r * FA_KS + d0;
            dst[0] = v0.x; dst[1] = v0.y; dst[2] = v0.z; dst[3] = v0.w;
            dst[4] = v1.x; dst[5] = v1.y; dst[6] = v1.z; dst[7] = v1.w;
        }
        __syncthreads();

        float acc[4][4];
#pragma unroll
        for (int nt = 0; nt < 4; nt++)
#pragma unroll
            for (int j = 0; j < 4; j++) acc[nt][j] = 0.f;

#pragma unroll
        for (int ks = 0; ks < 8; ks++) {
            uint32_t afr[4];
            LDSM_X4(afr[0], afr[1], afr[2], afr[3], qa_addr + (uint32_t)(ks * 8) * 4);
            uint32_t bfr[4][2];
#pragma unroll
            for (int p = 0; p < 2; p++)
                LDSM_X4(bfr[2 * p][0], bfr[2 * p][1], bfr[2 * p + 1][0], bfr[2 * p + 1][1],
                        kb_addr + (uint32_t)(p * 16 * FA_KS + ks * 8) * 4);
#pragma unroll
            for (int nt = 0; nt < 4; nt++)
                mma_tf32(acc[nt], afr, bfr[nt]);
        }
#pragma unroll
        for (int nt = 0; nt < 4; nt++) {
            const int col = kt * 128 + wn * 32 + nt * 8 + 2 * t4;
            const int row = wm * 16 + g;
            *(float2*)&sc[row * FA_SS + col]       = make_float2(acc[nt][0], acc[nt][1]);
            *(float2*)&sc[(row + 8) * FA_SS + col] = make_float2(acc[nt][2], acc[nt][3]);
        }
    }
    __syncthreads();

#pragma unroll
    for (int rr = 0; rr < 4; rr++) {
        const int row = wid * 4 + rr;
        float vals[16];
        float sum = 0.f;
#pragma unroll
        for (int t = 0; t < 4; t++) {
            const float4 v = *(const float4*)&sc[row * FA_SS + lane * 4 + t * 128];
            vals[t * 4 + 0] = fast_exp(v.x);
            vals[t * 4 + 1] = fast_exp(v.y);
            vals[t * 4 + 2] = fast_exp(v.z);
            vals[t * 4 + 3] = fast_exp(v.w);
            sum += vals[t * 4 + 0] + vals[t * 4 + 1] + vals[t * 4 + 2] + vals[t * 4 + 3];
        }
#pragma unroll
        for (int o = 16; o > 0; o >>= 1)
            sum += __shfl_xor_sync(0xFFFFFFFFu, sum, o);
        const float inv = 1.f / sum;
        float* prow = probs + ((size_t)bh * S_ + q0 + row) * S_;
#pragma unroll
        for (int t = 0; t < 4; t++) {
            float4 o;
            o.x = tf32r(vals[t * 4 + 0] * inv);
            o.y = tf32r(vals[t * 4 + 1] * inv);
            o.z = tf32r(vals[t * 4 + 2] * inv);
            o.w = tf32r(vals[t * 4 + 3] * inv);
            *(float4*)&sc[row * FA_SS + lane * 4 + t * 128] = o;
            *(float4*)&prow[lane * 4 + t * 128] = o;
        }
    }

    float pacc[2][4];
#pragma unroll
    for (int nt = 0; nt < 2; nt++)
#pragma unroll
        for (int j = 0; j < 4; j++) pacc[nt][j] = 0.f;

    for (int vt = 0; vt < 4; vt++) {
        __syncthreads();
#pragma unroll
        for (int i = 0; i < 8; i++) {
            const int idx = i * 256 + tid;
            const int r = idx >> 4;
            const int d0 = (idx & 15) * 4;
            const float4 v = *(const float4*)&qkv[(size_t)(b * S_ + vt * 128 + r) * 1536 + 2 * D_ + h * 64 + d0];
            float* dst = kv + r * FA_VS + d0;
            dst[0] = v.x; dst[1] = v.y; dst[2] = v.z; dst[3] = v.w;
        }
        __syncthreads();

#pragma unroll
        for (int ks = 0; ks < 16; ks++) {
            uint32_t afr[4];
            LDSM_X4(afr[0], afr[1], afr[2], afr[3],
                    pa_addr + (uint32_t)(vt * 128 + ks * 8) * 4);
#pragma unroll
            for (int nt = 0; nt < 2; nt++) {
                const float* bp = kv + (ks * 8 + t4) * FA_VS + wn * 16 + nt * 8 + g;
                uint32_t bfr[2] = {FBITS(bp[0]), FBITS(bp[4 * FA_VS])};
                mma_tf32(pacc[nt], afr, bfr);
            }
        }
    }

#pragma unroll
    for (int nt = 0; nt < 2; nt++) {
        const int row = b * S_ + q0 + wm * 16 + g;
        const int col = h * 64 + wn * 16 + nt * 8 + 2 * t4;
        *(float2*)&ctx[(size_t)row * D_ + col] =
            make_float2(tf32r(pacc[nt][0]), tf32r(pacc[nt][1]));
        *(float2*)&ctx[(size_t)(row + 8) * D_ + col] =
            make_float2(tf32r(pacc[nt][2]), tf32r(pacc[nt][3]));
    }
}

// ---------------- SIMT GEMM (input proj / head1) ----------------
template <int ACT>   // 0=none, 1=GELU, 2=add PE table + tf32 round
__global__ __launch_bounds__(256)
void gemm_kernel(const float* __restrict__ A, const float* __restrict__ W,
                 const float* __restrict__ bias, float* __restrict__ C,
                 int M, int N, int K, const float* __restrict__ pe)
{
    __shared__ __align__(16) float As[8][128];
    __shared__ __align__(16) float Ws[8][128];

    const int tid = threadIdx.x;
    const int tx = tid & 15;
    const int ty = tid >> 4;
    const int m0 = blockIdx.y * 128;
    const int n0 = blockIdx.x * 128;

    float acc[2][2][4][4];
#pragma unroll
    for (int p = 0; p < 2; p++)
#pragma unroll
        for (int q = 0; q < 2; q++)
#pragma unroll
            for (int i = 0; i < 4; i++)
#pragma unroll
                for (int j = 0; j < 4; j++) acc[p][q][i][j] = 0.f;

    const int lr = tid >> 1;
    const int lk = (tid & 1) * 4;
    const float* Ag = A + (size_t)(m0 + lr) * K + lk;
    const float* Wg = W + (size_t)(n0 + lr) * K + lk;
    const bool aval = (m0 + lr) < M;

    for (int k0 = 0; k0 < K; k0 += 8) {
        float4 av = make_float4(0.f, 0.f, 0.f, 0.f);
        if (aval) av = *(const float4*)(Ag + k0);
        const float4 wv = *(const float4*)(Wg + k0);
        __syncthreads();
        As[lk + 0][lr] = av.x; As[lk + 1][lr] = av.y;
        As[lk + 2][lr] = av.z; As[lk + 3][lr] = av.w;
        Ws[lk + 0][lr] = wv.x; Ws[lk + 1][lr] = wv.y;
        Ws[lk + 2][lr] = wv.z; Ws[lk + 3][lr] = wv.w;
        __syncthreads();
#pragma unroll
        for (int kk = 0; kk < 8; kk++) {
            const float4 a0 = *(const float4*)&As[kk][ty * 4];
            const float4 a1 = *(const float4*)&As[kk][64 + ty * 4];
            const float4 b0 = *(const float4*)&Ws[kk][tx * 4];
            const float4 b1 = *(const float4*)&Ws[kk][64 + tx * 4];
            const float ar[2][4] = {{a0.x, a0.y, a0.z, a0.w}, {a1.x, a1.y, a1.z, a1.w}};
            const float br[2][4] = {{b0.x, b0.y, b0.z, b0.w}, {b1.x, b1.y, b1.z, b1.w}};
#pragma unroll
            for (int p = 0; p < 2; p++)
#pragma unroll
                for (int q = 0; q < 2; q++)
#pragma unroll
                    for (int i = 0; i < 4; i++)
#pragma unroll
                        for (int j = 0; j < 4; j++)
                            acc[p][q][i][j] += ar[p][i] * br[q][j];
        }
    }

#pragma unroll
    for (int p = 0; p < 2; p++) {
#pragma unroll
        for (int i = 0; i < 4; i++) {
            const int m = m0 + p * 64 + ty * 4 + i;
            if (m >= M) continue;
#pragma unroll
            for (int q = 0; q < 2; q++) {
                const int c = n0 + q * 64 + tx * 4;
                float4 o;
                float* po = &o.x;
#pragma unroll
                for (int j = 0; j < 4; j++) {
                    float v = acc[p][q][i][j] + bias[c + j];
                    if (ACT == 1) {
                        v = gelu_exact(v);
                    } else if (ACT == 2) {
                        v += pe[(m & (S_ - 1)) * D_ + c + j];
                        v = tf32r(v);
                    }
                    po[j] = v;
                }
                *(float4*)&C[(size_t)m * N + c] = o;
            }
        }
    }
}

// ---------------- fused residual-add + LayerNorm (tf32-rounded output) ----------------
__global__ __launch_bounds__(128)
void ln_kernel(const float* __restrict__ x, const float* __restrict__ add,
               const float* __restrict__ w, const float* __restrict__ bvec,
               float* __restrict__ out)
{
    const int row = blockIdx.x;
    const int tid = threadIdx.x;
    const float* xr = x + (size_t)row * D_;
    const float* ar = add + (size_t)row * D_;
    float v[4];
    float s = 0.f;
#pragma unroll
    for (int i = 0; i < 4; i++) {
        const int c = tid + i * 128;
        v[i] = xr[c] + ar[c];
        s += v[i];
    }
    __shared__ float red[4];
#pragma unroll
    for (int o = 16; o > 0; o >>= 1) s += __shfl_xor_sync(0xFFFFFFFFu, s, o);
    if ((tid & 31) == 0) red[tid >> 5] = s;
    __syncthreads();
    const float mean = (red[0] + red[1] + red[2] + red[3]) * (1.f / 512.f);
    float vs = 0.f;
#pragma unroll
    for (int i = 0; i < 4; i++) {
        const float d = v[i] - mean;
        vs += d * d;
    }
    __syncthreads();
#pragma unroll
    for (int o = 16; o > 0; o >>= 1) vs += __shfl_xor_sync(0xFFFFFFFFu, vs, o);
    if ((tid & 31) == 0) red[tid >> 5] = vs;
    __syncthreads();
    const float rstd = rsqrtf((red[0] + red[1] + red[2] + red[3]) * (1.f / 512.f) + 1e-5f);
    float* orow = out + (size_t)row * D_;
#pragma unroll
    for (int i = 0; i < 4; i++) {
        const int c = tid + i * 128;
        orow[c] = tf32r((v[i] - mean) * rstd * w[c] + bvec[c]);
    }
}

// ---------------- mean+max pooling over sequence ----------------
__global__ __launch_bounds__(512)
void pool_kernel(const float* __restrict__ x, float* __restrict__ pool)
{
    const int b = blockIdx.x, d = threadIdx.x;
    float s = 0.f, m = -1e30f;
    for (int t = 0; t < S_; t++) {
        const float v = x[(size_t)(b * S_ + t) * D_ + d];
        s += v;
        m = fmaxf(m, v);
    }
    pool[b * (2 * D_) + d] = s * (1.f / 512.f);
    pool[b * (2 * D_) + D_ + d] = m;
}

// ---------------- final head ----------------
__global__ __launch_bounds__(128)
void head2_kernel(const float* __restrict__ h, const float* __restrict__ w,
                  const float* __restrict__ bb, float* __restrict__ out)
{
    const int b = blockIdx.x, tid = threadIdx.x;
    float s = 0.f;
    for (int c = tid; c < D_; c += 128) s += h[(size_t)b * D_ + c] * w[c];
    __shared__ float red[4];
#pragma unroll
    for (int o = 16; o > 0; o >>= 1) s += __shfl_xor_sync(0xFFFFFFFFu, s, o);
    if ((tid & 31) == 0) red[tid >> 5] = s;
    __syncthreads();
    if (tid == 0) out[b] = red[0] + red[1] + red[2] + red[3] + bb[0];
}

// ---------------- launch ----------------
extern "C" void kernel_launch(void* const* d_in, const int* in_sizes, int n_in,
                              void* d_out, int out_size)
{
    const float* x_in = (const float*)d_in[0];
    const float* w_in = (const float*)d_in[1];
    const float* b_in = (const float*)d_in[2];
    const float* inpw = (const float*)d_in[3];
    const float* inpb = (const float*)d_in[4];
    const float* outw = (const float*)d_in[5];
    const float* outb = (const float*)d_in[6];
    const float* ln1w = (const float*)d_in[7];
    const float* ln1b = (const float*)d_in[8];
    const float* ln2w = (const float*)d_in[9];
    const float* ln2b = (const float*)d_in[10];
    const float* ff1w = (const float*)d_in[11];
    const float* ff1b = (const float*)d_in[12];
    const float* ff2w = (const float*)d_in[13];
    const float* ff2b = (const float*)d_in[14];
    const float* h1w  = (const float*)d_in[15];
    const float* h1b  = (const float*)d_in[16];
    const float* h2w  = (const float*)d_in[17];
    const float* h2b  = (const float*)d_in[18];

    float* out  = (float*)d_out;
    float* attn = out + 32;   // [L,B,H,S,S] follows the [B,1] output

    float *px, *pqkv, *pctx, *ptmp, *pff, *ppool, *phead, *pwb, *ppe;
    cudaGetSymbolAddress((void**)&px,    g_x);
    cudaGetSymbolAddress((void**)&pqkv,  g_qkv);
    cudaGetSymbolAddress((void**)&pctx,  g_ctx);
    cudaGetSymbolAddress((void**)&ptmp,  g_tmp);
    cudaGetSymbolAddress((void**)&pff,   g_ff);
    cudaGetSymbolAddress((void**)&ppool, g_pool);
    cudaGetSymbolAddress((void**)&phead, g_head);
    cudaGetSymbolAddress((void**)&pwb,   g_wbuf);
    cudaGetSymbolAddress((void**)&ppe,   g_pe);

    cudaFuncSetAttribute(gemm_mma<0,1>, cudaFuncAttributeMaxDynamicSharedMemorySize, MM_SMEM);
    cudaFuncSetAttribute(gemm_mma<0,0>, cudaFuncAttributeMaxDynamicSharedMemorySize, MM_SMEM);
    cudaFuncSetAttribute(gemm_mma<1,1>, cudaFuncAttributeMaxDynamicSharedMemorySize, MM_SMEM);
    cudaFuncSetAttribute(fused_attn, cudaFuncAttributeMaxDynamicSharedMemorySize, FA_SMEM_BYTES);

    const dim3 blk(256);
    const dim3 mblk(128);

    // per-replay setup: tf32-round weights + PE table (~40us)
    {
        const int n_in_w  = L_ * 3 * D_ * D_;
        const int n_out_w = L_ * D_ * D_;
        const int n_ff1_w = L_ * FF_ * D_;
        const int n_ff2_w = L_ * D_ * FF_;
        round_copy<<<(n_in_w  + 1023) / 1024, 256>>>(inpw, pwb + WB_IN,  n_in_w);
        round_copy<<<(n_out_w + 1023) / 1024, 256>>>(outw, pwb + WB_OUT, n_out_w);
        round_copy<<<(n_ff1_w + 1023) / 1024, 256>>>(ff1w, pwb + WB_FF1, n_ff1_w);
        round_copy<<<(n_ff2_w + 1023) / 1024, 256>>>(ff2w, pwb + WB_FF2, n_ff2_w);
        pe_init<<<(S_ * D_) / 256, 256>>>(ppe);
    }

    // input projection + PE table (SIMT, output tf32-rounded)
    gemm_kernel<2><<<dim3(D_ / 128, TOK_ / 128), blk>>>(x_in, w_in, b_in, px, TOK_, D_, IN_, ppe);

    for (int l = 0; l < L_; l++) {
        // QKV projection (output rounded: feeds attention mma)
        gemm_mma<0,1><<<dim3((3 * D_) / 128, TOK_ / 128), mblk, MM_SMEM>>>(
            px, pwb + WB_IN + (size_t)l * 3 * D_ * D_, inpb + l * 3 * D_, pqkv, TOK_, 3 * D_, D_);

        float* attn_l = attn + (size_t)l * B_ * H_ * S_ * S_;

        // fused scores + softmax + probs-out + P@V
        fused_attn<<<dim3(S_ / 32, B_ * H_), blk, FA_SMEM_BYTES>>>(pqkv, attn_l, pctx);

        // output projection (feeds LN: no rounding)
        gemm_mma<0,0><<<dim3(D_ / 128, TOK_ / 128), mblk, MM_SMEM>>>(
            pctx, pwb + WB_OUT + (size_t)l * D_ * D_, outb + l * D_, ptmp, TOK_, D_, D_);

        ln_kernel<<<TOK_, 128>>>(px, ptmp, ln1w + l * D_, ln1b + l * D_, px);

        // ff1 + GELU (output rounded: feeds ff2 mma)
        gemm_mma<1,1><<<dim3(FF_ / 128, TOK_ / 128), mblk, MM_SMEM>>>(
            px, pwb + WB_FF1 + (size_t)l * FF_ * D_, ff1b + l * FF_, pff, TOK_, FF_, D_);

        // ff2 (feeds LN: no rounding)
        gemm_mma<0,0><<<dim3(D_ / 128, TOK_ / 128), mblk, MM_SMEM>>>(
            pff, pwb + WB_FF2 + (size_t)l * D_ * FF_, ff2b + l * D_, ptmp, TOK_, D_, FF_);

        ln_kernel<<<TOK_, 128>>>(px, ptmp, ln2w + l * D_, ln2b + l * D_, px);
    }

    pool_kernel<<<B_, 512>>>(px, ppool);
    gemm_kernel<1><<<dim3(D_ / 128, 1), blk>>>(ppool, h1w, h1b, phead, B_, D_, 2 * D_, ppe);
    head2_kernel<<<B_, 128>>>(phead, h2w, h2b, out);
}

// round 10
// speedup vs baseline: 3.0999x; 1.0050x over previous
#include <cuda_runtime.h>
#include <cstdint>
#include <math.h>

#define B_   32
#define S_   512
#define IN_  64
#define D_   512
#define H_   8
#define L_   4
#define FF_  2048
#define TOK_ (B_ * S_)   // 16384

// ---------------- scratch (device globals; no allocation allowed) ----------------
__device__ __align__(16) float g_x[TOK_ * D_];
__device__ __align__(16) float g_qkv[TOK_ * 3 * D_];
__device__ __align__(16) float g_ctx[TOK_ * D_];
__device__ __align__(16) float g_tmp[TOK_ * D_];
__device__ __align__(16) float g_ff[TOK_ * FF_];
__device__ __align__(16) float g_pool[B_ * 2 * D_];
__device__ __align__(16) float g_head[B_ * D_];
__device__ __align__(16) float g_pe[S_ * D_];     // positional encoding table
// tf32-rounded weights: [in_proj | out_proj | ff1 | ff2]
#define WB_IN  0
#define WB_OUT (WB_IN  + L_ * 3 * D_ * D_)
#define WB_FF1 (WB_OUT + L_ * D_ * D_)
#define WB_FF2 (WB_FF1 + L_ * FF_ * D_)
#define WB_TOT (WB_FF2 + L_ * D_ * FF_)
__device__ __align__(16) float g_wbuf[WB_TOT];

__device__ __forceinline__ float gelu_exact(float v) {
    return 0.5f * v * (1.0f + erff(v * 0.7071067811865475f));
}
__device__ __forceinline__ float tf32r(float f) {
    uint32_t u;
    asm("cvt.rna.tf32.f32 %0, %1;" : "=r"(u) : "f"(f));
    return __uint_as_float(u);
}
// fast exp: poly 2^f, all fma/alu pipe (no MUFU, no libm). valid |x| < ~80.
__device__ __forceinline__ float fast_exp(float x) {
    float y = x * 1.442695041f;
    float z = y + 12582912.f;
    float k = z - 12582912.f;
    float f = y - k;
    float p = 1.3333558e-3f;
    p = fmaf(p, f, 9.6181291e-3f);
    p = fmaf(p, f, 5.5504109e-2f);
    p = fmaf(p, f, 2.4022651e-1f);
    p = fmaf(p, f, 6.9314718e-1f);
    p = fmaf(p, f, 1.0f);
    int ki = (__float_as_int(z) - 0x4B400000) << 23;
    return __int_as_float(__float_as_int(p) + ki);
}
__device__ __forceinline__ uint32_t smem_u32(const void* p) {
    uint32_t a;
    asm("{ .reg .u64 t; cvta.to.shared.u64 t, %1; cvt.u32.u64 %0, t; }" : "=r"(a) : "l"(p));
    return a;
}
__device__ __forceinline__ void mma_tf32(float* c, const uint32_t* a, const uint32_t* b) {
    asm volatile(
        "mma.sync.aligned.m16n8k8.row.col.f32.tf32.tf32.f32 "
        "{%0,%1,%2,%3}, {%4,%5,%6,%7}, {%8,%9}, {%0,%1,%2,%3};"
        : "+f"(c[0]), "+f"(c[1]), "+f"(c[2]), "+f"(c[3])
        : "r"(a[0]), "r"(a[1]), "r"(a[2]), "r"(a[3]), "r"(b[0]), "r"(b[1]));
}
#define FBITS(x) __float_as_uint(x)
// ldmatrix x4 on 32-bit data viewed as b16 pairs (bit-exact move)
#define LDSM_X4(r0, r1, r2, r3, addr) \
    asm volatile("ldmatrix.sync.aligned.m8n8.x4.shared.b16 {%0,%1,%2,%3}, [%4];" \
        : "=r"(r0), "=r"(r1), "=r"(r2), "=r"(r3) : "r"(addr))

// ---------------- merged tf32 rounding of ALL weights (one launch) ----------------
__global__ __launch_bounds__(256)
void round_all(const float* __restrict__ w_in, const float* __restrict__ w_out,
               const float* __restrict__ w_ff1, const float* __restrict__ w_ff2,
               float* __restrict__ dst)
{
    const int i = (blockIdx.x * 256 + threadIdx.x) * 4;
    if (i >= WB_TOT) return;
    const float* src;
    int off;
    if (i < WB_OUT)      { src = w_in;  off = i - WB_IN;  }
    else if (i < WB_FF1) { src = w_out; off = i - WB_OUT; }
    else if (i < WB_FF2) { src = w_ff1; off = i - WB_FF1; }
    else                 { src = w_ff2; off = i - WB_FF2; }
    float4 v = *(const float4*)(src + off);
    v.x = tf32r(v.x); v.y = tf32r(v.y); v.z = tf32r(v.z); v.w = tf32r(v.w);
    *(float4*)(dst + i) = v;
}

// ---------------- positional encoding table (once per replay) ----------------
__global__ __launch_bounds__(256)
void pe_init(float* __restrict__ pe)
{
    const int i = blockIdx.x * 256 + threadIdx.x;   // grid covers S_*D_
    const int s = i >> 9;            // / D_
    const int d = i & (D_ - 1);
    const float freq = expf(-9.210340371976184f * (float)(d & ~1) / (float)D_);
    const float ang = (float)s * freq;
    pe[i] = (d & 1) ? cosf(ang) : sinf(ang);
}

// ======================= mma.sync tf32 GEMM =======================
// C[M,N] = act(A[M,K] * W[N,K]^T + bias). M%128==0, N%128==0, K%32==0, K>=96.
// 128x128x32 CTA tile, 128 threads = 4 warps in 2x2, each warp 64x64.
// 3-buffer / 2-prefetch cp.async pipeline, ONE barrier per K-chunk.
// Fragment loads via ldmatrix.x4. Operands pre-rounded to tf32.
#define MM_RS     36
#define MM_TILEB  (128 * MM_RS * 4)      // 18432 B per operand
#define MM_STAGE  (2 * MM_TILEB)         // 36864 B per stage
#define MM_NST    3
#define MM_SMEM   (MM_NST * MM_STAGE)    // 110592 B

__device__ __forceinline__ void mm_cp_issue(
    const float* __restrict__ A, const float* __restrict__ W,
    uint32_t sbase, int stage, int m0, int n0, int K, int k0, int tid)
{
    const uint32_t as = sbase + stage * MM_STAGE;
    const uint32_t bs = as + MM_TILEB;
#pragma unroll
    for (int i = 0; i < 8; i++) {
        const int idx = i * 128 + tid;
        const int row = idx >> 3;
        const int q = idx & 7;
        const uint32_t so = (uint32_t)(row * (MM_RS * 4) + q * 16);
        const float* ga = A + (size_t)(m0 + row) * K + k0 + q * 4;
        const float* gw = W + (size_t)(n0 + row) * K + k0 + q * 4;
        asm volatile("cp.async.cg.shared.global [%0], [%1], 16;" :: "r"(as + so), "l"(ga));
        asm volatile("cp.async.cg.shared.global [%0], [%1], 16;" :: "r"(bs + so), "l"(gw));
    }
    asm volatile("cp.async.commit_group;" ::: "memory");
}

template <int ACT, int RND>   // ACT: 0=none,1=GELU ; RND: round output to tf32
__global__ __launch_bounds__(128, 2)
void gemm_mma(const float* __restrict__ A, const float* __restrict__ W,
              const float* __restrict__ bias, float* __restrict__ C,
              int M, int N, int K)
{
    extern __shared__ char smem[];
    const uint32_t sbase = smem_u32(smem);
    const int tid = threadIdx.x;
    const int lane = tid & 31, wid = tid >> 5;
    const int g = lane >> 2, t4 = lane & 3;
    const int wm = wid & 1;          // M half (64 rows)
    const int wn = wid >> 1;         // N half (64 cols)
    const int m0 = blockIdx.y * 128, n0 = blockIdx.x * 128;

    const uint32_t a_lane = (uint32_t)((wm * 64 + (lane & 7) + (lane & 8)) * MM_RS
                                       + ((lane & 16) >> 2));
    const uint32_t b_lane = (uint32_t)((wn * 64 + ((lane & 16) >> 1) + (lane & 7)) * MM_RS
                                       + ((lane & 8) >> 1));

    float acc[4][8][4];
#pragma unroll
    for (int mt = 0; mt < 4; mt++)
#pragma unroll
        for (int nt = 0; nt < 8; nt++)
#pragma unroll
            for (int j = 0; j < 4; j++) acc[mt][nt][j] = 0.f;

    const int nch = K >> 5;          // assume nch >= 2
    // 3 buffers, 2 chunks prefetched, <=2 cp groups outstanding, 1 barrier/chunk
    mm_cp_issue(A, W, sbase, 0, m0, n0, K, 0, tid);
    mm_cp_issue(A, W, sbase, 1, m0, n0, K, 32, tid);

    int cur = 0;
    for (int c = 0; c < nch; c++) {
        if (c + 1 < nch)
            asm volatile("cp.async.wait_group 1;" ::: "memory");
        else
            asm volatile("cp.async.wait_group 0;" ::: "memory");
        __syncthreads();
        // every warp at this barrier finished iter c-1 -> safe to overwrite
        // stage (cur+2)%3 (it held chunk c-1), and chunk c is visible to all.
        if (c + 2 < nch) {
            int tgt = cur + 2; if (tgt >= 3) tgt -= 3;
            mm_cp_issue(A, W, sbase, tgt, m0, n0, K, (c + 2) * 32, tid);
        }

        const uint32_t a_base = sbase + cur * MM_STAGE + a_lane * 4;
        const uint32_t b_base = sbase + cur * MM_STAGE + MM_TILEB + b_lane * 4;

#pragma unroll
        for (int ks = 0; ks < 4; ks++) {
            uint32_t afr[4][4];
#pragma unroll
            for (int mt = 0; mt < 4; mt++)
                LDSM_X4(afr[mt][0], afr[mt][1], afr[mt][2], afr[mt][3],
                        a_base + (uint32_t)(mt * 16 * MM_RS + ks * 8) * 4);
            uint32_t bfr[8][2];
#pragma unroll
            for (int p = 0; p < 4; p++)
                LDSM_X4(bfr[2 * p][0], bfr[2 * p][1], bfr[2 * p + 1][0], bfr[2 * p + 1][1],
                        b_base + (uint32_t)(p * 16 * MM_RS + ks * 8) * 4);
#pragma unroll
            for (int mt = 0; mt < 4; mt++)
#pragma unroll
                for (int nt = 0; nt < 8; nt++)
                    mma_tf32(acc[mt][nt], afr[mt], bfr[nt]);
        }
        cur = (cur == 2) ? 0 : cur + 1;
    }

#pragma unroll
    for (int mt = 0; mt < 4; mt++) {
        const int r0 = m0 + wm * 64 + mt * 16 + g;
#pragma unroll
        for (int nt = 0; nt < 8; nt++) {
            const int cb = n0 + wn * 64 + nt * 8 + 2 * t4;
            const float b0 = bias[cb], b1 = bias[cb + 1];
            float v0 = acc[mt][nt][0] + b0;
            float v1 = acc[mt][nt][1] + b1;
            float v2 = acc[mt][nt][2] + b0;
            float v3 = acc[mt][nt][3] + b1;
            if (ACT == 1) {
                v0 = gelu_exact(v0); v1 = gelu_exact(v1);
                v2 = gelu_exact(v2); v3 = gelu_exact(v3);
            }
            if (RND) {
                v0 = tf32r(v0); v1 = tf32r(v1); v2 = tf32r(v2); v3 = tf32r(v3);
            }
            *(float2*)&C[(size_t)r0 * N + cb]       = make_float2(v0, v1);
            *(float2*)&C[(size_t)(r0 + 8) * N + cb] = make_float2(v2, v3);
        }
    }
}

// ======================= fused attention =======================
// block = (q-tile of 32 rows) x (b*H + h). 256 threads (8 warps), 2 CTAs/SM.
#define FA_QS 68
#define FA_SS 516
#define FA_KS 68
#define FA_VS 72       // 72 % 32 == 8 -> PV B-fragment loads conflict-free
#define FA_SMEM_FLOATS (32 * FA_QS + 32 * FA_SS + 128 * FA_VS)
#define FA_SMEM_BYTES  (FA_SMEM_FLOATS * 4)     // 111616

__global__ __launch_bounds__(256, 2)
void fused_attn(const float* __restrict__ qkv, float* __restrict__ probs,
                float* __restrict__ ctx)
{
    extern __shared__ float sm[];
    float* qs = sm;                       // [32][68]
    float* sc = sm + 32 * FA_QS;          // [32][516]
    float* kv = sc + 32 * FA_SS;          // [128][68] (K) / [128][72] (V)
    const uint32_t sbase = smem_u32(sm);

    const int tid = threadIdx.x;
    const int lane = tid & 31, wid = tid >> 5;
    const int g = lane >> 2, t4 = lane & 3;
    const int q0 = blockIdx.x * 32;
    const int bh = blockIdx.y;
    const int b = bh >> 3, h = bh & 7;
    const int wm = wid & 1;
    const int wn = wid >> 1;

    // ldmatrix lane addresses (element offsets; stride ≡ 16B mod 128B -> conflict-free)
    const uint32_t qa_addr = sbase +
        (uint32_t)((wm * 16 + (lane & 7) + (lane & 8)) * FA_QS + ((lane & 16) >> 2)) * 4;
    const uint32_t kb_addr = sbase + (uint32_t)(32 * FA_QS + 32 * FA_SS) * 4 +
        (uint32_t)((wn * 32 + ((lane & 16) >> 1) + (lane & 7)) * FA_KS + ((lane & 8) >> 1)) * 4;
    const uint32_t pa_addr = sbase + (uint32_t)(32 * FA_QS) * 4 +
        (uint32_t)((wm * 16 + (lane & 7) + (lane & 8)) * FA_SS + ((lane & 16) >> 2)) * 4;

    {
        const int r = tid >> 3;
        const int d0 = (tid & 7) * 8;
        const float* src = qkv + (size_t)(b * S_ + q0 + r) * 1536 + h * 64 + d0;
        const float4 v0 = *(const float4*)src;
        const float4 v1 = *(const float4*)(src + 4);
        float* dst = qs + r * FA_QS + d0;
        dst[0] = v0.x * 0.125f; dst[1] = v0.y * 0.125f;
        dst[2] = v0.z * 0.125f; dst[3] = v0.w * 0.125f;
        dst[4] = v1.x * 0.125f; dst[5] = v1.y * 0.125f;
        dst[6] = v1.z * 0.125f; dst[7] = v1.w * 0.125f;
    }

    for (int kt = 0; kt < 4; kt++) {
        __syncthreads();
#pragma unroll
        for (int i = 0; i < 4; i++) {
            const int idx = i * 256 + tid;
            const int r = idx >> 3;
            const int d0 = (idx & 7) * 8;
            const float* src = qkv + (size_t)(b * S_ + kt * 128 + r) * 1536 + D_ + h * 64 + d0;
            const float4 v0 = *(const float4*)src;
            const float4 v1 = *(const float4*)(src + 4);
            float* dst = kv + r * FA_KS + d0;
            dst[0] = v0.x; dst[1] = v0.y; dst[2] = v0.z; dst[3] = v0.w;
            dst[4] = v1.x; dst[5] = v1.y; dst[6] = v1.z; dst[7] = v1.w;
        }
        __syncthreads();

        float acc[4][4];
#pragma unroll
        for (int nt = 0; nt < 4; nt++)
#pragma unroll
            for (int j = 0; j < 4; j++) acc[nt][j] = 0.f;

#pragma unroll
        for (int ks = 0; ks < 8; ks++) {
            uint32_t afr[4];
            LDSM_X4(afr[0], afr[1], afr[2], afr[3], qa_addr + (uint32_t)(ks * 8) * 4);
            uint32_t bfr[4][2];
#pragma unroll
            for (int p = 0; p < 2; p++)
                LDSM_X4(bfr[2 * p][0], bfr[2 * p][1], bfr[2 * p + 1][0], bfr[2 * p + 1][1],
                        kb_addr + (uint32_t)(p * 16 * FA_KS + ks * 8) * 4);
#pragma unroll
            for (int nt = 0; nt < 4; nt++)
                mma_tf32(acc[nt], afr, bfr[nt]);
        }
#pragma unroll
        for (int nt = 0; nt < 4; nt++) {
            const int col = kt * 128 + wn * 32 + nt * 8 + 2 * t4;
            const int row = wm * 16 + g;
            *(float2*)&sc[row * FA_SS + col]       = make_float2(acc[nt][0], acc[nt][1]);
            *(float2*)&sc[(row + 8) * FA_SS + col] = make_float2(acc[nt][2], acc[nt][3]);
        }
    }
    __syncthreads();

#pragma unroll
    for (int rr = 0; rr < 4; rr++) {
        const int row = wid * 4 + rr;
        float vals[16];
        float sum = 0.f;
#pragma unroll
        for (int t = 0; t < 4; t++) {
            const float4 v = *(const float4*)&sc[row * FA_SS + lane * 4 + t * 128];
            vals[t * 4 + 0] = fast_exp(v.x);
            vals[t * 4 + 1] = fast_exp(v.y);
            vals[t * 4 + 2] = fast_exp(v.z);
            vals[t * 4 + 3] = fast_exp(v.w);
            sum += vals[t * 4 + 0] + vals[t * 4 + 1] + vals[t * 4 + 2] + vals[t * 4 + 3];
        }
#pragma unroll
        for (int o = 16; o > 0; o >>= 1)
            sum += __shfl_xor_sync(0xFFFFFFFFu, sum, o);
        const float inv = 1.f / sum;
        float* prow = probs + ((size_t)bh * S_ + q0 + row) * S_;
#pragma unroll
        for (int t = 0; t < 4; t++) {
            float4 o;
            o.x = tf32r(vals[t * 4 + 0] * inv);
            o.y = tf32r(vals[t * 4 + 1] * inv);
            o.z = tf32r(vals[t * 4 + 2] * inv);
            o.w = tf32r(vals[t * 4 + 3] * inv);
            *(float4*)&sc[row * FA_SS + lane * 4 + t * 128] = o;
            *(float4*)&prow[lane * 4 + t * 128] = o;
        }
    }

    float pacc[2][4];
#pragma unroll
    for (int nt = 0; nt < 2; nt++)
#pragma unroll
        for (int j = 0; j < 4; j++) pacc[nt][j] = 0.f;

    for (int vt = 0; vt < 4; vt++) {
        __syncthreads();
#pragma unroll
        for (int i = 0; i < 8; i++) {
            const int idx = i * 256 + tid;
            const int r = idx >> 4;
            const int d0 = (idx & 15) * 4;
            const float4 v = *(const float4*)&qkv[(size_t)(b * S_ + vt * 128 + r) * 1536 + 2 * D_ + h * 64 + d0];
            float* dst = kv + r * FA_VS + d0;
            dst[0] = v.x; dst[1] = v.y; dst[2] = v.z; dst[3] = v.w;
        }
        __syncthreads();

#pragma unroll
        for (int ks = 0; ks < 16; ks++) {
            uint32_t afr[4];
            LDSM_X4(afr[0], afr[1], afr[2], afr[3],
                    pa_addr + (uint32_t)(vt * 128 + ks * 8) * 4);
#pragma unroll
            for (int nt = 0; nt < 2; nt++) {
                const float* bp = kv + (ks * 8 + t4) * FA_VS + wn * 16 + nt * 8 + g;
                uint32_t bfr[2] = {FBITS(bp[0]), FBITS(bp[4 * FA_VS])};
                mma_tf32(pacc[nt], afr, bfr);
            }
        }
    }

#pragma unroll
    for (int nt = 0; nt < 2; nt++) {
        const int row = b * S_ + q0 + wm * 16 + g;
        const int col = h * 64 + wn * 16 + nt * 8 + 2 * t4;
        *(float2*)&ctx[(size_t)row * D_ + col] =
            make_float2(tf32r(pacc[nt][0]), tf32r(pacc[nt][1]));
        *(float2*)&ctx[(size_t)(row + 8) * D_ + col] =
            make_float2(tf32r(pacc[nt][2]), tf32r(pacc[nt][3]));
    }
}

// ---------------- SIMT GEMM (input proj / head1) ----------------
template <int ACT>   // 0=none, 1=GELU, 2=add PE table + tf32 round
__global__ __launch_bounds__(256)
void gemm_kernel(const float* __restrict__ A, const float* __restrict__ W,
                 const float* __restrict__ bias, float* __restrict__ C,
                 int M, int N, int K, const float* __restrict__ pe)
{
    __shared__ __align__(16) float As[8][128];
    __shared__ __align__(16) float Ws[8][128];

    const int tid = threadIdx.x;
    const int tx = tid & 15;
    const int ty = tid >> 4;
    const int m0 = blockIdx.y * 128;
    const int n0 = blockIdx.x * 128;

    float acc[2][2][4][4];
#pragma unroll
    for (int p = 0; p < 2; p++)
#pragma unroll
        for (int q = 0; q < 2; q++)
#pragma unroll
            for (int i = 0; i < 4; i++)
#pragma unroll
                for (int j = 0; j < 4; j++) acc[p][q][i][j] = 0.f;

    const int lr = tid >> 1;
    const int lk = (tid & 1) * 4;
    const float* Ag = A + (size_t)(m0 + lr) * K + lk;
    const float* Wg = W + (size_t)(n0 + lr) * K + lk;
    const bool aval = (m0 + lr) < M;

    for (int k0 = 0; k0 < K; k0 += 8) {
        float4 av = make_float4(0.f, 0.f, 0.f, 0.f);
        if (aval) av = *(const float4*)(Ag + k0);
        const float4 wv = *(const float4*)(Wg + k0);
        __syncthreads();
        As[lk + 0][lr] = av.x; As[lk + 1][lr] = av.y;
        As[lk + 2][lr] = av.z; As[lk + 3][lr] = av.w;
        Ws[lk + 0][lr] = wv.x; Ws[lk + 1][lr] = wv.y;
        Ws[lk + 2][lr] = wv.z; Ws[lk + 3][lr] = wv.w;
        __syncthreads();
#pragma unroll
        for (int kk = 0; kk < 8; kk++) {
            const float4 a0 = *(const float4*)&As[kk][ty * 4];
            const float4 a1 = *(const float4*)&As[kk][64 + ty * 4];
            const float4 b0 = *(const float4*)&Ws[kk][tx * 4];
            const float4 b1 = *(const float4*)&Ws[kk][64 + tx * 4];
            const float ar[2][4] = {{a0.x, a0.y, a0.z, a0.w}, {a1.x, a1.y, a1.z, a1.w}};
            const float br[2][4] = {{b0.x, b0.y, b0.z, b0.w}, {b1.x, b1.y, b1.z, b1.w}};
#pragma unroll
            for (int p = 0; p < 2; p++)
#pragma unroll
                for (int q = 0; q < 2; q++)
#pragma unroll
                    for (int i = 0; i < 4; i++)
#pragma unroll
                        for (int j = 0; j < 4; j++)
                            acc[p][q][i][j] += ar[p][i] * br[q][j];
        }
    }

#pragma unroll
    for (int p = 0; p < 2; p++) {
#pragma unroll
        for (int i = 0; i < 4; i++) {
            const int m = m0 + p * 64 + ty * 4 + i;
            if (m >= M) continue;
#pragma unroll
            for (int q = 0; q < 2; q++) {
                const int c = n0 + q * 64 + tx * 4;
                float4 o;
                float* po = &o.x;
#pragma unroll
                for (int j = 0; j < 4; j++) {
                    float v = acc[p][q][i][j] + bias[c + j];
                    if (ACT == 1) {
                        v = gelu_exact(v);
                    } else if (ACT == 2) {
                        v += pe[(m & (S_ - 1)) * D_ + c + j];
                        v = tf32r(v);
                    }
                    po[j] = v;
                }
                *(float4*)&C[(size_t)m * N + c] = o;
            }
        }
    }
}

// ---------------- fused residual-add + LayerNorm (tf32-rounded output) ----------------
__global__ __launch_bounds__(128)
void ln_kernel(const float* __restrict__ x, const float* __restrict__ add,
               const float* __restrict__ w, const float* __restrict__ bvec,
               float* __restrict__ out)
{
    const int row = blockIdx.x;
    const int tid = threadIdx.x;
    const float* xr = x + (size_t)row * D_;
    const float* ar = add + (size_t)row * D_;
    float v[4];
    float s = 0.f;
#pragma unroll
    for (int i = 0; i < 4; i++) {
        const int c = tid + i * 128;
        v[i] = xr[c] + ar[c];
        s += v[i];
    }
    __shared__ float red[4];
#pragma unroll
    for (int o = 16; o > 0; o >>= 1) s += __shfl_xor_sync(0xFFFFFFFFu, s, o);
    if ((tid & 31) == 0) red[tid >> 5] = s;
    __syncthreads();
    const float mean = (red[0] + red[1] + red[2] + red[3]) * (1.f / 512.f);
    float vs = 0.f;
#pragma unroll
    for (int i = 0; i < 4; i++) {
        const float d = v[i] - mean;
        vs += d * d;
    }
    __syncthreads();
#pragma unroll
    for (int o = 16; o > 0; o >>= 1) vs += __shfl_xor_sync(0xFFFFFFFFu, vs, o);
    if ((tid & 31) == 0) red[tid >> 5] = vs;
    __syncthreads();
    const float rstd = rsqrtf((red[0] + red[1] + red[2] + red[3]) * (1.f / 512.f) + 1e-5f);
    float* orow = out + (size_t)row * D_;
#pragma unroll
    for (int i = 0; i < 4; i++) {
        const int c = tid + i * 128;
        orow[c] = tf32r((v[i] - mean) * rstd * w[c] + bvec[c]);
    }
}

// ---------------- mean+max pooling over sequence ----------------
__global__ __launch_bounds__(512)
void pool_kernel(const float* __restrict__ x, float* __restrict__ pool)
{
    const int b = blockIdx.x, d = threadIdx.x;
    float s = 0.f, m = -1e30f;
    for (int t = 0; t < S_; t++) {
        const float v = x[(size_t)(b * S_ + t) * D_ + d];
        s += v;
        m = fmaxf(m, v);
    }
    pool[b * (2 * D_) + d] = s * (1.f / 512.f);
    pool[b * (2 * D_) + D_ + d] = m;
}

// ---------------- final head ----------------
__global__ __launch_bounds__(128)
void head2_kernel(const float* __restrict__ h, const float* __restrict__ w,
                  const float* __restrict__ bb, float* __restrict__ out)
{
    const int b = blockIdx.x, tid = threadIdx.x;
    float s = 0.f;
    for (int c = tid; c < D_; c += 128) s += h[(size_t)b * D_ + c] * w[c];
    __shared__ float red[4];
#pragma unroll
    for (int o = 16; o > 0; o >>= 1) s += __shfl_xor_sync(0xFFFFFFFFu, s, o);
    if ((tid & 31) == 0) red[tid >> 5] = s;
    __syncthreads();
    if (tid == 0) out[b] = red[0] + red[1] + red[2] + red[3] + bb[0];
}

// ---------------- launch ----------------
extern "C" void kernel_launch(void* const* d_in, const int* in_sizes, int n_in,
                              void* d_out, int out_size)
{
    const float* x_in = (const float*)d_in[0];
    const float* w_in = (const float*)d_in[1];
    const float* b_in = (const float*)d_in[2];
    const float* inpw = (const float*)d_in[3];
    const float* inpb = (const float*)d_in[4];
    const float* outw = (const float*)d_in[5];
    const float* outb = (const float*)d_in[6];
    const float* ln1w = (const float*)d_in[7];
    const float* ln1b = (const float*)d_in[8];
    const float* ln2w = (const float*)d_in[9];
    const float* ln2b = (const float*)d_in[10];
    const float* ff1w = (const float*)d_in[11];
    const float* ff1b = (const float*)d_in[12];
    const float* ff2w = (const float*)d_in[13];
    const float* ff2b = (const float*)d_in[14];
    const float* h1w  = (const float*)d_in[15];
    const float* h1b  = (const float*)d_in[16];
    const float* h2w  = (const float*)d_in[17];
    const float* h2b  = (const float*)d_in[18];

    float* out  = (float*)d_out;
    float* attn = out + 32;   // [L,B,H,S,S] follows the [B,1] output

    float *px, *pqkv, *pctx, *ptmp, *pff, *ppool, *phead, *pwb, *ppe;
    cudaGetSymbolAddress((void**)&px,    g_x);
    cudaGetSymbolAddress((void**)&pqkv,  g_qkv);
    cudaGetSymbolAddress((void**)&pctx,  g_ctx);
    cudaGetSymbolAddress((void**)&ptmp,  g_tmp);
    cudaGetSymbolAddress((void**)&pff,   g_ff);
    cudaGetSymbolAddress((void**)&ppool, g_pool);
    cudaGetSymbolAddress((void**)&phead, g_head);
    cudaGetSymbolAddress((void**)&pwb,   g_wbuf);
    cudaGetSymbolAddress((void**)&ppe,   g_pe);

    cudaFuncSetAttribute(gemm_mma<0,1>, cudaFuncAttributeMaxDynamicSharedMemorySize, MM_SMEM);
    cudaFuncSetAttribute(gemm_mma<0,0>, cudaFuncAttributeMaxDynamicSharedMemorySize, MM_SMEM);
    cudaFuncSetAttribute(gemm_mma<1,1>, cudaFuncAttributeMaxDynamicSharedMemorySize, MM_SMEM);
    cudaFuncSetAttribute(fused_attn, cudaFuncAttributeMaxDynamicSharedMemorySize, FA_SMEM_BYTES);

    const dim3 blk(256);
    const dim3 mblk(128);

    // per-replay setup: ONE merged tf32-rounding launch + PE table
    round_all<<<WB_TOT / 1024, 256>>>(inpw, outw, ff1w, ff2w, pwb);
    pe_init<<<(S_ * D_) / 256, 256>>>(ppe);

    // input projection + PE table (SIMT, output tf32-rounded)
    gemm_kernel<2><<<dim3(D_ / 128, TOK_ / 128), blk>>>(x_in, w_in, b_in, px, TOK_, D_, IN_, ppe);

    for (int l = 0; l < L_; l++) {
        // QKV projection (output rounded: feeds attention mma)
        gemm_mma<0,1><<<dim3((3 * D_) / 128, TOK_ / 128), mblk, MM_SMEM>>>(
            px, pwb + WB_IN + (size_t)l * 3 * D_ * D_, inpb + l * 3 * D_, pqkv, TOK_, 3 * D_, D_);

        float* attn_l = attn + (size_t)l * B_ * H_ * S_ * S_;

        // fused scores + softmax + probs-out + P@V
        fused_attn<<<dim3(S_ / 32, B_ * H_), blk, FA_SMEM_BYTES>>>(pqkv, attn_l, pctx);

        // output projection (feeds LN: no rounding)
        gemm_mma<0,0><<<dim3(D_ / 128, TOK_ / 128), mblk, MM_SMEM>>>(
            pctx, pwb + WB_OUT + (size_t)l * D_ * D_, outb + l * D_, ptmp, TOK_, D_, D_);

        ln_kernel<<<TOK_, 128>>>(px, ptmp, ln1w + l * D_, ln1b + l * D_, px);

        // ff1 + GELU (output rounded: feeds ff2 mma)
        gemm_mma<1,1><<<dim3(FF_ / 128, TOK_ / 128), mblk, MM_SMEM>>>(
            px, pwb + WB_FF1 + (size_t)l * FF_ * D_, ff1b + l * FF_, pff, TOK_, FF_, D_);

        // ff2 (feeds LN: no rounding)
        gemm_mma<0,0><<<dim3(D_ / 128, TOK_ / 128), mblk, MM_SMEM>>>(
            pff, pwb + WB_FF2 + (size_t)l * D_ * FF_, ff2b + l * D_, ptmp, TOK_, D_, FF_);

        ln_kernel<<<TOK_, 128>>>(px, ptmp, ln2w + l * D_, ln2b + l * D_, px);
    }

    pool_kernel<<<B_, 512>>>(px, ppool);
    gemm_kernel<1><<<dim3(D_ / 128, 1), blk>>>(ppool, h1w, h1b, phead, B_, D_, 2 * D_, ppe);
    head2_kernel<<<B_, 128>>>(phead, h2w, h2b, out);
}

// round 12
// speedup vs baseline: 3.2911x; 1.0617x over previous
#include <cuda_runtime.h>
#include <cstdint>
#include <math.h>

#define B_   32
#define S_   512
#define IN_  64
#define D_   512
#define H_   8
#define L_   4
#define FF_  2048
#define TOK_ (B_ * S_)   // 16384

// ---------------- scratch (device globals; no allocation allowed) ----------------
__device__ __align__(16) float g_x[TOK_ * D_];
__device__ __align__(16) float g_qkv[TOK_ * 3 * D_];
__device__ __align__(16) float g_ctx[TOK_ * D_];
__device__ __align__(16) float g_tmp[TOK_ * D_];
__device__ __align__(16) float g_ff[TOK_ * FF_];
__device__ __align__(16) float g_pool[B_ * 2 * D_];
__device__ __align__(16) float g_head[B_ * D_];
__device__ __align__(16) float g_pe[S_ * D_];     // positional encoding table
// tf32-rounded weights: [in_proj | out_proj | ff1 | ff2]
#define WB_IN  0
#define WB_OUT (WB_IN  + L_ * 3 * D_ * D_)
#define WB_FF1 (WB_OUT + L_ * D_ * D_)
#define WB_FF2 (WB_FF1 + L_ * FF_ * D_)
#define WB_TOT (WB_FF2 + L_ * D_ * FF_)
__device__ __align__(16) float g_wbuf[WB_TOT];

__device__ __forceinline__ float gelu_exact(float v) {
    return 0.5f * v * (1.0f + erff(v * 0.7071067811865475f));
}
__device__ __forceinline__ float tf32r(float f) {
    uint32_t u;
    asm("cvt.rna.tf32.f32 %0, %1;" : "=r"(u) : "f"(f));
    return __uint_as_float(u);
}
// fast exp: poly 2^f, all fma/alu pipe (no MUFU, no libm). valid |x| < ~80.
__device__ __forceinline__ float fast_exp(float x) {
    float y = x * 1.442695041f;
    float z = y + 12582912.f;
    float k = z - 12582912.f;
    float f = y - k;
    float p = 1.3333558e-3f;
    p = fmaf(p, f, 9.6181291e-3f);
    p = fmaf(p, f, 5.5504109e-2f);
    p = fmaf(p, f, 2.4022651e-1f);
    p = fmaf(p, f, 6.9314718e-1f);
    p = fmaf(p, f, 1.0f);
    int ki = (__float_as_int(z) - 0x4B400000) << 23;
    return __int_as_float(__float_as_int(p) + ki);
}
__device__ __forceinline__ uint32_t smem_u32(const void* p) {
    uint32_t a;
    asm("{ .reg .u64 t; cvta.to.shared.u64 t, %1; cvt.u32.u64 %0, t; }" : "=r"(a) : "l"(p));
    return a;
}
// NOTE: non-volatile — pure register op; lets the compiler interleave HMMA
// with the next step's ldmatrix (software pipelining for free).
__device__ __forceinline__ void mma_tf32(float* c, const uint32_t* a, const uint32_t* b) {
    asm("mma.sync.aligned.m16n8k8.row.col.f32.tf32.tf32.f32 "
        "{%0,%1,%2,%3}, {%4,%5,%6,%7}, {%8,%9}, {%0,%1,%2,%3};"
        : "+f"(c[0]), "+f"(c[1]), "+f"(c[2]), "+f"(c[3])
        : "r"(a[0]), "r"(a[1]), "r"(a[2]), "r"(a[3]), "r"(b[0]), "r"(b[1]));
}
#define FBITS(x) __float_as_uint(x)
// ldmatrix x4 on 32-bit data viewed as b16 pairs (bit-exact move).
// stays volatile: must not hoist above barriers (no visible memory operand).
#define LDSM_X4(r0, r1, r2, r3, addr) \
    asm volatile("ldmatrix.sync.aligned.m8n8.x4.shared.b16 {%0,%1,%2,%3}, [%4];" \
        : "=r"(r0), "=r"(r1), "=r"(r2), "=r"(r3) : "r"(addr))

// ---------------- merged tf32 rounding of ALL weights (one launch) ----------------
__global__ __launch_bounds__(256)
void round_all(const float* __restrict__ w_in, const float* __restrict__ w_out,
               const float* __restrict__ w_ff1, const float* __restrict__ w_ff2,
               float* __restrict__ dst)
{
    const int i = (blockIdx.x * 256 + threadIdx.x) * 4;
    if (i >= WB_TOT) return;
    const float* src;
    int off;
    if (i < WB_OUT)      { src = w_in;  off = i - WB_IN;  }
    else if (i < WB_FF1) { src = w_out; off = i - WB_OUT; }
    else if (i < WB_FF2) { src = w_ff1; off = i - WB_FF1; }
    else                 { src = w_ff2; off = i - WB_FF2; }
    float4 v = *(const float4*)(src + off);
    v.x = tf32r(v.x); v.y = tf32r(v.y); v.z = tf32r(v.z); v.w = tf32r(v.w);
    *(float4*)(dst + i) = v;
}

// ---------------- positional encoding table (once per replay) ----------------
__global__ __launch_bounds__(256)
void pe_init(float* __restrict__ pe)
{
    const int i = blockIdx.x * 256 + threadIdx.x;   // grid covers S_*D_
    const int s = i >> 9;            // / D_
    const int d = i & (D_ - 1);
    const float freq = expf(-9.210340371976184f * (float)(d & ~1) / (float)D_);
    const float ang = (float)s * freq;
    pe[i] = (d & 1) ? cosf(ang) : sinf(ang);
}

// ======================= mma.sync tf32 GEMM =======================
// C[M,N] = act(A[M,K] * W[N,K]^T + bias). M%128==0, N%128==0, K%32==0, K>=96.
// 128x128x32 CTA tile, 128 threads = 4 warps in 2x2, each warp 64x64.
// 3-buffer / 2-prefetch cp.async pipeline, ONE barrier per K-chunk,
// cp issue moved after mma to keep the MIO queue clear post-barrier.
#define MM_RS     36
#define MM_TILEB  (128 * MM_RS * 4)      // 18432 B per operand
#define MM_STAGE  (2 * MM_TILEB)         // 36864 B per stage
#define MM_NST    3
#define MM_SMEM   (MM_NST * MM_STAGE)    // 110592 B

__device__ __forceinline__ void mm_cp_issue(
    const float* __restrict__ A, const float* __restrict__ W,
    uint32_t sbase, int stage, int m0, int n0, int K, int k0, int tid)
{
    const uint32_t as = sbase + stage * MM_STAGE;
    const uint32_t bs = as + MM_TILEB;
#pragma unroll
    for (int i = 0; i < 8; i++) {
        const int idx = i * 128 + tid;
        const int row = idx >> 3;
        const int q = idx & 7;
        const uint32_t so = (uint32_t)(row * (MM_RS * 4) + q * 16);
        const float* ga = A + (size_t)(m0 + row) * K + k0 + q * 4;
        const float* gw = W + (size_t)(n0 + row) * K + k0 + q * 4;
        asm volatile("cp.async.cg.shared.global [%0], [%1], 16;" :: "r"(as + so), "l"(ga));
        asm volatile("cp.async.cg.shared.global [%0], [%1], 16;" :: "r"(bs + so), "l"(gw));
    }
    asm volatile("cp.async.commit_group;" ::: "memory");
}

template <int ACT, int RND>   // ACT: 0=none,1=GELU ; RND: round output to tf32
__global__ __launch_bounds__(128, 2)
void gemm_mma(const float* __restrict__ A, const float* __restrict__ W,
              const float* __restrict__ bias, float* __restrict__ C,
              int M, int N, int K)
{
    extern __shared__ char smem[];
    const uint32_t sbase = smem_u32(smem);
    const int tid = threadIdx.x;
    const int lane = tid & 31, wid = tid >> 5;
    const int g = lane >> 2, t4 = lane & 3;
    const int wm = wid & 1;          // M half (64 rows)
    const int wn = wid >> 1;         // N half (64 cols)
    const int m0 = blockIdx.y * 128, n0 = blockIdx.x * 128;

    const uint32_t a_lane = (uint32_t)((wm * 64 + (lane & 7) + (lane & 8)) * MM_RS
                                       + ((lane & 16) >> 2));
    const uint32_t b_lane = (uint32_t)((wn * 64 + ((lane & 16) >> 1) + (lane & 7)) * MM_RS
                                       + ((lane & 8) >> 1));

    float acc[4][8][4];
#pragma unroll
    for (int mt = 0; mt < 4; mt++)
#pragma unroll
        for (int nt = 0; nt < 8; nt++)
#pragma unroll
            for (int j = 0; j < 4; j++) acc[mt][nt][j] = 0.f;

    const int nch = K >> 5;          // assume nch >= 2
    // 3 buffers, 2 chunks prefetched, <=2 cp groups outstanding, 1 barrier/chunk
    mm_cp_issue(A, W, sbase, 0, m0, n0, K, 0, tid);
    mm_cp_issue(A, W, sbase, 1, m0, n0, K, 32, tid);

    int cur = 0;
    for (int c = 0; c < nch; c++) {
        if (c + 1 < nch)
            asm volatile("cp.async.wait_group 1;" ::: "memory");
        else
            asm volatile("cp.async.wait_group 0;" ::: "memory");
        __syncthreads();

        const uint32_t a_base = sbase + cur * MM_STAGE + a_lane * 4;
        const uint32_t b_base = sbase + cur * MM_STAGE + MM_TILEB + b_lane * 4;

#pragma unroll
        for (int ks = 0; ks < 4; ks++) {
            uint32_t afr[4][4];
#pragma unroll
            for (int mt = 0; mt < 4; mt++)
                LDSM_X4(afr[mt][0], afr[mt][1], afr[mt][2], afr[mt][3],
                        a_base + (uint32_t)(mt * 16 * MM_RS + ks * 8) * 4);
            uint32_t bfr[8][2];
#pragma unroll
            for (int p = 0; p < 4; p++)
                LDSM_X4(bfr[2 * p][0], bfr[2 * p][1], bfr[2 * p + 1][0], bfr[2 * p + 1][1],
                        b_base + (uint32_t)(p * 16 * MM_RS + ks * 8) * 4);
#pragma unroll
            for (int mt = 0; mt < 4; mt++)
#pragma unroll
                for (int nt = 0; nt < 8; nt++)
                    mma_tf32(acc[mt][nt], afr[mt], bfr[nt]);
        }
        // issue chunk c+2 AFTER compute: the top-of-iteration barrier already
        // guarantees no warp still reads stage (cur+2)%3 (it held chunk c-1).
        if (c + 2 < nch) {
            int tgt = cur + 2; if (tgt >= 3) tgt -= 3;
            mm_cp_issue(A, W, sbase, tgt, m0, n0, K, (c + 2) * 32, tid);
        }
        cur = (cur == 2) ? 0 : cur + 1;
    }

#pragma unroll
    for (int mt = 0; mt < 4; mt++) {
        const int r0 = m0 + wm * 64 + mt * 16 + g;
#pragma unroll
        for (int nt = 0; nt < 8; nt++) {
            const int cb = n0 + wn * 64 + nt * 8 + 2 * t4;
            const float b0 = bias[cb], b1 = bias[cb + 1];
            float v0 = acc[mt][nt][0] + b0;
            float v1 = acc[mt][nt][1] + b1;
            float v2 = acc[mt][nt][2] + b0;
            float v3 = acc[mt][nt][3] + b1;
            if (ACT == 1) {
                v0 = gelu_exact(v0); v1 = gelu_exact(v1);
                v2 = gelu_exact(v2); v3 = gelu_exact(v3);
            }
            if (RND) {
                v0 = tf32r(v0); v1 = tf32r(v1); v2 = tf32r(v2); v3 = tf32r(v3);
            }
            *(float2*)&C[(size_t)r0 * N + cb]       = make_float2(v0, v1);
            *(float2*)&C[(size_t)(r0 + 8) * N + cb] = make_float2(v2, v3);
        }
    }
}

// ======================= fused attention =======================
// block = (q-tile of 32 rows) x (b*H + h). 256 threads (8 warps), 2 CTAs/SM.
#define FA_QS 68
#define FA_SS 516
#define FA_KS 68
#define FA_VS 72       // 72 % 32 == 8 -> PV B-fragment loads conflict-free
#define FA_SMEM_FLOATS (32 * FA_QS + 32 * FA_SS + 128 * FA_VS)
#define FA_SMEM_BYTES  (FA_SMEM_FLOATS * 4)     // 111616

__global__ __launch_bounds__(256, 2)
void fused_attn(const float* __restrict__ qkv, float* __restrict__ probs,
                float* __restrict__ ctx)
{
    extern __shared__ float sm[];
    float* qs = sm;                       // [32][68]
    float* sc = sm + 32 * FA_QS;          // [32][516]
    float* kv = sc + 32 * FA_SS;          // [128][68] (K) / [128][72] (V)
    const uint32_t sbase = smem_u32(sm);

    const int tid = threadIdx.x;
    const int lane = tid & 31, wid = tid >> 5;
    const int g = lane >> 2, t4 = lane & 3;
    const int q0 = blockIdx.x * 32;
    const int bh = blockIdx.y;
    const int b = bh >> 3, h = bh & 7;
    const int wm = wid & 1;
    const int wn = wid >> 1;

    // ldmatrix lane addresses (element offsets; stride ≡ 16B mod 128B -> conflict-free)
    const uint32_t qa_addr = sbase +
        (uint32_t)((wm * 16 + (lane & 7) + (lane & 8)) * FA_QS + ((lane & 16) >> 2)) * 4;
    const uint32_t kb_addr = sbase + (uint32_t)(32 * FA_QS + 32 * FA_SS) * 4 +
        (uint32_t)((wn * 32 + ((lane & 16) >> 1) + (lane & 7)) * FA_KS + ((lane & 8) >> 1)) * 4;
    const uint32_t pa_addr = sbase + (uint32_t)(32 * FA_QS) * 4 +
        (uint32_t)((wm * 16 + (lane & 7) + (lane & 8)) * FA_SS + ((lane & 16) >> 2)) * 4;

    {
        const int r = tid >> 3;
        const int d0 = (tid & 7) * 8;
        const float* src = qkv + (size_t)(b * S_ + q0 + r) * 1536 + h * 64 + d0;
        const float4 v0 = *(const float4*)src;
        const float4 v1 = *(const float4*)(src + 4);
        float* dst = qs + r * FA_QS + d0;
        dst[0] = v0.x * 0.125f; dst[1] = v0.y * 0.125f;
        dst[2] = v0.z * 0.125f; dst[3] = v0.w * 0.125f;
        dst[4] = v1.x * 0.125f; dst[5] = v1.y * 0.125f;
        dst[6] = v1.z * 0.125f; dst[7] = v1.w * 0.125f;
    }

    for (int kt = 0; kt < 4; kt++) {
        __syncthreads();
#pragma unroll
        for (int i = 0; i < 4; i++) {
            const int idx = i * 256 + tid;
            const int r = idx >> 3;
            const int d0 = (idx & 7) * 8;
            const float* src = qkv + (size_t)(b * S_ + kt * 128 + r) * 1536 + D_ + h * 64 + d0;
            const float4 v0 = *(const float4*)src;
            const float4 v1 = *(const float4*)(src + 4);
            float* dst = kv + r * FA_KS + d0;
            dst[0] = v0.x; dst[1] = v0.y; dst[2] = v0.z; dst[3] = v0.w;
            dst[4] = v1.x; dst[5] = v1.y; dst[6] = v1.z; dst[7] = v1.w;
        }
        __syncthreads();

        float acc[4][4];
#pragma unroll
        for (int nt = 0; nt < 4; nt++)
#pragma unroll
            for (int j = 0; j < 4; j++) acc[nt][j] = 0.f;

#pragma unroll
        for (int ks = 0; ks < 8; ks++) {
            uint32_t afr[4];
            LDSM_X4(afr[0], afr[1], afr[2], afr[3], qa_addr + (uint32_t)(ks * 8) * 4);
            uint32_t bfr[4][2];
#pragma unroll
            for (int p = 0; p < 2; p++)
                LDSM_X4(bfr[2 * p][0], bfr[2 * p][1], bfr[2 * p + 1][0], bfr[2 * p + 1][1],
                        kb_addr + (uint32_t)(p * 16 * FA_KS + ks * 8) * 4);
#pragma unroll
            for (int nt = 0; nt < 4; nt++)
                mma_tf32(acc[nt], afr, bfr[nt]);
        }
#pragma unroll
        for (int nt = 0; nt < 4; nt++) {
            const int col = kt * 128 + wn * 32 + nt * 8 + 2 * t4;
            const int row = wm * 16 + g;
            *(float2*)&sc[row * FA_SS + col]       = make_float2(acc[nt][0], acc[nt][1]);
            *(float2*)&sc[(row + 8) * FA_SS + col] = make_float2(acc[nt][2], acc[nt][3]);
        }
    }
    __syncthreads();

#pragma unroll
    for (int rr = 0; rr < 4; rr++) {
        const int row = wid * 4 + rr;
        float vals[16];
        float sum = 0.f;
#pragma unroll
        for (int t = 0; t < 4; t++) {
            const float4 v = *(const float4*)&sc[row * FA_SS + lane * 4 + t * 128];
            vals[t * 4 + 0] = fast_exp(v.x);
            vals[t * 4 + 1] = fast_exp(v.y);
            vals[t * 4 + 2] = fast_exp(v.z);
            vals[t * 4 + 3] = fast_exp(v.w);
            sum += vals[t * 4 + 0] + vals[t * 4 + 1] + vals[t * 4 + 2] + vals[t * 4 + 3];
        }
#pragma unroll
        for (int o = 16; o > 0; o >>= 1)
            sum += __shfl_xor_sync(0xFFFFFFFFu, sum, o);
        const float inv = 1.f / sum;
        float* prow = probs + ((size_t)bh * S_ + q0 + row) * S_;
#pragma unroll
        for (int t = 0; t < 4; t++) {
            float4 o;
            o.x = tf32r(vals[t * 4 + 0] * inv);
            o.y = tf32r(vals[t * 4 + 1] * inv);
            o.z = tf32r(vals[t * 4 + 2] * inv);
            o.w = tf32r(vals[t * 4 + 3] * inv);
            *(float4*)&sc[row * FA_SS + lane * 4 + t * 128] = o;
            *(float4*)&prow[lane * 4 + t * 128] = o;
        }
    }

    float pacc[2][4];
#pragma unroll
    for (int nt = 0; nt < 2; nt++)
#pragma unroll
        for (int j = 0; j < 4; j++) pacc[nt][j] = 0.f;

    for (int vt = 0; vt < 4; vt++) {
        __syncthreads();
#pragma unroll
        for (int i = 0; i < 8; i++) {
            const int idx = i * 256 + tid;
            const int r = idx >> 4;
            const int d0 = (idx & 15) * 4;
            const float4 v = *(const float4*)&qkv[(size_t)(b * S_ + vt * 128 + r) * 1536 + 2 * D_ + h * 64 + d0];
            float* dst = kv + r * FA_VS + d0;
            dst[0] = v.x; dst[1] = v.y; dst[2] = v.z; dst[3] = v.w;
        }
        __syncthreads();

#pragma unroll
        for (int ks = 0; ks < 16; ks++) {
            uint32_t afr[4];
            LDSM_X4(afr[0], afr[1], afr[2], afr[3],
                    pa_addr + (uint32_t)(vt * 128 + ks * 8) * 4);
#pragma unroll
            for (int nt = 0; nt < 2; nt++) {
                const float* bp = kv + (ks * 8 + t4) * FA_VS + wn * 16 + nt * 8 + g;
                uint32_t bfr[2] = {FBITS(bp[0]), FBITS(bp[4 * FA_VS])};
                mma_tf32(pacc[nt], afr, bfr);
            }
        }
    }

#pragma unroll
    for (int nt = 0; nt < 2; nt++) {
        const int row = b * S_ + q0 + wm * 16 + g;
        const int col = h * 64 + wn * 16 + nt * 8 + 2 * t4;
        *(float2*)&ctx[(size_t)row * D_ + col] =
            make_float2(tf32r(pacc[nt][0]), tf32r(pacc[nt][1]));
        *(float2*)&ctx[(size_t)(row + 8) * D_ + col] =
            make_float2(tf32r(pacc[nt][2]), tf32r(pacc[nt][3]));
    }
}

// ---------------- SIMT GEMM (input proj / head1) ----------------
template <int ACT>   // 0=none, 1=GELU, 2=add PE table + tf32 round
__global__ __launch_bounds__(256)
void gemm_kernel(const float* __restrict__ A, const float* __restrict__ W,
                 const float* __restrict__ bias, float* __restrict__ C,
                 int M, int N, int K, const float* __restrict__ pe)
{
    __shared__ __align__(16) float As[8][128];
    __shared__ __align__(16) float Ws[8][128];

    const int tid = threadIdx.x;
    const int tx = tid & 15;
    const int ty = tid >> 4;
    const int m0 = blockIdx.y * 128;
    const int n0 = blockIdx.x * 128;

    float acc[2][2][4][4];
#pragma unroll
    for (int p = 0; p < 2; p++)
#pragma unroll
        for (int q = 0; q < 2; q++)
#pragma unroll
            for (int i = 0; i < 4; i++)
#pragma unroll
                for (int j = 0; j < 4; j++) acc[p][q][i][j] = 0.f;

    const int lr = tid >> 1;
    const int lk = (tid & 1) * 4;
    const float* Ag = A + (size_t)(m0 + lr) * K + lk;
    const float* Wg = W + (size_t)(n0 + lr) * K + lk;
    const bool aval = (m0 + lr) < M;

    for (int k0 = 0; k0 < K; k0 += 8) {
        float4 av = make_float4(0.f, 0.f, 0.f, 0.f);
        if (aval) av = *(const float4*)(Ag + k0);
        const float4 wv = *(const float4*)(Wg + k0);
        __syncthreads();
        As[lk + 0][lr] = av.x; As[lk + 1][lr] = av.y;
        As[lk + 2][lr] = av.z; As[lk + 3][lr] = av.w;
        Ws[lk + 0][lr] = wv.x; Ws[lk + 1][lr] = wv.y;
        Ws[lk + 2][lr] = wv.z; Ws[lk + 3][lr] = wv.w;
        __syncthreads();
#pragma unroll
        for (int kk = 0; kk < 8; kk++) {
            const float4 a0 = *(const float4*)&As[kk][ty * 4];
            const float4 a1 = *(const float4*)&As[kk][64 + ty * 4];
            const float4 b0 = *(const float4*)&Ws[kk][tx * 4];
            const float4 b1 = *(const float4*)&Ws[kk][64 + tx * 4];
            const float ar[2][4] = {{a0.x, a0.y, a0.z, a0.w}, {a1.x, a1.y, a1.z, a1.w}};
            const float br[2][4] = {{b0.x, b0.y, b0.z, b0.w}, {b1.x, b1.y, b1.z, b1.w}};
#pragma unroll
            for (int p = 0; p < 2; p++)
#pragma unroll
                for (int q = 0; q < 2; q++)
#pragma unroll
                    for (int i = 0; i < 4; i++)
#pragma unroll
                        for (int j = 0; j < 4; j++)
                            acc[p][q][i][j] += ar[p][i] * br[q][j];
        }
    }

#pragma unroll
    for (int p = 0; p < 2; p++) {
#pragma unroll
        for (int i = 0; i < 4; i++) {
            const int m = m0 + p * 64 + ty * 4 + i;
            if (m >= M) continue;
#pragma unroll
            for (int q = 0; q < 2; q++) {
                const int c = n0 + q * 64 + tx * 4;
                float4 o;
                float* po = &o.x;
#pragma unroll
                for (int j = 0; j < 4; j++) {
                    float v = acc[p][q][i][j] + bias[c + j];
                    if (ACT == 1) {
                        v = gelu_exact(v);
                    } else if (ACT == 2) {
                        v += pe[(m & (S_ - 1)) * D_ + c + j];
                        v = tf32r(v);
                    }
                    po[j] = v;
                }
                *(float4*)&C[(size_t)m * N + c] = o;
            }
        }
    }
}

// ---------------- fused residual-add + LayerNorm (tf32-rounded output) ----------------
__global__ __launch_bounds__(128)
void ln_kernel(const float* __restrict__ x, const float* __restrict__ add,
               const float* __restrict__ w, const float* __restrict__ bvec,
               float* __restrict__ out)
{
    const int row = blockIdx.x;
    const int tid = threadIdx.x;
    const float* xr = x + (size_t)row * D_;
    const float* ar = add + (size_t)row * D_;
    float v[4];
    float s = 0.f;
#pragma unroll
    for (int i = 0; i < 4; i++) {
        const int c = tid + i * 128;
        v[i] = xr[c] + ar[c];
        s += v[i];
    }
    __shared__ float red[4];
#pragma unroll
    for (int o = 16; o > 0; o >>= 1) s += __shfl_xor_sync(0xFFFFFFFFu, s, o);
    if ((tid & 31) == 0) red[tid >> 5] = s;
    __syncthreads();
    const float mean = (red[0] + red[1] + red[2] + red[3]) * (1.f / 512.f);
    float vs = 0.f;
#pragma unroll
    for (int i = 0; i < 4; i++) {
        const float d = v[i] - mean;
        vs += d * d;
    }
    __syncthreads();
#pragma unroll
    for (int o = 16; o > 0; o >>= 1) vs += __shfl_xor_sync(0xFFFFFFFFu, vs, o);
    if ((tid & 31) == 0) red[tid >> 5] = vs;
    __syncthreads();
    const float rstd = rsqrtf((red[0] + red[1] + red[2] + red[3]) * (1.f / 512.f) + 1e-5f);
    float* orow = out + (size_t)row * D_;
#pragma unroll
    for (int i = 0; i < 4; i++) {
        const int c = tid + i * 128;
        orow[c] = tf32r((v[i] - mean) * rstd * w[c] + bvec[c]);
    }
}

// ---------------- mean+max pooling over sequence ----------------
__global__ __launch_bounds__(512)
void pool_kernel(const float* __restrict__ x, float* __restrict__ pool)
{
    const int b = blockIdx.x, d = threadIdx.x;
    float s = 0.f, m = -1e30f;
    for (int t = 0; t < S_; t++) {
        const float v = x[(size_t)(b * S_ + t) * D_ + d];
        s += v;
        m = fmaxf(m, v);
    }
    pool[b * (2 * D_) + d] = s * (1.f / 512.f);
    pool[b * (2 * D_) + D_ + d] = m;
}

// ---------------- final head ----------------
__global__ __launch_bounds__(128)
void head2_kernel(const float* __restrict__ h, const float* __restrict__ w,
                  const float* __restrict__ bb, float* __restrict__ out)
{
    const int b = blockIdx.x, tid = threadIdx.x;
    float s = 0.f;
    for (int c = tid; c < D_; c += 128) s += h[(size_t)b * D_ + c] * w[c];
    __shared__ float red[4];
#pragma unroll
    for (int o = 16; o > 0; o >>= 1) s += __shfl_xor_sync(0xFFFFFFFFu, s, o);
    if ((tid & 31) == 0) red[tid >> 5] = s;
    __syncthreads();
    if (tid == 0) out[b] = red[0] + red[1] + red[2] + red[3] + bb[0];
}

// ---------------- launch ----------------
extern "C" void kernel_launch(void* const* d_in, const int* in_sizes, int n_in,
                              void* d_out, int out_size)
{
    const float* x_in = (const float*)d_in[0];
    const float* w_in = (const float*)d_in[1];
    const float* b_in = (const float*)d_in[2];
    const float* inpw = (const float*)d_in[3];
    const float* inpb = (const float*)d_in[4];
    const float* outw = (const float*)d_in[5];
    const float* outb = (const float*)d_in[6];
    const float* ln1w = (const float*)d_in[7];
    const float* ln1b = (const float*)d_in[8];
    const float* ln2w = (const float*)d_in[9];
    const float* ln2b = (const float*)d_in[10];
    const float* ff1w = (const float*)d_in[11];
    const float* ff1b = (const float*)d_in[12];
    const float* ff2w = (const float*)d_in[13];
    const float* ff2b = (const float*)d_in[14];
    const float* h1w  = (const float*)d_in[15];
    const float* h1b  = (const float*)d_in[16];
    const float* h2w  = (const float*)d_in[17];
    const float* h2b  = (const float*)d_in[18];

    float* out  = (float*)d_out;
    float* attn = out + 32;   // [L,B,H,S,S] follows the [B,1] output

    float *px, *pqkv, *pctx, *ptmp, *pff, *ppool, *phead, *pwb, *ppe;
    cudaGetSymbolAddress((void**)&px,    g_x);
    cudaGetSymbolAddress((void**)&pqkv,  g_qkv);
    cudaGetSymbolAddress((void**)&pctx,  g_ctx);
    cudaGetSymbolAddress((void**)&ptmp,  g_tmp);
    cudaGetSymbolAddress((void**)&pff,   g_ff);
    cudaGetSymbolAddress((void**)&ppool, g_pool);
    cudaGetSymbolAddress((void**)&phead, g_head);
    cudaGetSymbolAddress((void**)&pwb,   g_wbuf);
    cudaGetSymbolAddress((void**)&ppe,   g_pe);

    cudaFuncSetAttribute(gemm_mma<0,1>, cudaFuncAttributeMaxDynamicSharedMemorySize, MM_SMEM);
    cudaFuncSetAttribute(gemm_mma<0,0>, cudaFuncAttributeMaxDynamicSharedMemorySize, MM_SMEM);
    cudaFuncSetAttribute(gemm_mma<1,1>, cudaFuncAttributeMaxDynamicSharedMemorySize, MM_SMEM);
    cudaFuncSetAttribute(fused_attn, cudaFuncAttributeMaxDynamicSharedMemorySize, FA_SMEM_BYTES);

    const dim3 blk(256);
    const dim3 mblk(128);

    // per-replay setup: ONE merged tf32-rounding launch + PE table
    round_all<<<WB_TOT / 1024, 256>>>(inpw, outw, ff1w, ff2w, pwb);
    pe_init<<<(S_ * D_) / 256, 256>>>(ppe);

    // input projection + PE table (SIMT, output tf32-rounded)
    gemm_kernel<2><<<dim3(D_ / 128, TOK_ / 128), blk>>>(x_in, w_in, b_in, px, TOK_, D_, IN_, ppe);

    for (int l = 0; l < L_; l++) {
        // QKV projection (output rounded: feeds attention mma)
        gemm_mma<0,1><<<dim3((3 * D_) / 128, TOK_ / 128), mblk, MM_SMEM>>>(
            px, pwb + WB_IN + (size_t)l * 3 * D_ * D_, inpb + l * 3 * D_, pqkv, TOK_, 3 * D_, D_);

        float* attn_l = attn + (size_t)l * B_ * H_ * S_ * S_;

        // fused scores + softmax + probs-out + P@V
        fused_attn<<<dim3(S_ / 32, B_ * H_), blk, FA_SMEM_BYTES>>>(pqkv, attn_l, pctx);

        // output projection (feeds LN: no rounding)
        gemm_mma<0,0><<<dim3(D_ / 128, TOK_ / 128), mblk, MM_SMEM>>>(
            pctx, pwb + WB_OUT + (size_t)l * D_ * D_, outb + l * D_, ptmp, TOK_, D_, D_);

        ln_kernel<<<TOK_, 128>>>(px, ptmp, ln1w + l * D_, ln1b + l * D_, px);

        // ff1 + GELU (output rounded: feeds ff2 mma)
        gemm_mma<1,1><<<dim3(FF_ / 128, TOK_ / 128), mblk, MM_SMEM>>>(
            px, pwb + WB_FF1 + (size_t)l * FF_ * D_, ff1b + l * FF_, pff, TOK_, FF_, D_);

        // ff2 (feeds LN: no rounding)
        gemm_mma<0,0><<<dim3(D_ / 128, TOK_ / 128), mblk, MM_SMEM>>>(
            pff, pwb + WB_FF2 + (size_t)l * D_ * FF_, ff2b + l * D_, ptmp, TOK_, D_, FF_);

        ln_kernel<<<TOK_, 128>>>(px, ptmp, ln2w + l * D_, ln2b + l * D_, px);
    }

    pool_kernel<<<B_, 512>>>(px, ppool);
    gemm_kernel<1><<<dim3(D_ / 128, 1), blk>>>(ppool, h1w, h1b, phead, B_, D_, 2 * D_, ppe);
    head2_kernel<<<B_, 128>>>(phead, h2w, h2b, out);
}

// round 14
// speedup vs baseline: 4.5547x; 1.3839x over previous
#include <cuda_runtime.h>
#include <cuda_fp16.h>
#include <cstdint>
#include <math.h>

#define B_   32
#define S_   512
#define IN_  64
#define D_   512
#define H_   8
#define L_   4
#define FF_  2048
#define TOK_ (B_ * S_)   // 16384

// ---------------- scratch (device globals; no allocation allowed) ----------------
__device__ __align__(16) float  g_x[TOK_ * D_];          // fp32 residual stream
__device__ __align__(16) __half g_xh[TOK_ * D_];         // fp16 copy (GEMM input)
__device__ __align__(16) float  g_qkv[TOK_ * 3 * D_];    // fp32 (attention input)
__device__ __align__(16) __half g_ctxh[TOK_ * D_];       // fp16 ctx (out_proj input)
__device__ __align__(16) float  g_tmp[TOK_ * D_];        // fp32 GEMM outputs -> LN
__device__ __align__(16) __half g_ffh[TOK_ * FF_];       // fp16 GELU out (ff2 input)
__device__ __align__(16) float  g_pool[B_ * 2 * D_];
__device__ __align__(16) float  g_head[B_ * D_];
__device__ __align__(16) float  g_pe[S_ * D_];
// fp16 weights: [in_proj | out_proj | ff1 | ff2]
#define WB_IN  0
#define WB_OUT (WB_IN  + L_ * 3 * D_ * D_)
#define WB_FF1 (WB_OUT + L_ * D_ * D_)
#define WB_FF2 (WB_FF1 + L_ * FF_ * D_)
#define WB_TOT (WB_FF2 + L_ * D_ * FF_)
__device__ __align__(16) __half g_wbufh[WB_TOT];

__device__ __forceinline__ float gelu_exact(float v) {
    return 0.5f * v * (1.0f + erff(v * 0.7071067811865475f));
}
__device__ __forceinline__ float tf32r(float f) {
    uint32_t u;
    asm("cvt.rna.tf32.f32 %0, %1;" : "=r"(u) : "f"(f));
    return __uint_as_float(u);
}
__device__ __forceinline__ float fast_exp(float x) {
    float y = x * 1.442695041f;
    float z = y + 12582912.f;
    float k = z - 12582912.f;
    float f = y - k;
    float p = 1.3333558e-3f;
    p = fmaf(p, f, 9.6181291e-3f);
    p = fmaf(p, f, 5.5504109e-2f);
    p = fmaf(p, f, 2.4022651e-1f);
    p = fmaf(p, f, 6.9314718e-1f);
    p = fmaf(p, f, 1.0f);
    int ki = (__float_as_int(z) - 0x4B400000) << 23;
    return __int_as_float(__float_as_int(p) + ki);
}
__device__ __forceinline__ uint32_t smem_u32(const void* p) {
    uint32_t a;
    asm("{ .reg .u64 t; cvta.to.shared.u64 t, %1; cvt.u32.u64 %0, t; }" : "=r"(a) : "l"(p));
    return a;
}
// non-volatile: lets compiler interleave HMMA with next ldmatrix
__device__ __forceinline__ void mma_tf32(float* c, const uint32_t* a, const uint32_t* b) {
    asm("mma.sync.aligned.m16n8k8.row.col.f32.tf32.tf32.f32 "
        "{%0,%1,%2,%3}, {%4,%5,%6,%7}, {%8,%9}, {%0,%1,%2,%3};"
        : "+f"(c[0]), "+f"(c[1]), "+f"(c[2]), "+f"(c[3])
        : "r"(a[0]), "r"(a[1]), "r"(a[2]), "r"(a[3]), "r"(b[0]), "r"(b[1]));
}
__device__ __forceinline__ void mma_f16(float* c, const uint32_t* a, const uint32_t* b) {
    asm("mma.sync.aligned.m16n8k16.row.col.f32.f16.f16.f32 "
        "{%0,%1,%2,%3}, {%4,%5,%6,%7}, {%8,%9}, {%0,%1,%2,%3};"
        : "+f"(c[0]), "+f"(c[1]), "+f"(c[2]), "+f"(c[3])
        : "r"(a[0]), "r"(a[1]), "r"(a[2]), "r"(a[3]), "r"(b[0]), "r"(b[1]));
}
#define FBITS(x) __float_as_uint(x)
#define LDSM_X4(r0, r1, r2, r3, addr) \
    asm volatile("ldmatrix.sync.aligned.m8n8.x4.shared.b16 {%0,%1,%2,%3}, [%4];" \
        : "=r"(r0), "=r"(r1), "=r"(r2), "=r"(r3) : "r"(addr))

// ---------------- fp16 conversion of ALL weights (one launch) ----------------
__global__ __launch_bounds__(256)
void round_all(const float* __restrict__ w_in, const float* __restrict__ w_out,
               const float* __restrict__ w_ff1, const float* __restrict__ w_ff2,
               __half* __restrict__ dst)
{
    const int i = (blockIdx.x * 256 + threadIdx.x) * 4;
    if (i >= WB_TOT) return;
    const float* src;
    int off;
    if (i < WB_OUT)      { src = w_in;  off = i - WB_IN;  }
    else if (i < WB_FF1) { src = w_out; off = i - WB_OUT; }
    else if (i < WB_FF2) { src = w_ff1; off = i - WB_FF1; }
    else                 { src = w_ff2; off = i - WB_FF2; }
    const float4 v = *(const float4*)(src + off);
    __half2* d = (__half2*)(dst + i);
    d[0] = __floats2half2_rn(v.x, v.y);
    d[1] = __floats2half2_rn(v.z, v.w);
}

// ---------------- positional encoding table (once per replay) ----------------
__global__ __launch_bounds__(256)
void pe_init(float* __restrict__ pe)
{
    const int i = blockIdx.x * 256 + threadIdx.x;
    const int s = i >> 9;
    const int d = i & (D_ - 1);
    const float freq = expf(-9.210340371976184f * (float)(d & ~1) / (float)D_);
    const float ang = (float)s * freq;
    pe[i] = (d & 1) ? cosf(ang) : sinf(ang);
}

// ======================= fp16 mma.sync GEMM =======================
// C[M,N] = act(A[M,K] * W[N,K]^T + bias), A/W fp16, accum fp32.
// M%128==0, N%128==0, K%32==0, K>=96. 128x128x32 CTA tile, 128 thr (4 warps 2x2),
// warp tile 64x64 = 4mt x 8nt of m16n8k16. 3-buffer/2-prefetch cp.async, 1 barrier/chunk.
#define MH_RS     40                      // halves per row (32 data + 8 pad)
#define MH_TILEB  (128 * MH_RS * 2)       // 10240 B per operand
#define MH_STAGE  (2 * MH_TILEB)          // 20480 B per stage
#define MH_NST    3
#define MH_SMEM   (MH_NST * MH_STAGE)     // 61440 B

__device__ __forceinline__ void mh_cp_issue(
    const __half* __restrict__ A, const __half* __restrict__ W,
    uint32_t sbase, int stage, int m0, int n0, int K, int k0, int tid)
{
    const uint32_t as = sbase + stage * MH_STAGE;
    const uint32_t bs = as + MH_TILEB;
#pragma unroll
    for (int i = 0; i < 4; i++) {
        const int idx = i * 128 + tid;      // 0..511
        const int row = idx >> 2;
        const int q = idx & 3;
        const uint32_t so = (uint32_t)(row * (MH_RS * 2) + q * 16);
        const __half* ga = A + (size_t)(m0 + row) * K + k0 + q * 8;
        const __half* gw = W + (size_t)(n0 + row) * K + k0 + q * 8;
        asm volatile("cp.async.cg.shared.global [%0], [%1], 16;" :: "r"(as + so), "l"(ga));
        asm volatile("cp.async.cg.shared.global [%0], [%1], 16;" :: "r"(bs + so), "l"(gw));
    }
    asm volatile("cp.async.commit_group;" ::: "memory");
}

// ACT: 0=none, 1=exact GELU.  OUT: 0=fp32 raw, 1=fp32 tf32-rounded, 2=fp16
template <int ACT, int OUT>
__global__ __launch_bounds__(128, 2)
void gemm_h(const __half* __restrict__ A, const __half* __restrict__ W,
            const float* __restrict__ bias, float* __restrict__ C,
            __half* __restrict__ CH, int M, int N, int K)
{
    extern __shared__ char smem[];
    const uint32_t sbase = smem_u32(smem);
    const int tid = threadIdx.x;
    const int lane = tid & 31, wid = tid >> 5;
    const int g = lane >> 2, t4 = lane & 3;
    const int wm = wid & 1;
    const int wn = wid >> 1;
    const int m0 = blockIdx.y * 128, n0 = blockIdx.x * 128;

    // ldmatrix lane addresses (in halves):
    // A x4: mats (rows0-7,k0-7),(rows8-15,k0-7),(rows0-7,k8-15),(rows8-15,k8-15)
    const uint32_t a_lane = (uint32_t)((wm * 64 + (lane & 7) + (lane & 8)) * MH_RS
                                       + ((lane & 16) >> 1));
    // B x4 per nt-pair p: (n0-7,k0-7),(n0-7,k8-15),(n8-15,k0-7),(n8-15,k8-15)
    const uint32_t b_lane = (uint32_t)((wn * 64 + ((lane & 16) >> 1) + (lane & 7)) * MH_RS
                                       + (lane & 8));

    float acc[4][8][4];
#pragma unroll
    for (int mt = 0; mt < 4; mt++)
#pragma unroll
        for (int nt = 0; nt < 8; nt++)
#pragma unroll
            for (int j = 0; j < 4; j++) acc[mt][nt][j] = 0.f;

    const int nch = K >> 5;
    mh_cp_issue(A, W, sbase, 0, m0, n0, K, 0, tid);
    mh_cp_issue(A, W, sbase, 1, m0, n0, K, 32, tid);

    int cur = 0;
    for (int c = 0; c < nch; c++) {
        if (c + 1 < nch)
            asm volatile("cp.async.wait_group 1;" ::: "memory");
        else
            asm volatile("cp.async.wait_group 0;" ::: "memory");
        __syncthreads();

        const uint32_t a_base = sbase + cur * MH_STAGE + a_lane * 2;
        const uint32_t b_base = sbase + cur * MH_STAGE + MH_TILEB + b_lane * 2;

#pragma unroll
        for (int ks = 0; ks < 2; ks++) {      // two k16 steps per 32-chunk
            uint32_t afr[4][4];
#pragma unroll
            for (int mt = 0; mt < 4; mt++)
                LDSM_X4(afr[mt][0], afr[mt][1], afr[mt][2], afr[mt][3],
                        a_base + (uint32_t)(mt * 16 * MH_RS + ks * 16) * 2);
            uint32_t bfr[8][2];
#pragma unroll
            for (int p = 0; p < 4; p++)
                LDSM_X4(bfr[2 * p][0], bfr[2 * p][1], bfr[2 * p + 1][0], bfr[2 * p + 1][1],
                        b_base + (uint32_t)(p * 16 * MH_RS + ks * 16) * 2);
#pragma unroll
            for (int mt = 0; mt < 4; mt++)
#pragma unroll
                for (int nt = 0; nt < 8; nt++)
                    mma_f16(acc[mt][nt], afr[mt], bfr[nt]);
        }
        if (c + 2 < nch) {
            int tgt = cur + 2; if (tgt >= 3) tgt -= 3;
            mh_cp_issue(A, W, sbase, tgt, m0, n0, K, (c + 2) * 32, tid);
        }
        cur = (cur == 2) ? 0 : cur + 1;
    }

#pragma unroll
    for (int mt = 0; mt < 4; mt++) {
        const int r0 = m0 + wm * 64 + mt * 16 + g;
#pragma unroll
        for (int nt = 0; nt < 8; nt++) {
            const int cb = n0 + wn * 64 + nt * 8 + 2 * t4;
            const float b0 = bias[cb], b1 = bias[cb + 1];
            float v0 = acc[mt][nt][0] + b0;
            float v1 = acc[mt][nt][1] + b1;
            float v2 = acc[mt][nt][2] + b0;
            float v3 = acc[mt][nt][3] + b1;
            if (ACT == 1) {
                v0 = gelu_exact(v0); v1 = gelu_exact(v1);
                v2 = gelu_exact(v2); v3 = gelu_exact(v3);
            }
            if (OUT == 2) {
                *(__half2*)&CH[(size_t)r0 * N + cb]       = __floats2half2_rn(v0, v1);
                *(__half2*)&CH[(size_t)(r0 + 8) * N + cb] = __floats2half2_rn(v2, v3);
            } else {
                if (OUT == 1) {
                    v0 = tf32r(v0); v1 = tf32r(v1); v2 = tf32r(v2); v3 = tf32r(v3);
                }
                *(float2*)&C[(size_t)r0 * N + cb]       = make_float2(v0, v1);
                *(float2*)&C[(size_t)(r0 + 8) * N + cb] = make_float2(v2, v3);
            }
        }
    }
}

// ======================= fused attention (tf32, unchanged math) =======================
#define FA_QS 68
#define FA_SS 516
#define FA_KS 68
#define FA_VS 72
#define FA_SMEM_FLOATS (32 * FA_QS + 32 * FA_SS + 128 * FA_VS)
#define FA_SMEM_BYTES  (FA_SMEM_FLOATS * 4)     // 111616

__global__ __launch_bounds__(256, 2)
void fused_attn(const float* __restrict__ qkv, float* __restrict__ probs,
                __half* __restrict__ ctxh)
{
    extern __shared__ float sm[];
    float* qs = sm;
    float* sc = sm + 32 * FA_QS;
    float* kv = sc + 32 * FA_SS;
    const uint32_t sbase = smem_u32(sm);

    const int tid = threadIdx.x;
    const int lane = tid & 31, wid = tid >> 5;
    const int g = lane >> 2, t4 = lane & 3;
    const int q0 = blockIdx.x * 32;
    const int bh = blockIdx.y;
    const int b = bh >> 3, h = bh & 7;
    const int wm = wid & 1;
    const int wn = wid >> 1;

    const uint32_t qa_addr = sbase +
        (uint32_t)((wm * 16 + (lane & 7) + (lane & 8)) * FA_QS + ((lane & 16) >> 2)) * 4;
    const uint32_t kb_addr = sbase + (uint32_t)(32 * FA_QS + 32 * FA_SS) * 4 +
        (uint32_t)((wn * 32 + ((lane & 16) >> 1) + (lane & 7)) * FA_KS + ((lane & 8) >> 1)) * 4;
    const uint32_t pa_addr = sbase + (uint32_t)(32 * FA_QS) * 4 +
        (uint32_t)((wm * 16 + (lane & 7) + (lane & 8)) * FA_SS + ((lane & 16) >> 2)) * 4;

    {
        const int r = tid >> 3;
        const int d0 = (tid & 7) * 8;
        const float* src = qkv + (size_t)(b * S_ + q0 + r) * 1536 + h * 64 + d0;
        const float4 v0 = *(const float4*)src;
        const float4 v1 = *(const float4*)(src + 4);
        float* dst = qs + r * FA_QS + d0;
        dst[0] = v0.x * 0.125f; dst[1] = v0.y * 0.125f;
        dst[2] = v0.z * 0.125f; dst[3] = v0.w * 0.125f;
        dst[4] = v1.x * 0.125f; dst[5] = v1.y * 0.125f;
        dst[6] = v1.z * 0.125f; dst[7] = v1.w * 0.125f;
    }

    for (int kt = 0; kt < 4; kt++) {
        __syncthreads();
#pragma unroll
        for (int i = 0; i < 4; i++) {
            const int idx = i * 256 + tid;
            const int r = idx >> 3;
            const int d0 = (idx & 7) * 8;
            const float* src = qkv + (size_t)(b * S_ + kt * 128 + r) * 1536 + D_ + h * 64 + d0;
            const float4 v0 = *(const float4*)src;
            const float4 v1 = *(const float4*)(src + 4);
            float* dst = kv + r * FA_KS + d0;
            dst[0] = v0.x; dst[1] = v0.y; dst[2] = v0.z; dst[3] = v0.w;
            dst[4] = v1.x; dst[5] = v1.y; dst[6] = v1.z; dst[7] = v1.w;
        }
        __syncthreads();

        float acc[4][4];
#pragma unroll
        for (int nt = 0; nt < 4; nt++)
#pragma unroll
            for (int j = 0; j < 4; j++) acc[nt][j] = 0.f;

#pragma unroll
        for (int ks = 0; ks < 8; ks++) {
            uint32_t afr[4];
            LDSM_X4(afr[0], afr[1], afr[2], afr[3], qa_addr + (uint32_t)(ks * 8) * 4);
            uint32_t bfr[4][2];
#pragma unroll
            for (int p = 0; p < 2; p++)
                LDSM_X4(bfr[2 * p][0], bfr[2 * p][1], bfr[2 * p + 1][0], bfr[2 * p + 1][1],
                        kb_addr + (uint32_t)(p * 16 * FA_KS + ks * 8) * 4);
#pragma unroll
            for (int nt = 0; nt < 4; nt++)
                mma_tf32(acc[nt], afr, bfr[nt]);
        }
#pragma unroll
        for (int nt = 0; nt < 4; nt++) {
            const int col = kt * 128 + wn * 32 + nt * 8 + 2 * t4;
            const int row = wm * 16 + g;
            *(float2*)&sc[row * FA_SS + col]       = make_float2(acc[nt][0], acc[nt][1]);
            *(float2*)&sc[(row + 8) * FA_SS + col] = make_float2(acc[nt][2], acc[nt][3]);
        }
    }
    __syncthreads();

#pragma unroll
    for (int rr = 0; rr < 4; rr++) {
        const int row = wid * 4 + rr;
        float vals[16];
        float sum = 0.f;
#pragma unroll
        for (int t = 0; t < 4; t++) {
            const float4 v = *(const float4*)&sc[row * FA_SS + lane * 4 + t * 128];
            vals[t * 4 + 0] = fast_exp(v.x);
            vals[t * 4 + 1] = fast_exp(v.y);
            vals[t * 4 + 2] = fast_exp(v.z);
            vals[t * 4 + 3] = fast_exp(v.w);
            sum += vals[t * 4 + 0] + vals[t * 4 + 1] + vals[t * 4 + 2] + vals[t * 4 + 3];
        }
#pragma unroll
        for (int o = 16; o > 0; o >>= 1)
            sum += __shfl_xor_sync(0xFFFFFFFFu, sum, o);
        const float inv = 1.f / sum;
        float* prow = probs + ((size_t)bh * S_ + q0 + row) * S_;
#pragma unroll
        for (int t = 0; t < 4; t++) {
            float4 o;
            o.x = tf32r(vals[t * 4 + 0] * inv);
            o.y = tf32r(vals[t * 4 + 1] * inv);
            o.z = tf32r(vals[t * 4 + 2] * inv);
            o.w = tf32r(vals[t * 4 + 3] * inv);
            *(float4*)&sc[row * FA_SS + lane * 4 + t * 128] = o;
            *(float4*)&prow[lane * 4 + t * 128] = o;
        }
    }

    float pacc[2][4];
#pragma unroll
    for (int nt = 0; nt < 2; nt++)
#pragma unroll
        for (int j = 0; j < 4; j++) pacc[nt][j] = 0.f;

    for (int vt = 0; vt < 4; vt++) {
        __syncthreads();
#pragma unroll
        for (int i = 0; i < 8; i++) {
            const int idx = i * 256 + tid;
            const int r = idx >> 4;
            const int d0 = (idx & 15) * 4;
            const float4 v = *(const float4*)&qkv[(size_t)(b * S_ + vt * 128 + r) * 1536 + 2 * D_ + h * 64 + d0];
            float* dst = kv + r * FA_VS + d0;
            dst[0] = v.x; dst[1] = v.y; dst[2] = v.z; dst[3] = v.w;
        }
        __syncthreads();

#pragma unroll
        for (int ks = 0; ks < 16; ks++) {
            uint32_t afr[4];
            LDSM_X4(afr[0], afr[1], afr[2], afr[3],
                    pa_addr + (uint32_t)(vt * 128 + ks * 8) * 4);
#pragma unroll
            for (int nt = 0; nt < 2; nt++) {
                const float* bp = kv + (ks * 8 + t4) * FA_VS + wn * 16 + nt * 8 + g;
                uint32_t bfr[2] = {FBITS(bp[0]), FBITS(bp[4 * FA_VS])};
                mma_tf32(pacc[nt], afr, bfr);
            }
        }
    }

    // ctx -> fp16 (out_proj GEMM input)
#pragma unroll
    for (int nt = 0; nt < 2; nt++) {
        const int row = b * S_ + q0 + wm * 16 + g;
        const int col = h * 64 + wn * 16 + nt * 8 + 2 * t4;
        *(__half2*)&ctxh[(size_t)row * D_ + col] =
            __floats2half2_rn(pacc[nt][0], pacc[nt][1]);
        *(__half2*)&ctxh[(size_t)(row + 8) * D_ + col] =
            __floats2half2_rn(pacc[nt][2], pacc[nt][3]);
    }
}

// ---------------- SIMT GEMM (input proj / head1) ----------------
// ACT: 1=GELU (head1), 2=add PE table, write fp32 + fp16 copy (input proj)
template <int ACT>
__global__ __launch_bounds__(256)
void gemm_kernel(const float* __restrict__ A, const float* __restrict__ W,
                 const float* __restrict__ bias, float* __restrict__ C,
                 __half* __restrict__ CH,
                 int M, int N, int K, const float* __restrict__ pe)
{
    __shared__ __align__(16) float As[8][128];
    __shared__ __align__(16) float Ws[8][128];

    const int tid = threadIdx.x;
    const int tx = tid & 15;
    const int ty = tid >> 4;
    const int m0 = blockIdx.y * 128;
    const int n0 = blockIdx.x * 128;

    float acc[2][2][4][4];
#pragma unroll
    for (int p = 0; p < 2; p++)
#pragma unroll
        for (int q = 0; q < 2; q++)
#pragma unroll
            for (int i = 0; i < 4; i++)
#pragma unroll
                for (int j = 0; j < 4; j++) acc[p][q][i][j] = 0.f;

    const int lr = tid >> 1;
    const int lk = (tid & 1) * 4;
    const float* Ag = A + (size_t)(m0 + lr) * K + lk;
    const float* Wg = W + (size_t)(n0 + lr) * K + lk;
    const bool aval = (m0 + lr) < M;

    for (int k0 = 0; k0 < K; k0 += 8) {
        float4 av = make_float4(0.f, 0.f, 0.f, 0.f);
        if (aval) av = *(const float4*)(Ag + k0);
        const float4 wv = *(const float4*)(Wg + k0);
        __syncthreads();
        As[lk + 0][lr] = av.x; As[lk + 1][lr] = av.y;
        As[lk + 2][lr] = av.z; As[lk + 3][lr] = av.w;
        Ws[lk + 0][lr] = wv.x; Ws[lk + 1][lr] = wv.y;
        Ws[lk + 2][lr] = wv.z; Ws[lk + 3][lr] = wv.w;
        __syncthreads();
#pragma unroll
        for (int kk = 0; kk < 8; kk++) {
            const float4 a0 = *(const float4*)&As[kk][ty * 4];
            const float4 a1 = *(const float4*)&As[kk][64 + ty * 4];
            const float4 b0 = *(const float4*)&Ws[kk][tx * 4];
            const float4 b1 = *(const float4*)&Ws[kk][64 + tx * 4];
            const float ar[2][4] = {{a0.x, a0.y, a0.z, a0.w}, {a1.x, a1.y, a1.z, a1.w}};
            const float br[2][4] = {{b0.x, b0.y, b0.z, b0.w}, {b1.x, b1.y, b1.z, b1.w}};
#pragma unroll
            for (int p = 0; p < 2; p++)
#pragma unroll
                for (int q = 0; q < 2; q++)
#pragma unroll
                    for (int i = 0; i < 4; i++)
#pragma unroll
                        for (int j = 0; j < 4; j++)
                            acc[p][q][i][j] += ar[p][i] * br[q][j];
        }
    }

#pragma unroll
    for (int p = 0; p < 2; p++) {
#pragma unroll
        for (int i = 0; i < 4; i++) {
            const int m = m0 + p * 64 + ty * 4 + i;
            if (m >= M) continue;
#pragma unroll
            for (int q = 0; q < 2; q++) {
                const int c = n0 + q * 64 + tx * 4;
                float4 o;
                float* po = &o.x;
#pragma unroll
                for (int j = 0; j < 4; j++) {
                    float v = acc[p][q][i][j] + bias[c + j];
                    if (ACT == 1) {
                        v = gelu_exact(v);
                    } else if (ACT == 2) {
                        v += pe[(m & (S_ - 1)) * D_ + c + j];
                    }
                    po[j] = v;
                }
                *(float4*)&C[(size_t)m * N + c] = o;
                if (ACT == 2) {
                    __half2* hd = (__half2*)&CH[(size_t)m * N + c];
                    hd[0] = __floats2half2_rn(o.x, o.y);
                    hd[1] = __floats2half2_rn(o.z, o.w);
                }
            }
        }
    }
}

// ---------------- fused residual-add + LayerNorm (fp32 + fp16 outputs) ----------------
__global__ __launch_bounds__(128)
void ln_kernel(const float* __restrict__ x, const float* __restrict__ add,
               const float* __restrict__ w, const float* __restrict__ bvec,
               float* __restrict__ out, __half* __restrict__ outh)
{
    const int row = blockIdx.x;
    const int tid = threadIdx.x;
    const float* xr = x + (size_t)row * D_;
    const float* ar = add + (size_t)row * D_;
    float v[4];
    float s = 0.f;
#pragma unroll
    for (int i = 0; i < 4; i++) {
        const int c = tid + i * 128;
        v[i] = xr[c] + ar[c];
        s += v[i];
    }
    __shared__ float red[4];
#pragma unroll
    for (int o = 16; o > 0; o >>= 1) s += __shfl_xor_sync(0xFFFFFFFFu, s, o);
    if ((tid & 31) == 0) red[tid >> 5] = s;
    __syncthreads();
    const float mean = (red[0] + red[1] + red[2] + red[3]) * (1.f / 512.f);
    float vs = 0.f;
#pragma unroll
    for (int i = 0; i < 4; i++) {
        const float d = v[i] - mean;
        vs += d * d;
    }
    __syncthreads();
#pragma unroll
    for (int o = 16; o > 0; o >>= 1) vs += __shfl_xor_sync(0xFFFFFFFFu, vs, o);
    if ((tid & 31) == 0) red[tid >> 5] = vs;
    __syncthreads();
    const float rstd = rsqrtf((red[0] + red[1] + red[2] + red[3]) * (1.f / 512.f) + 1e-5f);
    float* orow = out + (size_t)row * D_;
    __half* hrow = outh + (size_t)row * D_;
#pragma unroll
    for (int i = 0; i < 4; i++) {
        const int c = tid + i * 128;
        const float val = (v[i] - mean) * rstd * w[c] + bvec[c];
        orow[c] = val;
        hrow[c] = __float2half_rn(val);
    }
}

// ---------------- mean+max pooling over sequence ----------------
__global__ __launch_bounds__(512)
void pool_kernel(const float* __restrict__ x, float* __restrict__ pool)
{
    const int b = blockIdx.x, d = threadIdx.x;
    float s = 0.f, m = -1e30f;
    for (int t = 0; t < S_; t++) {
        const float v = x[(size_t)(b * S_ + t) * D_ + d];
        s += v;
        m = fmaxf(m, v);
    }
    pool[b * (2 * D_) + d] = s * (1.f / 512.f);
    pool[b * (2 * D_) + D_ + d] = m;
}

// ---------------- final head ----------------
__global__ __launch_bounds__(128)
void head2_kernel(const float* __restrict__ h, const float* __restrict__ w,
                  const float* __restrict__ bb, float* __restrict__ out)
{
    const int b = blockIdx.x, tid = threadIdx.x;
    float s = 0.f;
    for (int c = tid; c < D_; c += 128) s += h[(size_t)b * D_ + c] * w[c];
    __shared__ float red[4];
#pragma unroll
    for (int o = 16; o > 0; o >>= 1) s += __shfl_xor_sync(0xFFFFFFFFu, s, o);
    if ((tid & 31) == 0) red[tid >> 5] = s;
    __syncthreads();
    if (tid == 0) out[b] = red[0] + red[1] + red[2] + red[3] + bb[0];
}

// ---------------- launch ----------------
extern "C" void kernel_launch(void* const* d_in, const int* in_sizes, int n_in,
                              void* d_out, int out_size)
{
    const float* x_in = (const float*)d_in[0];
    const float* w_in = (const float*)d_in[1];
    const float* b_in = (const float*)d_in[2];
    const float* inpw = (const float*)d_in[3];
    const float* inpb = (const float*)d_in[4];
    const float* outw = (const float*)d_in[5];
    const float* outb = (const float*)d_in[6];
    const float* ln1w = (const float*)d_in[7];
    const float* ln1b = (const float*)d_in[8];
    const float* ln2w = (const float*)d_in[9];
    const float* ln2b = (const float*)d_in[10];
    const float* ff1w = (const float*)d_in[11];
    const float* ff1b = (const float*)d_in[12];
    const float* ff2w = (const float*)d_in[13];
    const float* ff2b = (const float*)d_in[14];
    const float* h1w  = (const float*)d_in[15];
    const float* h1b  = (const float*)d_in[16];
    const float* h2w  = (const float*)d_in[17];
    const float* h2b  = (const float*)d_in[18];

    float* out  = (float*)d_out;
    float* attn = out + 32;   // [L,B,H,S,S] follows the [B,1] output

    float *px, *pqkv, *ptmp, *ppool, *phead, *ppe;
    __half *pxh, *pctxh, *pffh, *pwbh;
    cudaGetSymbolAddress((void**)&px,    g_x);
    cudaGetSymbolAddress((void**)&pxh,   g_xh);
    cudaGetSymbolAddress((void**)&pqkv,  g_qkv);
    cudaGetSymbolAddress((void**)&pctxh, g_ctxh);
    cudaGetSymbolAddress((void**)&ptmp,  g_tmp);
    cudaGetSymbolAddress((void**)&pffh,  g_ffh);
    cudaGetSymbolAddress((void**)&ppool, g_pool);
    cudaGetSymbolAddress((void**)&phead, g_head);
    cudaGetSymbolAddress((void**)&pwbh,  g_wbufh);
    cudaGetSymbolAddress((void**)&ppe,   g_pe);

    cudaFuncSetAttribute(gemm_h<0,1>, cudaFuncAttributeMaxDynamicSharedMemorySize, MH_SMEM);
    cudaFuncSetAttribute(gemm_h<0,0>, cudaFuncAttributeMaxDynamicSharedMemorySize, MH_SMEM);
    cudaFuncSetAttribute(gemm_h<1,2>, cudaFuncAttributeMaxDynamicSharedMemorySize, MH_SMEM);
    cudaFuncSetAttribute(fused_attn, cudaFuncAttributeMaxDynamicSharedMemorySize, FA_SMEM_BYTES);

    const dim3 blk(256);
    const dim3 mblk(128);

    // per-replay setup: fp16 weights + PE table
    round_all<<<(WB_TOT + 1023) / 1024, 256>>>(inpw, outw, ff1w, ff2w, pwbh);
    pe_init<<<(S_ * D_) / 256, 256>>>(ppe);

    // input projection + PE (SIMT; writes fp32 residual + fp16 GEMM copy)
    gemm_kernel<2><<<dim3(D_ / 128, TOK_ / 128), blk>>>(
        x_in, w_in, b_in, px, pxh, TOK_, D_, IN_, ppe);

    for (int l = 0; l < L_; l++) {
        // QKV projection (fp16 in, fp32 tf32-rounded out -> attention)
        gemm_h<0,1><<<dim3((3 * D_) / 128, TOK_ / 128), mblk, MH_SMEM>>>(
            pxh, pwbh + WB_IN + (size_t)l * 3 * D_ * D_, inpb + l * 3 * D_,
            pqkv, nullptr, TOK_, 3 * D_, D_);

        float* attn_l = attn + (size_t)l * B_ * H_ * S_ * S_;

        // fused scores + softmax + probs-out + P@V (ctx -> fp16)
        fused_attn<<<dim3(S_ / 32, B_ * H_), blk, FA_SMEM_BYTES>>>(pqkv, attn_l, pctxh);

        // output projection (fp16 in, fp32 out -> LN)
        gemm_h<0,0><<<dim3(D_ / 128, TOK_ / 128), mblk, MH_SMEM>>>(
            pctxh, pwbh + WB_OUT + (size_t)l * D_ * D_, outb + l * D_,
            ptmp, nullptr, TOK_, D_, D_);

        ln_kernel<<<TOK_, 128>>>(px, ptmp, ln1w + l * D_, ln1b + l * D_, px, pxh);

        // ff1 + GELU (fp16 in, fp16 out -> ff2)
        gemm_h<1,2><<<dim3(FF_ / 128, TOK_ / 128), mblk, MH_SMEM>>>(
            pxh, pwbh + WB_FF1 + (size_t)l * FF_ * D_, ff1b + l * FF_,
            nullptr, pffh, TOK_, FF_, D_);

        // ff2 (fp16 in, fp32 out -> LN)
        gemm_h<0,0><<<dim3(D_ / 128, TOK_ / 128), mblk, MH_SMEM>>>(
            pffh, pwbh + WB_FF2 + (size_t)l * D_ * FF_, ff2b + l * D_,
            ptmp, nullptr, TOK_, D_, FF_);

        ln_kernel<<<TOK_, 128>>>(px, ptmp, ln2w + l * D_, ln2b + l * D_, px, pxh);
    }

    pool_kernel<<<B_, 512>>>(px, ppool);
    gemm_kernel<1><<<dim3(D_ / 128, 1), blk>>>(
        ppool, h1w, h1b, phead, nullptr, B_, D_, 2 * D_, ppe);
    head2_kernel<<<B_, 128>>>(phead, h2w, h2b, out);
}

// round 15
// speedup vs baseline: 5.7423x; 1.2607x over previous
#include <cuda_runtime.h>
#include <cuda_fp16.h>
#include <cstdint>
#include <math.h>

#define B_   32
#define S_   512
#define IN_  64
#define D_   512
#define H_   8
#define L_   4
#define FF_  2048
#define TOK_ (B_ * S_)   // 16384

// ---------------- scratch (device globals; no allocation allowed) ----------------
__device__ __align__(16) float  g_x[TOK_ * D_];          // fp32 residual stream
__device__ __align__(16) __half g_xh[TOK_ * D_];         // fp16 copy (GEMM input)
__device__ __align__(16) __half g_qkvh[TOK_ * 3 * D_];   // fp16 qkv (attention input)
__device__ __align__(16) __half g_ctxh[TOK_ * D_];       // fp16 ctx (out_proj input)
__device__ __align__(16) float  g_tmp[TOK_ * D_];        // fp32 GEMM outputs -> LN
__device__ __align__(16) __half g_ffh[TOK_ * FF_];       // fp16 GELU out (ff2 input)
__device__ __align__(16) float  g_pool[B_ * 2 * D_];
__device__ __align__(16) float  g_head[B_ * D_];
__device__ __align__(16) float  g_pe[S_ * D_];
// fp16 weights: [in_proj | out_proj | ff1 | ff2]
#define WB_IN  0
#define WB_OUT (WB_IN  + L_ * 3 * D_ * D_)
#define WB_FF1 (WB_OUT + L_ * D_ * D_)
#define WB_FF2 (WB_FF1 + L_ * FF_ * D_)
#define WB_TOT (WB_FF2 + L_ * D_ * FF_)
__device__ __align__(16) __half g_wbufh[WB_TOT];

__device__ __forceinline__ float gelu_exact(float v) {
    return 0.5f * v * (1.0f + erff(v * 0.7071067811865475f));
}
__device__ __forceinline__ float fast_exp(float x) {
    float y = x * 1.442695041f;
    float z = y + 12582912.f;
    float k = z - 12582912.f;
    float f = y - k;
    float p = 1.3333558e-3f;
    p = fmaf(p, f, 9.6181291e-3f);
    p = fmaf(p, f, 5.5504109e-2f);
    p = fmaf(p, f, 2.4022651e-1f);
    p = fmaf(p, f, 6.9314718e-1f);
    p = fmaf(p, f, 1.0f);
    int ki = (__float_as_int(z) - 0x4B400000) << 23;
    return __int_as_float(__float_as_int(p) + ki);
}
__device__ __forceinline__ uint32_t smem_u32(const void* p) {
    uint32_t a;
    asm("{ .reg .u64 t; cvta.to.shared.u64 t, %1; cvt.u32.u64 %0, t; }" : "=r"(a) : "l"(p));
    return a;
}
// non-volatile: lets compiler interleave HMMA with next ldmatrix
__device__ __forceinline__ void mma_f16(float* c, const uint32_t* a, const uint32_t* b) {
    asm("mma.sync.aligned.m16n8k16.row.col.f32.f16.f16.f32 "
        "{%0,%1,%2,%3}, {%4,%5,%6,%7}, {%8,%9}, {%0,%1,%2,%3};"
        : "+f"(c[0]), "+f"(c[1]), "+f"(c[2]), "+f"(c[3])
        : "r"(a[0]), "r"(a[1]), "r"(a[2]), "r"(a[3]), "r"(b[0]), "r"(b[1]));
}
#define LDSM_X4(r0, r1, r2, r3, addr) \
    asm volatile("ldmatrix.sync.aligned.m8n8.x4.shared.b16 {%0,%1,%2,%3}, [%4];" \
        : "=r"(r0), "=r"(r1), "=r"(r2), "=r"(r3) : "r"(addr))
// trans variant: loads 4 k-major 8x8 b16 matrices, delivering n-major fragments
#define LDSM_X4_T(r0, r1, r2, r3, addr) \
    asm volatile("ldmatrix.sync.aligned.m8n8.x4.trans.shared.b16 {%0,%1,%2,%3}, [%4];" \
        : "=r"(r0), "=r"(r1), "=r"(r2), "=r"(r3) : "r"(addr))

// ---------------- fp16 conversion of ALL weights (one launch) ----------------
__global__ __launch_bounds__(256)
void round_all(const float* __restrict__ w_in, const float* __restrict__ w_out,
               const float* __restrict__ w_ff1, const float* __restrict__ w_ff2,
               __half* __restrict__ dst)
{
    const int i = (blockIdx.x * 256 + threadIdx.x) * 4;
    if (i >= WB_TOT) return;
    const float* src;
    int off;
    if (i < WB_OUT)      { src = w_in;  off = i - WB_IN;  }
    else if (i < WB_FF1) { src = w_out; off = i - WB_OUT; }
    else if (i < WB_FF2) { src = w_ff1; off = i - WB_FF1; }
    else                 { src = w_ff2; off = i - WB_FF2; }
    const float4 v = *(const float4*)(src + off);
    __half2* d = (__half2*)(dst + i);
    d[0] = __floats2half2_rn(v.x, v.y);
    d[1] = __floats2half2_rn(v.z, v.w);
}

// ---------------- positional encoding table (once per replay) ----------------
__global__ __launch_bounds__(256)
void pe_init(float* __restrict__ pe)
{
    const int i = blockIdx.x * 256 + threadIdx.x;
    const int s = i >> 9;
    const int d = i & (D_ - 1);
    const float freq = expf(-9.210340371976184f * (float)(d & ~1) / (float)D_);
    const float ang = (float)s * freq;
    pe[i] = (d & 1) ? cosf(ang) : sinf(ang);
}

// ======================= fp16 mma.sync GEMM =======================
// C[M,N] = act(A[M,K] * W[N,K]^T + bias), A/W fp16, accum fp32.
// 128x128x32 CTA tile, 128 thr (4 warps 2x2), warp 64x64 of m16n8k16.
#define MH_RS     40                      // halves per row (32 data + 8 pad)
#define MH_TILEB  (128 * MH_RS * 2)       // 10240 B per operand
#define MH_STAGE  (2 * MH_TILEB)          // 20480 B per stage
#define MH_NST    3
#define MH_SMEM   (MH_NST * MH_STAGE)     // 61440 B

__device__ __forceinline__ void mh_cp_issue(
    const __half* __restrict__ A, const __half* __restrict__ W,
    uint32_t sbase, int stage, int m0, int n0, int K, int k0, int tid)
{
    const uint32_t as = sbase + stage * MH_STAGE;
    const uint32_t bs = as + MH_TILEB;
#pragma unroll
    for (int i = 0; i < 4; i++) {
        const int idx = i * 128 + tid;
        const int row = idx >> 2;
        const int q = idx & 3;
        const uint32_t so = (uint32_t)(row * (MH_RS * 2) + q * 16);
        const __half* ga = A + (size_t)(m0 + row) * K + k0 + q * 8;
        const __half* gw = W + (size_t)(n0 + row) * K + k0 + q * 8;
        asm volatile("cp.async.cg.shared.global [%0], [%1], 16;" :: "r"(as + so), "l"(ga));
        asm volatile("cp.async.cg.shared.global [%0], [%1], 16;" :: "r"(bs + so), "l"(gw));
    }
    asm volatile("cp.async.commit_group;" ::: "memory");
}

// ACT: 0=none, 1=exact GELU.  OUT: 0=fp32, 2=fp16
template <int ACT, int OUT>
__global__ __launch_bounds__(128, 2)
void gemm_h(const __half* __restrict__ A, const __half* __restrict__ W,
            const float* __restrict__ bias, float* __restrict__ C,
            __half* __restrict__ CH, int M, int N, int K)
{
    extern __shared__ char smem[];
    const uint32_t sbase = smem_u32(smem);
    const int tid = threadIdx.x;
    const int lane = tid & 31, wid = tid >> 5;
    const int g = lane >> 2, t4 = lane & 3;
    const int wm = wid & 1;
    const int wn = wid >> 1;
    const int m0 = blockIdx.y * 128, n0 = blockIdx.x * 128;

    const uint32_t a_lane = (uint32_t)((wm * 64 + (lane & 7) + (lane & 8)) * MH_RS
                                       + ((lane & 16) >> 1));
    const uint32_t b_lane = (uint32_t)((wn * 64 + ((lane & 16) >> 1) + (lane & 7)) * MH_RS
                                       + (lane & 8));

    float acc[4][8][4];
#pragma unroll
    for (int mt = 0; mt < 4; mt++)
#pragma unroll
        for (int nt = 0; nt < 8; nt++)
#pragma unroll
            for (int j = 0; j < 4; j++) acc[mt][nt][j] = 0.f;

    const int nch = K >> 5;
    mh_cp_issue(A, W, sbase, 0, m0, n0, K, 0, tid);
    mh_cp_issue(A, W, sbase, 1, m0, n0, K, 32, tid);

    int cur = 0;
    for (int c = 0; c < nch; c++) {
        if (c + 1 < nch)
            asm volatile("cp.async.wait_group 1;" ::: "memory");
        else
            asm volatile("cp.async.wait_group 0;" ::: "memory");
        __syncthreads();

        const uint32_t a_base = sbase + cur * MH_STAGE + a_lane * 2;
        const uint32_t b_base = sbase + cur * MH_STAGE + MH_TILEB + b_lane * 2;

#pragma unroll
        for (int ks = 0; ks < 2; ks++) {
            uint32_t afr[4][4];
#pragma unroll
            for (int mt = 0; mt < 4; mt++)
                LDSM_X4(afr[mt][0], afr[mt][1], afr[mt][2], afr[mt][3],
                        a_base + (uint32_t)(mt * 16 * MH_RS + ks * 16) * 2);
            uint32_t bfr[8][2];
#pragma unroll
            for (int p = 0; p < 4; p++)
                LDSM_X4(bfr[2 * p][0], bfr[2 * p][1], bfr[2 * p + 1][0], bfr[2 * p + 1][1],
                        b_base + (uint32_t)(p * 16 * MH_RS + ks * 16) * 2);
#pragma unroll
            for (int mt = 0; mt < 4; mt++)
#pragma unroll
                for (int nt = 0; nt < 8; nt++)
                    mma_f16(acc[mt][nt], afr[mt], bfr[nt]);
        }
        if (c + 2 < nch) {
            int tgt = cur + 2; if (tgt >= 3) tgt -= 3;
            mh_cp_issue(A, W, sbase, tgt, m0, n0, K, (c + 2) * 32, tid);
        }
        cur = (cur == 2) ? 0 : cur + 1;
    }

#pragma unroll
    for (int mt = 0; mt < 4; mt++) {
        const int r0 = m0 + wm * 64 + mt * 16 + g;
#pragma unroll
        for (int nt = 0; nt < 8; nt++) {
            const int cb = n0 + wn * 64 + nt * 8 + 2 * t4;
            const float b0 = bias[cb], b1 = bias[cb + 1];
            float v0 = acc[mt][nt][0] + b0;
            float v1 = acc[mt][nt][1] + b1;
            float v2 = acc[mt][nt][2] + b0;
            float v3 = acc[mt][nt][3] + b1;
            if (ACT == 1) {
                v0 = gelu_exact(v0); v1 = gelu_exact(v1);
                v2 = gelu_exact(v2); v3 = gelu_exact(v3);
            }
            if (OUT == 2) {
                *(__half2*)&CH[(size_t)r0 * N + cb]       = __floats2half2_rn(v0, v1);
                *(__half2*)&CH[(size_t)(r0 + 8) * N + cb] = __floats2half2_rn(v2, v3);
            } else {
                *(float2*)&C[(size_t)r0 * N + cb]       = make_float2(v0, v1);
                *(float2*)&C[(size_t)(r0 + 8) * N + cb] = make_float2(v2, v3);
            }
        }
    }
}

// ======================= fused attention (fp16 mma) =======================
// block = (q-tile 32) x (b*H+h). 256 threads (8 warps), 2 CTAs/SM.
// Layout (bytes): qs fp16 [32][72] @0 (4608) | sc fp32 [32][516] @4608 (66048)
//                 kv fp16 [128][72] @70656 (18432)  -> total 89088.
// After softmax, fp16 probs are written into the FIRST 1024 B of each row's own
// (dead) fp32 score row: row r @ 4608 + r*2064, 512 halves. Row stride 2064 =
// 129*16B -> conflict-free ldmatrix. Same-warp read-before-write, rows private.
#define FA_QS_B   0
#define FA_SC_B   4608
#define FA_KV_B   70656
#define FA_SMEM_BYTES 89088
#define FA_SS 516      // fp32 score stride (floats)
#define FA_PH_B 2064   // fp16 prob row stride (bytes)

__global__ __launch_bounds__(256, 2)
void fused_attn(const __half* __restrict__ qkv, float* __restrict__ probs,
                __half* __restrict__ ctxh)
{
    extern __shared__ char smem[];
    const uint32_t sbase = smem_u32(smem);
    __half* qs = (__half*)(smem + FA_QS_B);
    float*  sc = (float*)(smem + FA_SC_B);
    __half* kv = (__half*)(smem + FA_KV_B);

    const int tid = threadIdx.x;
    const int lane = tid & 31, wid = tid >> 5;
    const int g = lane >> 2, t4 = lane & 3;
    const int q0 = blockIdx.x * 32;
    const int bh = blockIdx.y;
    const int b = bh >> 3, h = bh & 7;
    const int wm = wid & 1;
    const int wn = wid >> 1;

    // ldmatrix lane addresses
    const uint32_t qa_addr = sbase + FA_QS_B +
        (uint32_t)((wm * 16 + (lane & 7) + (lane & 8)) * 72 + ((lane & 16) >> 1)) * 2;
    const uint32_t kb_addr = sbase + FA_KV_B +
        (uint32_t)((wn * 32 + ((lane & 16) >> 1) + (lane & 7)) * 72 + (lane & 8)) * 2;
    const uint32_t pa_addr = sbase + FA_SC_B +
        (uint32_t)(wm * 16 + (lane & 7) + (lane & 8)) * FA_PH_B + (uint32_t)((lane & 16) >> 1) * 2;
    // V (k-major) -> B fragment via ldmatrix.trans:
    // lanes 0-7: k0-7/n+0 | 8-15: k8-15/n+0 | 16-23: k0-7/n+8 | 24-31: k8-15/n+8
    const uint32_t vb_addr = sbase + FA_KV_B +
        (uint32_t)((lane & 15) * 72 + wn * 16 + ((lane & 16) >> 1)) * 2;

    // ---- load Q tile (x 0.125; exact power-of-2 scale in fp16) ----
    {
        const int r = tid >> 3;
        const int d0 = (tid & 7) * 8;
        const __half* src = qkv + (size_t)(b * S_ + q0 + r) * 1536 + h * 64 + d0;
        const __half2 scale = __floats2half2_rn(0.125f, 0.125f);
        const uint2 raw0 = *(const uint2*)src;
        const uint2 raw1 = *(const uint2*)(src + 4);
        __half2* dst = (__half2*)(qs + r * 72 + d0);
        dst[0] = __hmul2(*(const __half2*)&raw0.x, scale);
        dst[1] = __hmul2(*(const __half2*)&raw0.y, scale);
        dst[2] = __hmul2(*(const __half2*)&raw1.x, scale);
        dst[3] = __hmul2(*(const __half2*)&raw1.y, scale);
    }

    // ---- scores: 4 K-tiles of 128 ----
    for (int kt = 0; kt < 4; kt++) {
        __syncthreads();
#pragma unroll
        for (int i = 0; i < 4; i++) {
            const int idx = i * 256 + tid;
            const int r = idx >> 3;
            const int d0 = (idx & 7) * 8;
            const __half* src = qkv + (size_t)(b * S_ + kt * 128 + r) * 1536 + D_ + h * 64 + d0;
            *(uint4*)(kv + r * 72 + d0) = *(const uint4*)src;
        }
        __syncthreads();

        float acc[4][4];
#pragma unroll
        for (int nt = 0; nt < 4; nt++)
#pragma unroll
            for (int j = 0; j < 4; j++) acc[nt][j] = 0.f;

#pragma unroll
        for (int ks = 0; ks < 4; ks++) {        // 4 x k16 over HD=64
            uint32_t afr[4];
            LDSM_X4(afr[0], afr[1], afr[2], afr[3], qa_addr + (uint32_t)(ks * 16) * 2);
            uint32_t bfr[4][2];
#pragma unroll
            for (int p = 0; p < 2; p++)
                LDSM_X4(bfr[2 * p][0], bfr[2 * p][1], bfr[2 * p + 1][0], bfr[2 * p + 1][1],
                        kb_addr + (uint32_t)(p * 16 * 72 + ks * 16) * 2);
#pragma unroll
            for (int nt = 0; nt < 4; nt++)
                mma_f16(acc[nt], afr, bfr[nt]);
        }
#pragma unroll
        for (int nt = 0; nt < 4; nt++) {
            const int col = kt * 128 + wn * 32 + nt * 8 + 2 * t4;
            const int row = wm * 16 + g;
            *(float2*)&sc[row * FA_SS + col]       = make_float2(acc[nt][0], acc[nt][1]);
            *(float2*)&sc[(row + 8) * FA_SS + col] = make_float2(acc[nt][2], acc[nt][3]);
        }
    }
    __syncthreads();

    // ---- softmax: fp32 scores -> fp16 probs (smem, aliased) + fp32 probs (gmem) ----
#pragma unroll
    for (int rr = 0; rr < 4; rr++) {
        const int row = wid * 4 + rr;
        float vals[16];
        float sum = 0.f;
#pragma unroll
        for (int t = 0; t < 4; t++) {
            const float4 v = *(const float4*)&sc[row * FA_SS + lane * 4 + t * 128];
            vals[t * 4 + 0] = fast_exp(v.x);
            vals[t * 4 + 1] = fast_exp(v.y);
            vals[t * 4 + 2] = fast_exp(v.z);
            vals[t * 4 + 3] = fast_exp(v.w);
            sum += vals[t * 4 + 0] + vals[t * 4 + 1] + vals[t * 4 + 2] + vals[t * 4 + 3];
        }
#pragma unroll
        for (int o = 16; o > 0; o >>= 1)
            sum += __shfl_xor_sync(0xFFFFFFFFu, sum, o);
        const float inv = 1.f / sum;
        float* prow = probs + ((size_t)bh * S_ + q0 + row) * S_;
        __half* phrow = (__half*)((char*)sc + row * FA_PH_B);
#pragma unroll
        for (int t = 0; t < 4; t++) {
            const int c = lane * 4 + t * 128;
            const __half2 h0 = __floats2half2_rn(vals[t * 4 + 0] * inv, vals[t * 4 + 1] * inv);
            const __half2 h1 = __floats2half2_rn(vals[t * 4 + 2] * inv, vals[t * 4 + 3] * inv);
            *(__half2*)&phrow[c]     = h0;
            *(__half2*)&phrow[c + 2] = h1;
            float4 o;
            o.x = __half2float(__low2half(h0));
            o.y = __half2float(__high2half(h0));
            o.z = __half2float(__low2half(h1));
            o.w = __half2float(__high2half(h1));
            *(float4*)&prow[c] = o;
        }
    }

    // ---- ctx = P @ V : 4 V-tiles of 128, fp16 mma, V via ldmatrix.trans ----
    float pacc[2][4];
#pragma unroll
    for (int nt = 0; nt < 2; nt++)
#pragma unroll
        for (int j = 0; j < 4; j++) pacc[nt][j] = 0.f;

    for (int vt = 0; vt < 4; vt++) {
        __syncthreads();
#pragma unroll
        for (int i = 0; i < 4; i++) {
            const int idx = i * 256 + tid;
            const int r = idx >> 3;
            const int d0 = (idx & 7) * 8;
            const __half* src = qkv + (size_t)(b * S_ + vt * 128 + r) * 1536 + 2 * D_ + h * 64 + d0;
            *(uint4*)(kv + r * 72 + d0) = *(const uint4*)src;
        }
        __syncthreads();

#pragma unroll
        for (int ks = 0; ks < 8; ks++) {        // 8 x k16 over 128 keys
            uint32_t afr[4];
            LDSM_X4(afr[0], afr[1], afr[2], afr[3],
                    pa_addr + (uint32_t)(vt * 128 + ks * 16) * 2);
            uint32_t bfr[2][2];
            LDSM_X4_T(bfr[0][0], bfr[0][1], bfr[1][0], bfr[1][1],
                      vb_addr + (uint32_t)(ks * 16 * 72) * 2);
            mma_f16(pacc[0], afr, bfr[0]);
            mma_f16(pacc[1], afr, bfr[1]);
        }
    }

    // ctx -> fp16 (out_proj GEMM input)
#pragma unroll
    for (int nt = 0; nt < 2; nt++) {
        const int row = b * S_ + q0 + wm * 16 + g;
        const int col = h * 64 + wn * 16 + nt * 8 + 2 * t4;
        *(__half2*)&ctxh[(size_t)row * D_ + col] =
            __floats2half2_rn(pacc[nt][0], pacc[nt][1]);
        *(__half2*)&ctxh[(size_t)(row + 8) * D_ + col] =
            __floats2half2_rn(pacc[nt][2], pacc[nt][3]);
    }
}

// ---------------- SIMT GEMM (input proj / head1) ----------------
// ACT: 1=GELU (head1), 2=add PE table + write fp32/fp16 pair (input proj)
template <int ACT>
__global__ __launch_bounds__(256)
void gemm_kernel(const float* __restrict__ A, const float* __restrict__ W,
                 const float* __restrict__ bias, float* __restrict__ C,
                 __half* __restrict__ CH,
                 int M, int N, int K, const float* __restrict__ pe)
{
    __shared__ __align__(16) float As[8][128];
    __shared__ __align__(16) float Ws[8][128];

    const int tid = threadIdx.x;
    const int tx = tid & 15;
    const int ty = tid >> 4;
    const int m0 = blockIdx.y * 128;
    const int n0 = blockIdx.x * 128;

    float acc[2][2][4][4];
#pragma unroll
    for (int p = 0; p < 2; p++)
#pragma unroll
        for (int q = 0; q < 2; q++)
#pragma unroll
            for (int i = 0; i < 4; i++)
#pragma unroll
                for (int j = 0; j < 4; j++) acc[p][q][i][j] = 0.f;

    const int lr = tid >> 1;
    const int lk = (tid & 1) * 4;
    const float* Ag = A + (size_t)(m0 + lr) * K + lk;
    const float* Wg = W + (size_t)(n0 + lr) * K + lk;
    const bool aval = (m0 + lr) < M;

    for (int k0 = 0; k0 < K; k0 += 8) {
        float4 av = make_float4(0.f, 0.f, 0.f, 0.f);
        if (aval) av = *(const float4*)(Ag + k0);
        const float4 wv = *(const float4*)(Wg + k0);
        __syncthreads();
        As[lk + 0][lr] = av.x; As[lk + 1][lr] = av.y;
        As[lk + 2][lr] = av.z; As[lk + 3][lr] = av.w;
        Ws[lk + 0][lr] = wv.x; Ws[lk + 1][lr] = wv.y;
        Ws[lk + 2][lr] = wv.z; Ws[lk + 3][lr] = wv.w;
        __syncthreads();
#pragma unroll
        for (int kk = 0; kk < 8; kk++) {
            const float4 a0 = *(const float4*)&As[kk][ty * 4];
            const float4 a1 = *(const float4*)&As[kk][64 + ty * 4];
            const float4 b0 = *(const float4*)&Ws[kk][tx * 4];
            const float4 b1 = *(const float4*)&Ws[kk][64 + tx * 4];
            const float ar[2][4] = {{a0.x, a0.y, a0.z, a0.w}, {a1.x, a1.y, a1.z, a1.w}};
            const float br[2][4] = {{b0.x, b0.y, b0.z, b0.w}, {b1.x, b1.y, b1.z, b1.w}};
#pragma unroll
            for (int p = 0; p < 2; p++)
#pragma unroll
                for (int q = 0; q < 2; q++)
#pragma unroll
                    for (int i = 0; i < 4; i++)
#pragma unroll
                        for (int j = 0; j < 4; j++)
                            acc[p][q][i][j] += ar[p][i] * br[q][j];
        }
    }

#pragma unroll
    for (int p = 0; p < 2; p++) {
#pragma unroll
        for (int i = 0; i < 4; i++) {
            const int m = m0 + p * 64 + ty * 4 + i;
            if (m >= M) continue;
#pragma unroll
            for (int q = 0; q < 2; q++) {
                const int c = n0 + q * 64 + tx * 4;
                float4 o;
                float* po = &o.x;
#pragma unroll
                for (int j = 0; j < 4; j++) {
                    float v = acc[p][q][i][j] + bias[c + j];
                    if (ACT == 1) {
                        v = gelu_exact(v);
                    } else if (ACT == 2) {
                        v += pe[(m & (S_ - 1)) * D_ + c + j];
                    }
                    po[j] = v;
                }
                *(float4*)&C[(size_t)m * N + c] = o;
                if (ACT == 2) {
                    __half2* hd = (__half2*)&CH[(size_t)m * N + c];
                    hd[0] = __floats2half2_rn(o.x, o.y);
                    hd[1] = __floats2half2_rn(o.z, o.w);
                }
            }
        }
    }
}

// ---------------- fused residual-add + LayerNorm (fp32 + fp16 outputs) ----------------
__global__ __launch_bounds__(128)
void ln_kernel(const float* __restrict__ x, const float* __restrict__ add,
               const float* __restrict__ w, const float* __restrict__ bvec,
               float* __restrict__ out, __half* __restrict__ outh)
{
    const int row = blockIdx.x;
    const int tid = threadIdx.x;
    const float* xr = x + (size_t)row * D_;
    const float* ar = add + (size_t)row * D_;
    float v[4];
    float s = 0.f;
#pragma unroll
    for (int i = 0; i < 4; i++) {
        const int c = tid + i * 128;
        v[i] = xr[c] + ar[c];
        s += v[i];
    }
    __shared__ float red[4];
#pragma unroll
    for (int o = 16; o > 0; o >>= 1) s += __shfl_xor_sync(0xFFFFFFFFu, s, o);
    if ((tid & 31) == 0) red[tid >> 5] = s;
    __syncthreads();
    const float mean = (red[0] + red[1] + red[2] + red[3]) * (1.f / 512.f);
    float vs = 0.f;
#pragma unroll
    for (int i = 0; i < 4; i++) {
        const float d = v[i] - mean;
        vs += d * d;
    }
    __syncthreads();
#pragma unroll
    for (int o = 16; o > 0; o >>= 1) vs += __shfl_xor_sync(0xFFFFFFFFu, vs, o);
    if ((tid & 31) == 0) red[tid >> 5] = vs;
    __syncthreads();
    const float rstd = rsqrtf((red[0] + red[1] + red[2] + red[3]) * (1.f / 512.f) + 1e-5f);
    float* orow = out + (size_t)row * D_;
    __half* hrow = outh + (size_t)row * D_;
#pragma unroll
    for (int i = 0; i < 4; i++) {
        const int c = tid + i * 128;
        const float val = (v[i] - mean) * rstd * w[c] + bvec[c];
        orow[c] = val;
        hrow[c] = __float2half_rn(val);
    }
}

// ---------------- mean+max pooling over sequence ----------------
__global__ __launch_bounds__(512)
void pool_kernel(const float* __restrict__ x, float* __restrict__ pool)
{
    const int b = blockIdx.x, d = threadIdx.x;
    float s = 0.f, m = -1e30f;
    for (int t = 0; t < S_; t++) {
        const float v = x[(size_t)(b * S_ + t) * D_ + d];
        s += v;
        m = fmaxf(m, v);
    }
    pool[b * (2 * D_) + d] = s * (1.f / 512.f);
    pool[b * (2 * D_) + D_ + d] = m;
}

// ---------------- final head ----------------
__global__ __launch_bounds__(128)
void head2_kernel(const float* __restrict__ h, const float* __restrict__ w,
                  const float* __restrict__ bb, float* __restrict__ out)
{
    const int b = blockIdx.x, tid = threadIdx.x;
    float s = 0.f;
    for (int c = tid; c < D_; c += 128) s += h[(size_t)b * D_ + c] * w[c];
    __shared__ float red[4];
#pragma unroll
    for (int o = 16; o > 0; o >>= 1) s += __shfl_xor_sync(0xFFFFFFFFu, s, o);
    if ((tid & 31) == 0) red[tid >> 5] = s;
    __syncthreads();
    if (tid == 0) out[b] = red[0] + red[1] + red[2] + red[3] + bb[0];
}

// ---------------- launch ----------------
extern "C" void kernel_launch(void* const* d_in, const int* in_sizes, int n_in,
                              void* d_out, int out_size)
{
    const float* x_in = (const float*)d_in[0];
    const float* w_in = (const float*)d_in[1];
    const float* b_in = (const float*)d_in[2];
    const float* inpw = (const float*)d_in[3];
    const float* inpb = (const float*)d_in[4];
    const float* outw = (const float*)d_in[5];
    const float* outb = (const float*)d_in[6];
    const float* ln1w = (const float*)d_in[7];
    const float* ln1b = (const float*)d_in[8];
    const float* ln2w = (const float*)d_in[9];
    const float* ln2b = (const float*)d_in[10];
    const float* ff1w = (const float*)d_in[11];
    const float* ff1b = (const float*)d_in[12];
    const float* ff2w = (const float*)d_in[13];
    const float* ff2b = (const float*)d_in[14];
    const float* h1w  = (const float*)d_in[15];
    const float* h1b  = (const float*)d_in[16];
    const float* h2w  = (const float*)d_in[17];
    const float* h2b  = (const float*)d_in[18];

    float* out  = (float*)d_out;
    float* attn = out + 32;   // [L,B,H,S,S] follows the [B,1] output

    float *px, *ptmp, *ppool, *phead, *ppe;
    __half *pxh, *pqkvh, *pctxh, *pffh, *pwbh;
    cudaGetSymbolAddress((void**)&px,    g_x);
    cudaGetSymbolAddress((void**)&pxh,   g_xh);
    cudaGetSymbolAddress((void**)&pqkvh, g_qkvh);
    cudaGetSymbolAddress((void**)&pctxh, g_ctxh);
    cudaGetSymbolAddress((void**)&ptmp,  g_tmp);
    cudaGetSymbolAddress((void**)&pffh,  g_ffh);
    cudaGetSymbolAddress((void**)&ppool, g_pool);
    cudaGetSymbolAddress((void**)&phead, g_head);
    cudaGetSymbolAddress((void**)&pwbh,  g_wbufh);
    cudaGetSymbolAddress((void**)&ppe,   g_pe);

    cudaFuncSetAttribute(gemm_h<0,2>, cudaFuncAttributeMaxDynamicSharedMemorySize, MH_SMEM);
    cudaFuncSetAttribute(gemm_h<0,0>, cudaFuncAttributeMaxDynamicSharedMemorySize, MH_SMEM);
    cudaFuncSetAttribute(gemm_h<1,2>, cudaFuncAttributeMaxDynamicSharedMemorySize, MH_SMEM);
    cudaFuncSetAttribute(fused_attn, cudaFuncAttributeMaxDynamicSharedMemorySize, FA_SMEM_BYTES);

    const dim3 blk(256);
    const dim3 mblk(128);

    // per-replay setup: fp16 weights + PE table
    round_all<<<(WB_TOT + 1023) / 1024, 256>>>(inpw, outw, ff1w, ff2w, pwbh);
    pe_init<<<(S_ * D_) / 256, 256>>>(ppe);

    // input projection + PE (SIMT; fp32 residual + fp16 GEMM copy)
    gemm_kernel<2><<<dim3(D_ / 128, TOK_ / 128), blk>>>(
        x_in, w_in, b_in, px, pxh, TOK_, D_, IN_, ppe);

    for (int l = 0; l < L_; l++) {
        // QKV projection (fp16 in, fp16 out -> attention)
        gemm_h<0,2><<<dim3((3 * D_) / 128, TOK_ / 128), mblk, MH_SMEM>>>(
            pxh, pwbh + WB_IN + (size_t)l * 3 * D_ * D_, inpb + l * 3 * D_,
            nullptr, pqkvh, TOK_, 3 * D_, D_);

        float* attn_l = attn + (size_t)l * B_ * H_ * S_ * S_;

        // fused scores + softmax + probs-out + P@V (all fp16 mma)
        fused_attn<<<dim3(S_ / 32, B_ * H_), blk, FA_SMEM_BYTES>>>(pqkvh, attn_l, pctxh);

        // output projection (fp16 in, fp32 out -> LN)
        gemm_h<0,0><<<dim3(D_ / 128, TOK_ / 128), mblk, MH_SMEM>>>(
            pctxh, pwbh + WB_OUT + (size_t)l * D_ * D_, outb + l * D_,
            ptmp, nullptr, TOK_, D_, D_);

        ln_kernel<<<TOK_, 128>>>(px, ptmp, ln1w + l * D_, ln1b + l * D_, px, pxh);

        // ff1 + GELU (fp16 in, fp16 out -> ff2)
        gemm_h<1,2><<<dim3(FF_ / 128, TOK_ / 128), mblk, MH_SMEM>>>(
            pxh, pwbh + WB_FF1 + (size_t)l * FF_ * D_, ff1b + l * FF_,
            nullptr, pffh, TOK_, FF_, D_);

        // ff2 (fp16 in, fp32 out -> LN)
        gemm_h<0,0><<<dim3(D_ / 128, TOK_ / 128), mblk, MH_SMEM>>>(
            pffh, pwbh + WB_FF2 + (size_t)l * D_ * FF_, ff2b + l * D_,
            ptmp, nullptr, TOK_, D_, FF_);

        ln_kernel<<<TOK_, 128>>>(px, ptmp, ln2w + l * D_, ln2b + l * D_, px, pxh);
    }

    pool_kernel<<<B_, 512>>>(px, ppool);
    gemm_kernel<1><<<dim3(D_ / 128, 1), blk>>>(
        ppool, h1w, h1b, phead, nullptr, B_, D_, 2 * D_, ppe);
    head2_kernel<<<B_, 128>>>(phead, h2w, h2b, out);
}